// round 4
// baseline (speedup 1.0000x reference)
#include <cuda_runtime.h>
#include <math.h>
#include <float.h>
#include <stdint.h>

// ---------------------------------------------------------------------------
// Supernetwork: backbone (3x conv+BN+relu+pool) -> beam search -> MoE dispatch
// B=2048, BEAMS=4, DEPTH=3, HID=128, NOPS=4
// Determinism: NO float atomics anywhere (BN stats feed argmax -> any
// run-to-run ulp noise flips discrete decisions). Two-phase fixed-order
// reductions instead.
// ---------------------------------------------------------------------------

#define NB 2048

// ------------------------------ scratch ------------------------------------
__device__ float g_buf1[(size_t)NB * 32 * 900];   // conv1 out (30x30)
__device__ float g_buf2[(size_t)NB * 32 * 225];   // pool1 out (15x15)
__device__ float g_buf3[(size_t)NB * 32 * 169];   // conv2 out (13x13)
__device__ float g_buf4[(size_t)NB * 32 * 36];    // pool2 out (6x6)
__device__ float g_buf5[(size_t)NB * 32 * 16];    // conv3 out (4x4)
__device__ float g_h0[(size_t)NB * 128];          // backbone feature
__device__ float g_hid[(size_t)NB * 4 * 128];     // dispatch state
__device__ float g_psum[32 * NB];                 // per-(channel,img) partial sum
__device__ float g_psq[32 * NB];                  // per-(channel,img) partial sumsq
__device__ float g_scale[3][32];
__device__ float g_shift[3][32];
__device__ int   g_op[3 * NB * 4];                // [step][n][beam]
__device__ float g_pv[3 * NB * 4];

// --------------------------- f32x2 helpers ---------------------------------
typedef unsigned long long u64t;

__device__ __forceinline__ void ffma2(u64t& c, u64t a, u64t b) {
    asm("fma.rn.f32x2 %0, %1, %2, %0;" : "+l"(c) : "l"(a), "l"(b));
}
__device__ __forceinline__ u64t splat2(float v) {
    u64t r;
    asm("mov.b64 %0, {%1, %1};" : "=l"(r) : "r"(__float_as_uint(v)));
    return r;
}
__device__ __forceinline__ float lo32(u64t v) { return __uint_as_float((unsigned)v); }
__device__ __forceinline__ float hi32(u64t v) { return __uint_as_float((unsigned)(v >> 32)); }

__device__ __forceinline__ float warp_sum(float v) {
#pragma unroll
    for (int off = 16; off; off >>= 1) v += __shfl_down_sync(0xffffffffu, v, off);
    return v;
}

// ------------------- conv1: 3->32, 32x32 -> 30x30 --------------------------
// 480 threads = 16 oc-pairs x 30 output rows. Weights in smem per (ic,k).
__global__ __launch_bounds__(480) void conv1_kernel(
    const float* __restrict__ x, const float* __restrict__ w,
    const float* __restrict__ bias)
{
    __shared__ float s_img[3 * 1024];
    __shared__ float s_w[27 * 32];   // [k][oc]
    __shared__ float s_b[32];
    int tid = threadIdx.x;
    int img = blockIdx.x;
    const float* xb = x + (size_t)img * 3072;
    for (int i = tid; i < 3072; i += 480) s_img[i] = xb[i];
    for (int i = tid; i < 864; i += 480) {
        int oc = i / 27, k = i % 27;
        s_w[k * 32 + oc] = w[i];
    }
    if (tid < 32) s_b[tid] = bias[tid];
    __syncthreads();

    int ocp = tid & 15;
    int row = tid >> 4;   // 0..29
    u64t acc[30];
    u64t bv = *(const u64t*)(s_b + ocp * 2);
#pragma unroll
    for (int i = 0; i < 30; i++) acc[i] = bv;

#pragma unroll
    for (int ic = 0; ic < 3; ic++) {
#pragma unroll
        for (int ky = 0; ky < 3; ky++) {
            const float* irow = s_img + ic * 1024 + (row + ky) * 32;
            float in[32];
#pragma unroll
            for (int i = 0; i < 32; i++) in[i] = irow[i];
#pragma unroll
            for (int kx = 0; kx < 3; kx++) {
                u64t wv = *(const u64t*)(s_w + ((ic * 3 + ky) * 3 + kx) * 32 + ocp * 2);
#pragma unroll
                for (int ox = 0; ox < 30; ox++)
                    ffma2(acc[ox], wv, splat2(in[ox + kx]));
            }
        }
    }
    float* ob = g_buf1 + ((size_t)img * 32 + ocp * 2) * 900 + row * 30;
#pragma unroll
    for (int ox = 0; ox < 30; ox++) { ob[ox] = lo32(acc[ox]); ob[900 + ox] = hi32(acc[ox]); }
}

// ---------------- per-(channel,image) partial sum / sumsq ------------------
// Deterministic: fixed lane-strided order + shuffle tree; no atomics.
__global__ __launch_bounds__(256) void stats_kernel(int which, int HW)
{
    const float* buf = (which == 0) ? g_buf1 : (which == 1) ? g_buf3 : g_buf5;
    int img = blockIdx.x;
    int warp = threadIdx.x >> 5, lane = threadIdx.x & 31;
    for (int c = warp; c < 32; c += 8) {
        const float* p = buf + ((size_t)img * 32 + c) * HW;
        float s = 0.f, q = 0.f;
        for (int i = lane; i < HW; i += 32) { float v = p[i]; s += v; q += v * v; }
        s = warp_sum(s); q = warp_sum(q);
        if (lane == 0) {
            g_psum[c * NB + img] = s;
            g_psq[c * NB + img] = q;
        }
    }
}

// Per-channel reduction over 2048 images in fixed pairwise order, then
// compute BN scale/shift. One block per channel.
__global__ __launch_bounds__(256) void reduce_stats_kernel(
    int stage, float invN,
    const float* __restrict__ gamma, const float* __restrict__ beta)
{
    __shared__ float ss[256], sq[256];
    int c = blockIdx.x;
    int t = threadIdx.x;
    float s = 0.f, q = 0.f;
#pragma unroll
    for (int k = 0; k < NB / 256; k++) {
        int img = t + k * 256;
        s += g_psum[c * NB + img];
        q += g_psq[c * NB + img];
    }
    ss[t] = s; sq[t] = q;
    __syncthreads();
#pragma unroll
    for (int off = 128; off; off >>= 1) {
        if (t < off) { ss[t] += ss[t + off]; sq[t] += sq[t + off]; }
        __syncthreads();
    }
    if (t == 0) {
        float mu = ss[0] * invN;
        float var = sq[0] * invN - mu * mu;
        float sc = gamma[c] * rsqrtf(var + 1e-5f);
        g_scale[stage][c] = sc;
        g_shift[stage][c] = beta[c] - mu * sc;
    }
}

// ---------------------- bn + relu + avgpool2 stages ------------------------
__global__ __launch_bounds__(256) void pool1_kernel() {
    int img = blockIdx.x;
    for (int i = threadIdx.x; i < 32 * 225; i += 256) {
        int c = i / 225, p = i % 225;
        int oy = p / 15, ox = p % 15;
        const float* b = g_buf1 + ((size_t)img * 32 + c) * 900 + (2 * oy) * 30 + 2 * ox;
        float sc = g_scale[0][c], sh = g_shift[0][c];
        float v = fmaxf(b[0] * sc + sh, 0.f) + fmaxf(b[1] * sc + sh, 0.f)
                + fmaxf(b[30] * sc + sh, 0.f) + fmaxf(b[31] * sc + sh, 0.f);
        g_buf2[((size_t)img * 32 + c) * 225 + p] = v * 0.25f;
    }
}

__global__ __launch_bounds__(256) void pool2_kernel() {
    int img = blockIdx.x;
    for (int i = threadIdx.x; i < 32 * 36; i += 256) {
        int c = i / 36, p = i % 36;
        int oy = p / 6, ox = p % 6;
        const float* b = g_buf3 + ((size_t)img * 32 + c) * 169 + (2 * oy) * 13 + 2 * ox;
        float sc = g_scale[1][c], sh = g_shift[1][c];
        float v = fmaxf(b[0] * sc + sh, 0.f) + fmaxf(b[1] * sc + sh, 0.f)
                + fmaxf(b[13] * sc + sh, 0.f) + fmaxf(b[14] * sc + sh, 0.f);
        g_buf4[((size_t)img * 32 + c) * 36 + p] = v * 0.25f;
    }
}

__global__ __launch_bounds__(128) void pool3_kernel() {
    int img = blockIdx.x;
    int i = threadIdx.x;   // 0..127 = c*4 + oy*2 + ox
    int c = i >> 2, p = i & 3;
    int oy = p >> 1, ox = p & 1;
    const float* b = g_buf5 + ((size_t)img * 32 + c) * 16 + (2 * oy) * 4 + 2 * ox;
    float sc = g_scale[2][c], sh = g_shift[2][c];
    float v = fmaxf(b[0] * sc + sh, 0.f) + fmaxf(b[1] * sc + sh, 0.f)
            + fmaxf(b[4] * sc + sh, 0.f) + fmaxf(b[5] * sc + sh, 0.f);
    g_h0[(size_t)img * 128 + i] = v * 0.25f;
}

// ------------------- conv2: 32->32, 15x15 -> 13x13 -------------------------
// 224 threads (208 active = 16 oc-pairs x 13 rows). Dynamic smem 65.7KB.
__global__ __launch_bounds__(224) void conv2_kernel(
    const float* __restrict__ w, const float* __restrict__ bias)
{
    extern __shared__ float sm[];
    float* s_img = sm;           // 32*225 = 7200
    float* s_w = sm + 7200;      // 288*32 = 9216, layout [ic*9+k][oc]
    __shared__ float s_b[32];
    int tid = threadIdx.x;
    int img = blockIdx.x;
    const float* ib = g_buf2 + (size_t)img * 7200;
    for (int i = tid; i < 7200; i += 224) s_img[i] = ib[i];
    for (int i = tid; i < 9216; i += 224) {
        int oc = i / 288, r = i % 288;
        s_w[r * 32 + oc] = w[i];
    }
    if (tid < 32) s_b[tid] = bias[tid];
    __syncthreads();

    if (tid < 208) {
        int ocp = tid & 15;
        int row = tid >> 4;   // 0..12
        u64t acc[13];
        u64t bv = *(const u64t*)(s_b + ocp * 2);
#pragma unroll
        for (int i = 0; i < 13; i++) acc[i] = bv;

        for (int ic = 0; ic < 32; ic++) {
#pragma unroll
            for (int ky = 0; ky < 3; ky++) {
                const float* irow = s_img + ic * 225 + (row + ky) * 15;
                float in[15];
#pragma unroll
                for (int i = 0; i < 15; i++) in[i] = irow[i];
#pragma unroll
                for (int kx = 0; kx < 3; kx++) {
                    u64t wv = *(const u64t*)(s_w + (ic * 9 + ky * 3 + kx) * 32 + ocp * 2);
#pragma unroll
                    for (int ox = 0; ox < 13; ox++)
                        ffma2(acc[ox], wv, splat2(in[ox + kx]));
                }
            }
        }
        float* ob = g_buf3 + ((size_t)img * 32 + ocp * 2) * 169 + row * 13;
#pragma unroll
        for (int ox = 0; ox < 13; ox++) { ob[ox] = lo32(acc[ox]); ob[169 + ox] = hi32(acc[ox]); }
    }
}

// ------------------- conv3: 32->32, 6x6 -> 4x4 -----------------------------
// 256 threads = 16 oc-pairs x 16 pixels.
__global__ __launch_bounds__(256) void conv3_kernel(
    const float* __restrict__ w, const float* __restrict__ bias)
{
    __shared__ float s_img[32 * 36];
    __shared__ float s_w[288 * 32];
    __shared__ float s_b[32];
    int tid = threadIdx.x;
    int img = blockIdx.x;
    const float* ib = g_buf4 + (size_t)img * 1152;
    for (int i = tid; i < 1152; i += 256) s_img[i] = ib[i];
    for (int i = tid; i < 9216; i += 256) {
        int oc = i / 288, r = i % 288;
        s_w[r * 32 + oc] = w[i];
    }
    if (tid < 32) s_b[tid] = bias[tid];
    __syncthreads();

    int ocp = tid & 15;
    int pix = tid >> 4;         // 0..15
    int oy = pix >> 2, ox = pix & 3;
    u64t acc = *(const u64t*)(s_b + ocp * 2);
    for (int ic = 0; ic < 32; ic++) {
#pragma unroll
        for (int ky = 0; ky < 3; ky++) {
            const float* irow = s_img + ic * 36 + (oy + ky) * 6 + ox;
#pragma unroll
            for (int kx = 0; kx < 3; kx++) {
                u64t wv = *(const u64t*)(s_w + (ic * 9 + ky * 3 + kx) * 32 + ocp * 2);
                ffma2(acc, wv, splat2(irow[kx]));
            }
        }
    }
    float* ob = g_buf5 + ((size_t)img * 32 + ocp * 2) * 16 + pix;
    ob[0] = lo32(acc);
    ob[16] = hi32(acc);
}

// --------------------------- beam search -----------------------------------
// One 128-thread block per sample.
__global__ __launch_bounds__(128) void beam_kernel(
    const float* __restrict__ W_hh, const float* __restrict__ b_h,
    const float* __restrict__ E_op, const float* __restrict__ W_ho,
    const float* __restrict__ b_ho)
{
    __shared__ float s_h0[128];
    __shared__ float s_h[4][128];
    __shared__ float s_hn[4][128];
    __shared__ float s_Who[512];    // same linear layout as W_ho [d][o]
    __shared__ float s_logits[4][4];
    __shared__ float s_scores[4];
    __shared__ int   s_op[4];
    __shared__ int   s_src[4];

    int n = blockIdx.x;
    int tid = threadIdx.x;
    int warp = tid >> 5, lane = tid & 31;

    s_h0[tid] = g_h0[(size_t)n * 128 + tid];
#pragma unroll
    for (int i = 0; i < 4; i++) s_Who[i * 128 + tid] = W_ho[i * 128 + tid];
    __syncthreads();

    // logits0: warp o computes logit o
    {
        float a = 0.f;
        for (int d = lane; d < 128; d += 32) a += s_h0[d] * s_Who[d * 4 + warp];
        a = warp_sum(a);
        if (lane == 0) s_logits[0][warp] = a + b_ho[warp];
    }
    __syncthreads();

    if (tid == 0) {
        float l[4], e[4];
        float m = -FLT_MAX;
#pragma unroll
        for (int o = 0; o < 4; o++) { l[o] = s_logits[0][o]; m = fmaxf(m, l[o]); }
        float sum = 0.f;
#pragma unroll
        for (int o = 0; o < 4; o++) { e[o] = expf(l[o] - m); sum += e[o]; }
        float logsum = logf(sum);
        float inv = 1.f / sum;
        bool used[4] = {false, false, false, false};
        for (int b = 0; b < 4; b++) {
            int best = -1; float bv = -FLT_MAX;
            for (int o = 0; o < 4; o++) {
                float lp = l[o] - m - logsum;
                if (!used[o] && lp > bv) { bv = lp; best = o; }
            }
            used[best] = true;
            s_scores[b] = bv;
            s_op[b] = best;
            g_op[0 * (NB * 4) + n * 4 + b] = best;
            g_pv[0 * (NB * 4) + n * 4 + b] = e[best] * inv;
        }
    }
    __syncthreads();

    // common = h0 @ W_hh; h[b] = tanh(common + E_op[op_b] + b_h)
    {
        float common = 0.f;
#pragma unroll 8
        for (int k = 0; k < 128; k++) common += s_h0[k] * W_hh[k * 128 + tid];
        float bh = b_h[tid];
#pragma unroll
        for (int b = 0; b < 4; b++)
            s_h[b][tid] = tanhf(common + E_op[s_op[b] * 128 + tid] + bh);
    }
    __syncthreads();

    for (int step = 1; step < 3; step++) {
        // logits[b][*]: warp b handles beam b
        {
            float a0 = 0.f, a1 = 0.f, a2 = 0.f, a3 = 0.f;
            for (int d = lane; d < 128; d += 32) {
                float v = s_h[warp][d];
                a0 += v * s_Who[d * 4 + 0];
                a1 += v * s_Who[d * 4 + 1];
                a2 += v * s_Who[d * 4 + 2];
                a3 += v * s_Who[d * 4 + 3];
            }
            a0 = warp_sum(a0); a1 = warp_sum(a1); a2 = warp_sum(a2); a3 = warp_sum(a3);
            if (lane == 0) {
                s_logits[warp][0] = a0 + b_ho[0];
                s_logits[warp][1] = a1 + b_ho[1];
                s_logits[warp][2] = a2 + b_ho[2];
                s_logits[warp][3] = a3 + b_ho[3];
            }
        }
        __syncthreads();

        if (tid == 0) {
            float cand[16], probs[16];
            for (int b = 0; b < 4; b++) {
                float l[4], e[4];
                float m = -FLT_MAX;
#pragma unroll
                for (int o = 0; o < 4; o++) { l[o] = s_logits[b][o]; m = fmaxf(m, l[o]); }
                float sum = 0.f;
#pragma unroll
                for (int o = 0; o < 4; o++) { e[o] = expf(l[o] - m); sum += e[o]; }
                float logsum = logf(sum);
                float inv = 1.f / sum;
#pragma unroll
                for (int o = 0; o < 4; o++) {
                    cand[b * 4 + o] = s_scores[b] + (l[o] - m - logsum);
                    probs[b * 4 + o] = e[o] * inv;
                }
            }
            bool used[16];
            for (int i = 0; i < 16; i++) used[i] = false;
            float ns[4];
            for (int b = 0; b < 4; b++) {
                int best = -1; float bv = -FLT_MAX;
                for (int f = 0; f < 16; f++)
                    if (!used[f] && cand[f] > bv) { bv = cand[f]; best = f; }
                used[best] = true;
                ns[b] = bv;
                int src = best >> 2, op = best & 3;
                s_src[b] = src; s_op[b] = op;
                g_op[step * (NB * 4) + n * 4 + b] = op;
                g_pv[step * (NB * 4) + n * 4 + b] = probs[best];
            }
#pragma unroll
            for (int b = 0; b < 4; b++) s_scores[b] = ns[b];
        }
        __syncthreads();

        if (step < 2) {
            int r0 = s_src[0], r1 = s_src[1], r2 = s_src[2], r3 = s_src[3];
            float a0 = 0.f, a1 = 0.f, a2 = 0.f, a3 = 0.f;
#pragma unroll 4
            for (int k = 0; k < 128; k++) {
                float wv = W_hh[k * 128 + tid];
                a0 += s_h[r0][k] * wv;
                a1 += s_h[r1][k] * wv;
                a2 += s_h[r2][k] * wv;
                a3 += s_h[r3][k] * wv;
            }
            float bh = b_h[tid];
            s_hn[0][tid] = tanhf(a0 + E_op[s_op[0] * 128 + tid] + bh);
            s_hn[1][tid] = tanhf(a1 + E_op[s_op[1] * 128 + tid] + bh);
            s_hn[2][tid] = tanhf(a2 + E_op[s_op[2] * 128 + tid] + bh);
            s_hn[3][tid] = tanhf(a3 + E_op[s_op[3] * 128 + tid] + bh);
            __syncthreads();
#pragma unroll
            for (int b = 0; b < 4; b++) s_h[b][tid] = s_hn[b][tid];
            __syncthreads();
        }
    }
}

// --------------------------- dispatch chain --------------------------------
__global__ __launch_bounds__(256) void hid_init_kernel() {
    size_t i = (size_t)blockIdx.x * 256 + threadIdx.x;   // over 8192*128
    int m = (int)(i >> 7), j = (int)(i & 127);
    int n = m >> 2;
    g_hid[i] = g_h0[(size_t)n * 128 + j];
}

__global__ __launch_bounds__(128) void dispatch_kernel(
    const float* __restrict__ exp_w, const float* __restrict__ exp_b, int step)
{
    __shared__ float s_hid[128];
    __shared__ int s_idx;
    __shared__ float s_val;
    int m = blockIdx.x;
    int j = threadIdx.x;
    s_hid[j] = g_hid[(size_t)m * 128 + j];
    if (j == 0) {
        int op = g_op[step * (NB * 4) + m];
        float p = g_pv[step * (NB * 4) + m];
        s_idx = (p > 0.f) ? op : 0;
        s_val = p;
    }
    __syncthreads();
    int e = s_idx;
    float val = s_val;
    float r;
    if (e == 3) {
        r = s_hid[j];
    } else {
        float acc = exp_b[e * 128 + j];
        const float* wp = exp_w + (size_t)e * 16384 + j;
#pragma unroll 4
        for (int d = 0; d < 128; d++) acc += s_hid[d] * wp[d * 128];
        r = acc;
    }
    g_hid[(size_t)m * 128 + j] = fmaxf(r * val, 0.f);
}

// --------------------------- final projection ------------------------------
__global__ __launch_bounds__(256) void out_kernel(
    const float* __restrict__ out_w, const float* __restrict__ out_b,
    float* __restrict__ out)
{
    int warp = threadIdx.x >> 5, lane = threadIdx.x & 31;
    int row = blockIdx.x * 8 + warp;   // 8192 rows
    const float* hp = g_hid + (size_t)row * 128;
    float acc[10];
#pragma unroll
    for (int o = 0; o < 10; o++) acc[o] = 0.f;
    for (int d = lane; d < 128; d += 32) {
        float v = hp[d];
#pragma unroll
        for (int o = 0; o < 10; o++) acc[o] += v * out_w[d * 10 + o];
    }
#pragma unroll
    for (int o = 0; o < 10; o++) acc[o] = warp_sum(acc[o]);
    if (lane == 0) {
#pragma unroll
        for (int o = 0; o < 10; o++) out[(size_t)row * 10 + o] = acc[o] + out_b[o];
    }
}

// ---------------------------------------------------------------------------
extern "C" void kernel_launch(void* const* d_in, const int* in_sizes, int n_in,
                              void* d_out, int out_size)
{
    const float* x    = (const float*)d_in[0];
    const float* cw1  = (const float*)d_in[1];
    const float* cb1  = (const float*)d_in[2];
    const float* g1   = (const float*)d_in[3];
    const float* be1  = (const float*)d_in[4];
    const float* cw2  = (const float*)d_in[5];
    const float* cb2  = (const float*)d_in[6];
    const float* g2   = (const float*)d_in[7];
    const float* be2  = (const float*)d_in[8];
    const float* cw3  = (const float*)d_in[9];
    const float* cb3  = (const float*)d_in[10];
    const float* g3   = (const float*)d_in[11];
    const float* be3  = (const float*)d_in[12];
    const float* W_hh = (const float*)d_in[13];
    const float* b_h  = (const float*)d_in[14];
    const float* E_op = (const float*)d_in[15];
    const float* W_ho = (const float*)d_in[16];
    const float* b_ho = (const float*)d_in[17];
    const float* expw = (const float*)d_in[18];
    const float* expb = (const float*)d_in[19];
    const float* outw = (const float*)d_in[20];
    const float* outb = (const float*)d_in[21];
    float* out = (float*)d_out;

    cudaFuncSetAttribute(conv2_kernel, cudaFuncAttributeMaxDynamicSharedMemorySize,
                         (7200 + 9216) * 4);

    conv1_kernel<<<NB, 480>>>(x, cw1, cb1);
    stats_kernel<<<NB, 256>>>(0, 900);
    reduce_stats_kernel<<<32, 256>>>(0, 1.f / (NB * 900.f), g1, be1);
    pool1_kernel<<<NB, 256>>>();

    conv2_kernel<<<NB, 224, (7200 + 9216) * 4>>>(cw2, cb2);
    stats_kernel<<<NB, 256>>>(1, 169);
    reduce_stats_kernel<<<32, 256>>>(1, 1.f / (NB * 169.f), g2, be2);
    pool2_kernel<<<NB, 256>>>();

    conv3_kernel<<<NB, 256>>>(cw3, cb3);
    stats_kernel<<<NB, 256>>>(2, 16);
    reduce_stats_kernel<<<32, 256>>>(2, 1.f / (NB * 16.f), g3, be3);
    pool3_kernel<<<NB, 128>>>();

    beam_kernel<<<NB, 128>>>(W_hh, b_h, E_op, W_ho, b_ho);

    hid_init_kernel<<<(NB * 4 * 128) / 256, 256>>>();
    dispatch_kernel<<<NB * 4, 128>>>(expw, expb, 0);
    dispatch_kernel<<<NB * 4, 128>>>(expw, expb, 1);
    dispatch_kernel<<<NB * 4, 128>>>(expw, expb, 2);

    out_kernel<<<NB * 4 / 8, 256>>>(outw, outb, out);
}

// round 5
// speedup vs baseline: 1.3529x; 1.3529x over previous
#include <cuda_runtime.h>
#include <math.h>
#include <float.h>
#include <stdint.h>

// ---------------------------------------------------------------------------
// Supernetwork: backbone (3x conv+BN+relu+pool) -> beam search -> MoE dispatch
// B=2048, BEAMS=4, DEPTH=3, HID=128, NOPS=4
//
// Round-5 structure:
//  * All intermediate activation buffers are NHWC so conv stores are
//    contiguous channel-pairs (STG.64, fully coalesced) - kills the ~8x DRAM
//    write amplification of the NCHW scatter stores.
//  * BN batch stats fused into each conv kernel (register-side sums,
//    fixed-order smem reduction -> per-image partials). No stats kernels.
//  * hid_init + 3 dispatch steps + output projection fused into ONE kernel:
//    hid stays in SMEM, experts computed as dense SMEM GEMMs.
//  * Determinism: no float atomics; every FP reduction has a fixed order.
// ---------------------------------------------------------------------------

#define NB 2048

// ------------------------------ scratch ------------------------------------
__device__ float g_buf1[(size_t)NB * 30 * 30 * 32];  // conv1 out, NHWC
__device__ float g_buf2[(size_t)NB * 15 * 15 * 32];  // pool1 out, NHWC
__device__ float g_buf3[(size_t)NB * 13 * 13 * 32];  // conv2 out, NHWC
__device__ float g_buf4[(size_t)NB * 6 * 6 * 32];    // pool2 out, NHWC
__device__ float g_buf5[(size_t)NB * 16 * 32];       // conv3 out, NHWC (4x4)
__device__ float g_h0[(size_t)NB * 128];             // backbone feature (NCHW flatten)
__device__ float g_psum[32 * NB];                    // per-(channel,img) partial sum
__device__ float g_psq[32 * NB];                     // per-(channel,img) partial sumsq
__device__ float g_scale[3][32];
__device__ float g_shift[3][32];
__device__ int   g_op[3 * NB * 4];                   // [step][n*4+beam]
__device__ float g_pv[3 * NB * 4];

// --------------------------- f32x2 helpers ---------------------------------
typedef unsigned long long u64t;

__device__ __forceinline__ void ffma2(u64t& c, u64t a, u64t b) {
    asm("fma.rn.f32x2 %0, %1, %2, %0;" : "+l"(c) : "l"(a), "l"(b));
}
__device__ __forceinline__ u64t splat2(float v) {
    u64t r;
    asm("mov.b64 %0, {%1, %1};" : "=l"(r) : "r"(__float_as_uint(v)));
    return r;
}
__device__ __forceinline__ float lo32(u64t v) { return __uint_as_float((unsigned)v); }
__device__ __forceinline__ float hi32(u64t v) { return __uint_as_float((unsigned)(v >> 32)); }

__device__ __forceinline__ float warp_sum(float v) {
#pragma unroll
    for (int off = 16; off; off >>= 1) v += __shfl_down_sync(0xffffffffu, v, off);
    return v;
}

// ------------------- conv1: 3->32, 32x32 -> 30x30, fused stats -------------
// 480 threads = 16 oc-pairs x 30 output rows. Output NHWC via STG.64.
__global__ __launch_bounds__(480) void conv1_kernel(
    const float* __restrict__ x, const float* __restrict__ w,
    const float* __restrict__ bias)
{
    __shared__ float s_img[3 * 1024];
    __shared__ float s_w[27 * 32];   // [k][oc]
    __shared__ float s_b[32];
    __shared__ float s_ss[32][30];
    __shared__ float s_sq[32][30];
    int tid = threadIdx.x;
    int img = blockIdx.x;
    const float* xb = x + (size_t)img * 3072;
    for (int i = tid; i < 3072; i += 480) s_img[i] = xb[i];
    for (int i = tid; i < 864; i += 480) {
        int oc = i / 27, k = i % 27;
        s_w[k * 32 + oc] = w[i];
    }
    if (tid < 32) s_b[tid] = bias[tid];
    __syncthreads();

    int ocp = tid & 15;
    int row = tid >> 4;   // 0..29
    u64t acc[30];
    u64t bv = *(const u64t*)(s_b + ocp * 2);
#pragma unroll
    for (int i = 0; i < 30; i++) acc[i] = bv;

#pragma unroll
    for (int ic = 0; ic < 3; ic++) {
#pragma unroll
        for (int ky = 0; ky < 3; ky++) {
            const float* irow = s_img + ic * 1024 + (row + ky) * 32;
            float in[32];
#pragma unroll
            for (int i = 0; i < 32; i++) in[i] = irow[i];
#pragma unroll
            for (int kx = 0; kx < 3; kx++) {
                u64t wv = *(const u64t*)(s_w + ((ic * 3 + ky) * 3 + kx) * 32 + ocp * 2);
#pragma unroll
                for (int ox = 0; ox < 30; ox++)
                    ffma2(acc[ox], wv, splat2(in[ox + kx]));
            }
        }
    }
    // NHWC store: ((img*30+row)*30+ox)*32 + 2*ocp   -> coalesced STG.64
    u64t* ob = (u64t*)(g_buf1 + (((size_t)img * 30 + row) * 30) * 32 + 2 * ocp);
    float slo = 0.f, qlo = 0.f, shi = 0.f, qhi = 0.f;
#pragma unroll
    for (int ox = 0; ox < 30; ox++) {
        u64t v = acc[ox];
        ob[ox * 16] = v;   // 16 u64 = 32 floats per pixel
        float a = lo32(v), b2 = hi32(v);
        slo += a; qlo += a * a; shi += b2; qhi += b2 * b2;
    }
    s_ss[2 * ocp][row] = slo; s_sq[2 * ocp][row] = qlo;
    s_ss[2 * ocp + 1][row] = shi; s_sq[2 * ocp + 1][row] = qhi;
    __syncthreads();
    if (tid < 32) {
        float s = 0.f, q = 0.f;
#pragma unroll
        for (int r = 0; r < 30; r++) { s += s_ss[tid][r]; q += s_sq[tid][r]; }
        g_psum[tid * NB + img] = s;
        g_psq[tid * NB + img] = q;
    }
}

// Per-channel reduction over 2048 images (fixed pairwise order) -> scale/shift.
__global__ __launch_bounds__(256) void reduce_stats_kernel(
    int stage, float invN,
    const float* __restrict__ gamma, const float* __restrict__ beta)
{
    __shared__ float ss[256], sq[256];
    int c = blockIdx.x;
    int t = threadIdx.x;
    float s = 0.f, q = 0.f;
#pragma unroll
    for (int k = 0; k < NB / 256; k++) {
        int img = t + k * 256;
        s += g_psum[c * NB + img];
        q += g_psq[c * NB + img];
    }
    ss[t] = s; sq[t] = q;
    __syncthreads();
#pragma unroll
    for (int off = 128; off; off >>= 1) {
        if (t < off) { ss[t] += ss[t + off]; sq[t] += sq[t + off]; }
        __syncthreads();
    }
    if (t == 0) {
        float mu = ss[0] * invN;
        float var = sq[0] * invN - mu * mu;
        float sc = gamma[c] * rsqrtf(var + 1e-5f);
        g_scale[stage][c] = sc;
        g_shift[stage][c] = beta[c] - mu * sc;
    }
}

// ---------------------- bn + relu + avgpool2 (NHWC->NHWC) ------------------
__global__ __launch_bounds__(256) void pool1_kernel() {
    int img = blockIdx.x;
    for (int i = threadIdx.x; i < 7200; i += 256) {
        int c = i & 31, p = i >> 5;           // p = oy*15+ox
        int oy = p / 15, ox = p % 15;
        const float* b = g_buf1 + (((size_t)img * 30 + 2 * oy) * 30 + 2 * ox) * 32 + c;
        float sc = g_scale[0][c], sh = g_shift[0][c];
        float v = fmaxf(b[0] * sc + sh, 0.f) + fmaxf(b[32] * sc + sh, 0.f)
                + fmaxf(b[960] * sc + sh, 0.f) + fmaxf(b[992] * sc + sh, 0.f);
        g_buf2[((size_t)img * 225 + p) * 32 + c] = v * 0.25f;
    }
}

__global__ __launch_bounds__(256) void pool2_kernel() {
    int img = blockIdx.x;
    for (int i = threadIdx.x; i < 1152; i += 256) {
        int c = i & 31, p = i >> 5;           // p = oy*6+ox
        int oy = p / 6, ox = p % 6;
        const float* b = g_buf3 + (((size_t)img * 13 + 2 * oy) * 13 + 2 * ox) * 32 + c;
        float sc = g_scale[1][c], sh = g_shift[1][c];
        float v = fmaxf(b[0] * sc + sh, 0.f) + fmaxf(b[32] * sc + sh, 0.f)
                + fmaxf(b[416] * sc + sh, 0.f) + fmaxf(b[448] * sc + sh, 0.f);
        g_buf4[((size_t)img * 36 + p) * 32 + c] = v * 0.25f;
    }
}

__global__ __launch_bounds__(128) void pool3_kernel() {
    int img = blockIdx.x;
    int i = threadIdx.x;
    int c = i & 31, p = i >> 5;               // p = oy*2+ox
    int oy = p >> 1, ox = p & 1;
    const float* b = g_buf5 + ((size_t)img * 16 + (2 * oy) * 4 + 2 * ox) * 32 + c;
    float sc = g_scale[2][c], sh = g_shift[2][c];
    float v = fmaxf(b[0] * sc + sh, 0.f) + fmaxf(b[32] * sc + sh, 0.f)
            + fmaxf(b[128] * sc + sh, 0.f) + fmaxf(b[160] * sc + sh, 0.f);
    // h0 flattens NCHW: h0[c*4 + oy*2 + ox]
    g_h0[(size_t)img * 128 + c * 4 + p] = v * 0.25f;
}

// ------------- conv2: 32->32, 15x15 -> 13x13, fused stats ------------------
// 224 threads (208 active = 16 oc-pairs x 13 rows). Dynamic smem 65.7KB.
__global__ __launch_bounds__(224) void conv2_kernel(
    const float* __restrict__ w, const float* __restrict__ bias)
{
    extern __shared__ float sm[];
    float* s_img = sm;           // [c][225]
    float* s_w = sm + 7200;      // [ic*9+k][oc]
    __shared__ float s_b[32];
    __shared__ float s_ss[32][13];
    __shared__ float s_sq[32][13];
    int tid = threadIdx.x;
    int img = blockIdx.x;
    const float* ib = g_buf2 + (size_t)img * 7200;   // NHWC
    for (int i = tid; i < 7200; i += 224) {
        int c = i & 31, p = i >> 5;
        s_img[c * 225 + p] = ib[i];    // stride 225 (odd) -> conflict-free
    }
    for (int i = tid; i < 9216; i += 224) {
        int oc = i / 288, r = i % 288;
        s_w[r * 32 + oc] = w[i];
    }
    if (tid < 32) s_b[tid] = bias[tid];
    __syncthreads();

    if (tid < 208) {
        int ocp = tid & 15;
        int row = tid >> 4;   // 0..12
        u64t acc[13];
        u64t bv = *(const u64t*)(s_b + ocp * 2);
#pragma unroll
        for (int i = 0; i < 13; i++) acc[i] = bv;

        for (int ic = 0; ic < 32; ic++) {
#pragma unroll
            for (int ky = 0; ky < 3; ky++) {
                const float* irow = s_img + ic * 225 + (row + ky) * 15;
                float in[15];
#pragma unroll
                for (int i = 0; i < 15; i++) in[i] = irow[i];
#pragma unroll
                for (int kx = 0; kx < 3; kx++) {
                    u64t wv = *(const u64t*)(s_w + (ic * 9 + ky * 3 + kx) * 32 + ocp * 2);
#pragma unroll
                    for (int ox = 0; ox < 13; ox++)
                        ffma2(acc[ox], wv, splat2(in[ox + kx]));
                }
            }
        }
        u64t* ob = (u64t*)(g_buf3 + (((size_t)img * 13 + row) * 13) * 32 + 2 * ocp);
        float slo = 0.f, qlo = 0.f, shi = 0.f, qhi = 0.f;
#pragma unroll
        for (int ox = 0; ox < 13; ox++) {
            u64t v = acc[ox];
            ob[ox * 16] = v;
            float a = lo32(v), b2 = hi32(v);
            slo += a; qlo += a * a; shi += b2; qhi += b2 * b2;
        }
        s_ss[2 * ocp][row] = slo; s_sq[2 * ocp][row] = qlo;
        s_ss[2 * ocp + 1][row] = shi; s_sq[2 * ocp + 1][row] = qhi;
    }
    __syncthreads();
    if (tid < 32) {
        float s = 0.f, q = 0.f;
#pragma unroll
        for (int r = 0; r < 13; r++) { s += s_ss[tid][r]; q += s_sq[tid][r]; }
        g_psum[tid * NB + img] = s;
        g_psq[tid * NB + img] = q;
    }
}

// ------------- conv3: 32->32, 6x6 -> 4x4, fused stats ----------------------
// 256 threads = 16 oc-pairs x 16 pixels.
__global__ __launch_bounds__(256) void conv3_kernel(
    const float* __restrict__ w, const float* __restrict__ bias)
{
    __shared__ float s_img[32 * 37];   // padded stride 37 -> conflict-free
    __shared__ float s_w[288 * 32];
    __shared__ float s_b[32];
    __shared__ float s_ss[32][16];
    __shared__ float s_sq[32][16];
    int tid = threadIdx.x;
    int img = blockIdx.x;
    const float* ib = g_buf4 + (size_t)img * 1152;   // NHWC
    for (int i = tid; i < 1152; i += 256) {
        int c = i & 31, p = i >> 5;
        s_img[c * 37 + p] = ib[i];
    }
    for (int i = tid; i < 9216; i += 256) {
        int oc = i / 288, r = i % 288;
        s_w[r * 32 + oc] = w[i];
    }
    if (tid < 32) s_b[tid] = bias[tid];
    __syncthreads();

    int ocp = tid & 15;
    int pix = tid >> 4;         // 0..15
    int oy = pix >> 2, ox = pix & 3;
    u64t acc = *(const u64t*)(s_b + ocp * 2);
    for (int ic = 0; ic < 32; ic++) {
#pragma unroll
        for (int ky = 0; ky < 3; ky++) {
            const float* irow = s_img + ic * 37 + (oy + ky) * 6 + ox;
#pragma unroll
            for (int kx = 0; kx < 3; kx++) {
                u64t wv = *(const u64t*)(s_w + (ic * 9 + ky * 3 + kx) * 32 + ocp * 2);
                ffma2(acc, wv, splat2(irow[kx]));
            }
        }
    }
    *(u64t*)(g_buf5 + ((size_t)img * 16 + pix) * 32 + 2 * ocp) = acc;
    float a = lo32(acc), b2 = hi32(acc);
    s_ss[2 * ocp][pix] = a;  s_sq[2 * ocp][pix] = a * a;
    s_ss[2 * ocp + 1][pix] = b2; s_sq[2 * ocp + 1][pix] = b2 * b2;
    __syncthreads();
    if (tid < 32) {
        float s = 0.f, q = 0.f;
#pragma unroll
        for (int r = 0; r < 16; r++) { s += s_ss[tid][r]; q += s_sq[tid][r]; }
        g_psum[tid * NB + img] = s;
        g_psq[tid * NB + img] = q;
    }
}

// --------------------------- beam search -----------------------------------
__global__ __launch_bounds__(128) void beam_kernel(
    const float* __restrict__ W_hh, const float* __restrict__ b_h,
    const float* __restrict__ E_op, const float* __restrict__ W_ho,
    const float* __restrict__ b_ho)
{
    __shared__ float s_h0[128];
    __shared__ float s_h[4][128];
    __shared__ float s_hn[4][128];
    __shared__ float s_Who[512];
    __shared__ float s_logits[4][4];
    __shared__ float s_scores[4];
    __shared__ int   s_op[4];
    __shared__ int   s_src[4];

    int n = blockIdx.x;
    int tid = threadIdx.x;
    int warp = tid >> 5, lane = tid & 31;

    s_h0[tid] = g_h0[(size_t)n * 128 + tid];
#pragma unroll
    for (int i = 0; i < 4; i++) s_Who[i * 128 + tid] = W_ho[i * 128 + tid];
    __syncthreads();

    {
        float a = 0.f;
        for (int d = lane; d < 128; d += 32) a += s_h0[d] * s_Who[d * 4 + warp];
        a = warp_sum(a);
        if (lane == 0) s_logits[0][warp] = a + b_ho[warp];
    }
    __syncthreads();

    if (tid == 0) {
        float l[4], e[4];
        float m = -FLT_MAX;
#pragma unroll
        for (int o = 0; o < 4; o++) { l[o] = s_logits[0][o]; m = fmaxf(m, l[o]); }
        float sum = 0.f;
#pragma unroll
        for (int o = 0; o < 4; o++) { e[o] = expf(l[o] - m); sum += e[o]; }
        float logsum = logf(sum);
        float inv = 1.f / sum;
        bool used[4] = {false, false, false, false};
        for (int b = 0; b < 4; b++) {
            int best = -1; float bv = -FLT_MAX;
            for (int o = 0; o < 4; o++) {
                float lp = l[o] - m - logsum;
                if (!used[o] && lp > bv) { bv = lp; best = o; }
            }
            used[best] = true;
            s_scores[b] = bv;
            s_op[b] = best;
            g_op[0 * (NB * 4) + n * 4 + b] = best;
            g_pv[0 * (NB * 4) + n * 4 + b] = e[best] * inv;
        }
    }
    __syncthreads();

    {
        float common = 0.f;
#pragma unroll 8
        for (int k = 0; k < 128; k++) common += s_h0[k] * W_hh[k * 128 + tid];
        float bh = b_h[tid];
#pragma unroll
        for (int b = 0; b < 4; b++)
            s_h[b][tid] = tanhf(common + E_op[s_op[b] * 128 + tid] + bh);
    }
    __syncthreads();

    for (int step = 1; step < 3; step++) {
        {
            float a0 = 0.f, a1 = 0.f, a2 = 0.f, a3 = 0.f;
            for (int d = lane; d < 128; d += 32) {
                float v = s_h[warp][d];
                a0 += v * s_Who[d * 4 + 0];
                a1 += v * s_Who[d * 4 + 1];
                a2 += v * s_Who[d * 4 + 2];
                a3 += v * s_Who[d * 4 + 3];
            }
            a0 = warp_sum(a0); a1 = warp_sum(a1); a2 = warp_sum(a2); a3 = warp_sum(a3);
            if (lane == 0) {
                s_logits[warp][0] = a0 + b_ho[0];
                s_logits[warp][1] = a1 + b_ho[1];
                s_logits[warp][2] = a2 + b_ho[2];
                s_logits[warp][3] = a3 + b_ho[3];
            }
        }
        __syncthreads();

        if (tid == 0) {
            float cand[16], probs[16];
            for (int b = 0; b < 4; b++) {
                float l[4], e[4];
                float m = -FLT_MAX;
#pragma unroll
                for (int o = 0; o < 4; o++) { l[o] = s_logits[b][o]; m = fmaxf(m, l[o]); }
                float sum = 0.f;
#pragma unroll
                for (int o = 0; o < 4; o++) { e[o] = expf(l[o] - m); sum += e[o]; }
                float logsum = logf(sum);
                float inv = 1.f / sum;
#pragma unroll
                for (int o = 0; o < 4; o++) {
                    cand[b * 4 + o] = s_scores[b] + (l[o] - m - logsum);
                    probs[b * 4 + o] = e[o] * inv;
                }
            }
            bool used[16];
            for (int i = 0; i < 16; i++) used[i] = false;
            float ns[4];
            for (int b = 0; b < 4; b++) {
                int best = -1; float bv = -FLT_MAX;
                for (int f = 0; f < 16; f++)
                    if (!used[f] && cand[f] > bv) { bv = cand[f]; best = f; }
                used[best] = true;
                ns[b] = bv;
                int src = best >> 2, op = best & 3;
                s_src[b] = src; s_op[b] = op;
                g_op[step * (NB * 4) + n * 4 + b] = op;
                g_pv[step * (NB * 4) + n * 4 + b] = probs[best];
            }
#pragma unroll
            for (int b = 0; b < 4; b++) s_scores[b] = ns[b];
        }
        __syncthreads();

        if (step < 2) {
            int r0 = s_src[0], r1 = s_src[1], r2 = s_src[2], r3 = s_src[3];
            float a0 = 0.f, a1 = 0.f, a2 = 0.f, a3 = 0.f;
#pragma unroll 4
            for (int k = 0; k < 128; k++) {
                float wv = W_hh[k * 128 + tid];
                a0 += s_h[r0][k] * wv;
                a1 += s_h[r1][k] * wv;
                a2 += s_h[r2][k] * wv;
                a3 += s_h[r3][k] * wv;
            }
            float bh = b_h[tid];
            s_hn[0][tid] = tanhf(a0 + E_op[s_op[0] * 128 + tid] + bh);
            s_hn[1][tid] = tanhf(a1 + E_op[s_op[1] * 128 + tid] + bh);
            s_hn[2][tid] = tanhf(a2 + E_op[s_op[2] * 128 + tid] + bh);
            s_hn[3][tid] = tanhf(a3 + E_op[s_op[3] * 128 + tid] + bh);
            __syncthreads();
#pragma unroll
            for (int b = 0; b < 4; b++) s_h[b][tid] = s_hn[b][tid];
            __syncthreads();
        }
    }
}

// ------------- fused dispatch chain + output projection --------------------
// 256 blocks x 32 rows. hid lives in SMEM across all 3 steps; each step
// computes all 3 experts as dense SMEM GEMMs and merges by op (e==3 identity).
__global__ __launch_bounds__(256) void dispatch_all_kernel(
    const float* __restrict__ exp_w, const float* __restrict__ exp_b,
    const float* __restrict__ out_w, const float* __restrict__ out_b,
    float* __restrict__ out)
{
    extern __shared__ float sm[];
    float* s_w = sm;              // 16384 floats (64KB)
    float* buf0 = sm + 16384;     // 32x128
    float* buf1 = sm + 20480;     // 32x128
    __shared__ float s_b[128];
    __shared__ float s_outw[1280];
    __shared__ float s_outb[10];
    __shared__ int   s_opA[32];
    __shared__ float s_pvA[32];

    int tid = threadIdx.x;
    int mb = blockIdx.x * 32;

    for (int i = tid; i < 4096; i += 256) {
        int r = i >> 7, j = i & 127;
        buf0[i] = g_h0[(size_t)((mb + r) >> 2) * 128 + j];
    }
    for (int i = tid; i < 1280; i += 256) s_outw[i] = out_w[i];
    if (tid < 10) s_outb[tid] = out_b[tid];

    float* cur = buf0;
    float* nxt = buf1;

    int cp = tid & 63, rowg = tid >> 6;
    int r0 = rowg * 8, j0 = cp * 2;

    for (int step = 0; step < 3; step++) {
        if (tid < 32) {
            int op = g_op[step * (NB * 4) + mb + tid];
            float p = g_pv[step * (NB * 4) + mb + tid];
            s_opA[tid] = (p > 0.f) ? op : 0;
            s_pvA[tid] = p;
        }
        __syncthreads();

        // identity rows (op==3)
        for (int i = tid; i < 4096; i += 256) {
            int r = i >> 7;
            if (s_opA[r] == 3) nxt[i] = fmaxf(cur[i] * s_pvA[r], 0.f);
        }

        for (int e = 0; e < 3; e++) {
            __syncthreads();   // prior users of s_w / identity writers done
            for (int i = tid; i < 16384; i += 256) s_w[i] = exp_w[e * 16384 + i];
            if (tid < 128) s_b[tid] = exp_b[e * 128 + tid];
            __syncthreads();

            u64t acc[8];
#pragma unroll
            for (int k = 0; k < 8; k++) acc[k] = 0ull;
#pragma unroll 2
            for (int d = 0; d < 128; d++) {
                u64t w2 = *(const u64t*)(s_w + d * 128 + j0);
#pragma unroll
                for (int k = 0; k < 8; k++)
                    ffma2(acc[k], w2, splat2(cur[(r0 + k) * 128 + d]));
            }
            u64t b2 = *(const u64t*)(s_b + j0);
#pragma unroll
            for (int k = 0; k < 8; k++) {
                int r = r0 + k;
                if (s_opA[r] == e) {
                    float v = s_pvA[r];
                    float2 st;
                    st.x = fmaxf((lo32(acc[k]) + lo32(b2)) * v, 0.f);
                    st.y = fmaxf((hi32(acc[k]) + hi32(b2)) * v, 0.f);
                    *(float2*)(nxt + r * 128 + j0) = st;
                }
            }
        }
        __syncthreads();
        float* t = cur; cur = nxt; nxt = t;
    }

    // output projection: 32 rows x 10
    for (int i = tid; i < 320; i += 256) {
        int r = i / 10, o = i % 10;
        float a = s_outb[o];
        const float* hp = cur + r * 128;
#pragma unroll 8
        for (int d = 0; d < 128; d++) a += hp[d] * s_outw[d * 10 + o];
        out[(size_t)(mb + r) * 10 + o] = a;
    }
}

// ---------------------------------------------------------------------------
extern "C" void kernel_launch(void* const* d_in, const int* in_sizes, int n_in,
                              void* d_out, int out_size)
{
    const float* x    = (const float*)d_in[0];
    const float* cw1  = (const float*)d_in[1];
    const float* cb1  = (const float*)d_in[2];
    const float* g1   = (const float*)d_in[3];
    const float* be1  = (const float*)d_in[4];
    const float* cw2  = (const float*)d_in[5];
    const float* cb2  = (const float*)d_in[6];
    const float* g2   = (const float*)d_in[7];
    const float* be2  = (const float*)d_in[8];
    const float* cw3  = (const float*)d_in[9];
    const float* cb3  = (const float*)d_in[10];
    const float* g3   = (const float*)d_in[11];
    const float* be3  = (const float*)d_in[12];
    const float* W_hh = (const float*)d_in[13];
    const float* b_h  = (const float*)d_in[14];
    const float* E_op = (const float*)d_in[15];
    const float* W_ho = (const float*)d_in[16];
    const float* b_ho = (const float*)d_in[17];
    const float* expw = (const float*)d_in[18];
    const float* expb = (const float*)d_in[19];
    const float* outw = (const float*)d_in[20];
    const float* outb = (const float*)d_in[21];
    float* out = (float*)d_out;

    cudaFuncSetAttribute(conv2_kernel, cudaFuncAttributeMaxDynamicSharedMemorySize,
                         (7200 + 9216) * 4);
    cudaFuncSetAttribute(dispatch_all_kernel, cudaFuncAttributeMaxDynamicSharedMemorySize,
                         24576 * 4);

    conv1_kernel<<<NB, 480>>>(x, cw1, cb1);
    reduce_stats_kernel<<<32, 256>>>(0, 1.f / (NB * 900.f), g1, be1);
    pool1_kernel<<<NB, 256>>>();

    conv2_kernel<<<NB, 224, (7200 + 9216) * 4>>>(cw2, cb2);
    reduce_stats_kernel<<<32, 256>>>(1, 1.f / (NB * 169.f), g2, be2);
    pool2_kernel<<<NB, 256>>>();

    conv3_kernel<<<NB, 256>>>(cw3, cb3);
    reduce_stats_kernel<<<32, 256>>>(2, 1.f / (NB * 16.f), g3, be3);
    pool3_kernel<<<NB, 128>>>();

    beam_kernel<<<NB, 128>>>(W_hh, b_h, E_op, W_ho, b_ho);

    dispatch_all_kernel<<<NB * 4 / 32, 256, 24576 * 4>>>(expw, expb, outw, outb, out);
}

// round 6
// speedup vs baseline: 1.4668x; 1.0842x over previous
#include <cuda_runtime.h>
#include <math.h>
#include <float.h>
#include <stdint.h>

// ---------------------------------------------------------------------------
// Supernetwork: backbone (3x conv+BN+relu+pool) -> beam search -> MoE dispatch
// B=2048, BEAMS=4, DEPTH=3, HID=128, NOPS=4
//
// Round-6:
//  * conv2: 2 images/block, smem image rows padded to 16 floats so input
//    loads are LDS.128 (was 15x LDS.32 from odd-stride rows). occ 21->28
//    warps/SM, LDS instruction count ~3x lower.
//  * conv1: explicit float4 smem input loads.
//  * NHWC everywhere; BN stats fused in convs; fused dispatch+out kernel.
//  * Determinism: no float atomics; fixed-order reductions only.
// ---------------------------------------------------------------------------

#define NB 2048

// ------------------------------ scratch ------------------------------------
__device__ float g_buf1[(size_t)NB * 30 * 30 * 32];  // conv1 out, NHWC
__device__ float g_buf2[(size_t)NB * 15 * 15 * 32];  // pool1 out, NHWC
__device__ float g_buf3[(size_t)NB * 13 * 13 * 32];  // conv2 out, NHWC
__device__ float g_buf4[(size_t)NB * 6 * 6 * 32];    // pool2 out, NHWC
__device__ float g_buf5[(size_t)NB * 16 * 32];       // conv3 out, NHWC (4x4)
__device__ float g_h0[(size_t)NB * 128];             // backbone feature
__device__ float g_psum[32 * NB];
__device__ float g_psq[32 * NB];
__device__ float g_scale[3][32];
__device__ float g_shift[3][32];
__device__ int   g_op[3 * NB * 4];
__device__ float g_pv[3 * NB * 4];

// --------------------------- f32x2 helpers ---------------------------------
typedef unsigned long long u64t;

__device__ __forceinline__ void ffma2(u64t& c, u64t a, u64t b) {
    asm("fma.rn.f32x2 %0, %1, %2, %0;" : "+l"(c) : "l"(a), "l"(b));
}
__device__ __forceinline__ u64t splat2(float v) {
    u64t r;
    asm("mov.b64 %0, {%1, %1};" : "=l"(r) : "r"(__float_as_uint(v)));
    return r;
}
__device__ __forceinline__ float lo32(u64t v) { return __uint_as_float((unsigned)v); }
__device__ __forceinline__ float hi32(u64t v) { return __uint_as_float((unsigned)(v >> 32)); }

__device__ __forceinline__ float warp_sum(float v) {
#pragma unroll
    for (int off = 16; off; off >>= 1) v += __shfl_down_sync(0xffffffffu, v, off);
    return v;
}

// ------------------- conv1: 3->32, 32x32 -> 30x30, fused stats -------------
__global__ __launch_bounds__(480) void conv1_kernel(
    const float* __restrict__ x, const float* __restrict__ w,
    const float* __restrict__ bias)
{
    __shared__ float s_img[3 * 1024];
    __shared__ float s_w[27 * 32];
    __shared__ float s_b[32];
    __shared__ float s_ss[32][30];
    __shared__ float s_sq[32][30];
    int tid = threadIdx.x;
    int img = blockIdx.x;
    const float* xb = x + (size_t)img * 3072;
    for (int i = tid; i < 768; i += 480)
        ((float4*)s_img)[i] = ((const float4*)xb)[i];
    for (int i = tid; i < 864; i += 480) {
        int oc = i / 27, k = i % 27;
        s_w[k * 32 + oc] = w[i];
    }
    if (tid < 32) s_b[tid] = bias[tid];
    __syncthreads();

    int ocp = tid & 15;
    int row = tid >> 4;   // 0..29
    u64t acc[30];
    u64t bv = *(const u64t*)(s_b + ocp * 2);
#pragma unroll
    for (int i = 0; i < 30; i++) acc[i] = bv;

#pragma unroll
    for (int ic = 0; ic < 3; ic++) {
#pragma unroll
        for (int ky = 0; ky < 3; ky++) {
            const float4* irow4 = (const float4*)(s_img + ic * 1024 + (row + ky) * 32);
            float in[32];
#pragma unroll
            for (int i = 0; i < 8; i++) {
                float4 v4 = irow4[i];
                in[4 * i] = v4.x; in[4 * i + 1] = v4.y;
                in[4 * i + 2] = v4.z; in[4 * i + 3] = v4.w;
            }
#pragma unroll
            for (int kx = 0; kx < 3; kx++) {
                u64t wv = *(const u64t*)(s_w + ((ic * 3 + ky) * 3 + kx) * 32 + ocp * 2);
#pragma unroll
                for (int ox = 0; ox < 30; ox++)
                    ffma2(acc[ox], wv, splat2(in[ox + kx]));
            }
        }
    }
    u64t* ob = (u64t*)(g_buf1 + (((size_t)img * 30 + row) * 30) * 32 + 2 * ocp);
    float slo = 0.f, qlo = 0.f, shi = 0.f, qhi = 0.f;
#pragma unroll
    for (int ox = 0; ox < 30; ox++) {
        u64t v = acc[ox];
        ob[ox * 16] = v;
        float a = lo32(v), b2 = hi32(v);
        slo += a; qlo += a * a; shi += b2; qhi += b2 * b2;
    }
    s_ss[2 * ocp][row] = slo; s_sq[2 * ocp][row] = qlo;
    s_ss[2 * ocp + 1][row] = shi; s_sq[2 * ocp + 1][row] = qhi;
    __syncthreads();
    if (tid < 32) {
        float s = 0.f, q = 0.f;
#pragma unroll
        for (int r = 0; r < 30; r++) { s += s_ss[tid][r]; q += s_sq[tid][r]; }
        g_psum[tid * NB + img] = s;
        g_psq[tid * NB + img] = q;
    }
}

// Per-channel reduction over 2048 images (fixed pairwise order) -> scale/shift.
__global__ __launch_bounds__(256) void reduce_stats_kernel(
    int stage, float invN,
    const float* __restrict__ gamma, const float* __restrict__ beta)
{
    __shared__ float ss[256], sq[256];
    int c = blockIdx.x;
    int t = threadIdx.x;
    float s = 0.f, q = 0.f;
#pragma unroll
    for (int k = 0; k < NB / 256; k++) {
        int img = t + k * 256;
        s += g_psum[c * NB + img];
        q += g_psq[c * NB + img];
    }
    ss[t] = s; sq[t] = q;
    __syncthreads();
#pragma unroll
    for (int off = 128; off; off >>= 1) {
        if (t < off) { ss[t] += ss[t + off]; sq[t] += sq[t + off]; }
        __syncthreads();
    }
    if (t == 0) {
        float mu = ss[0] * invN;
        float var = sq[0] * invN - mu * mu;
        float sc = gamma[c] * rsqrtf(var + 1e-5f);
        g_scale[stage][c] = sc;
        g_shift[stage][c] = beta[c] - mu * sc;
    }
}

// ---------------------- bn + relu + avgpool2 (NHWC->NHWC) ------------------
__global__ __launch_bounds__(256) void pool1_kernel() {
    int img = blockIdx.x;
    for (int i = threadIdx.x; i < 7200; i += 256) {
        int c = i & 31, p = i >> 5;
        int oy = p / 15, ox = p % 15;
        const float* b = g_buf1 + (((size_t)img * 30 + 2 * oy) * 30 + 2 * ox) * 32 + c;
        float sc = g_scale[0][c], sh = g_shift[0][c];
        float v = fmaxf(b[0] * sc + sh, 0.f) + fmaxf(b[32] * sc + sh, 0.f)
                + fmaxf(b[960] * sc + sh, 0.f) + fmaxf(b[992] * sc + sh, 0.f);
        g_buf2[((size_t)img * 225 + p) * 32 + c] = v * 0.25f;
    }
}

__global__ __launch_bounds__(256) void pool2_kernel() {
    int img = blockIdx.x;
    for (int i = threadIdx.x; i < 1152; i += 256) {
        int c = i & 31, p = i >> 5;
        int oy = p / 6, ox = p % 6;
        const float* b = g_buf3 + (((size_t)img * 13 + 2 * oy) * 13 + 2 * ox) * 32 + c;
        float sc = g_scale[1][c], sh = g_shift[1][c];
        float v = fmaxf(b[0] * sc + sh, 0.f) + fmaxf(b[32] * sc + sh, 0.f)
                + fmaxf(b[416] * sc + sh, 0.f) + fmaxf(b[448] * sc + sh, 0.f);
        g_buf4[((size_t)img * 36 + p) * 32 + c] = v * 0.25f;
    }
}

__global__ __launch_bounds__(128) void pool3_kernel() {
    int img = blockIdx.x;
    int i = threadIdx.x;
    int c = i & 31, p = i >> 5;
    int oy = p >> 1, ox = p & 1;
    const float* b = g_buf5 + ((size_t)img * 16 + (2 * oy) * 4 + 2 * ox) * 32 + c;
    float sc = g_scale[2][c], sh = g_shift[2][c];
    float v = fmaxf(b[0] * sc + sh, 0.f) + fmaxf(b[32] * sc + sh, 0.f)
            + fmaxf(b[128] * sc + sh, 0.f) + fmaxf(b[160] * sc + sh, 0.f);
    g_h0[(size_t)img * 128 + c * 4 + p] = v * 0.25f;
}

// ------------- conv2: 32->32, 15x15 -> 13x13, 2 images/block ---------------
// 448 threads: sub-image = tid/224, local 224 (208 active = 16 ocp x 13 rows).
// smem image layout [c][row][16] (padded) -> LDS.128 input loads.
__global__ __launch_bounds__(448, 2) void conv2_kernel(
    const float* __restrict__ w, const float* __restrict__ bias)
{
    extern __shared__ float sm[];
    float* s_img = sm;            // 2 * 32*15*16 = 15360
    float* s_w = sm + 15360;      // 9216, layout [ic*9+k][oc]
    __shared__ float s_b[32];
    __shared__ float s_ss[2][32][13];
    __shared__ float s_sq[2][32][13];
    int tid = threadIdx.x;
    int img0 = blockIdx.x * 2;

    const float* ib = g_buf2 + (size_t)img0 * 7200;   // two consecutive images
    for (int i = tid; i < 14400; i += 448) {
        int sub = i / 7200, j = i % 7200;
        int c = j & 31, p = j >> 5;
        s_img[sub * 7680 + c * 240 + (p / 15) * 16 + (p % 15)] = ib[i];
    }
    for (int i = tid; i < 9216; i += 448) {
        int oc = i / 288, r = i % 288;
        s_w[r * 32 + oc] = w[i];
    }
    if (tid < 32) s_b[tid] = bias[tid];
    __syncthreads();

    int sub = tid / 224;
    int local = tid % 224;
    if (local < 208) {
        int ocp = local & 15;
        int row = local >> 4;   // 0..12
        const float* imgbase = s_img + sub * 7680;
        u64t acc[13];
        u64t bv = *(const u64t*)(s_b + ocp * 2);
#pragma unroll
        for (int i = 0; i < 13; i++) acc[i] = bv;

        for (int ic = 0; ic < 32; ic++) {
#pragma unroll
            for (int ky = 0; ky < 3; ky++) {
                const float4* irow4 = (const float4*)(imgbase + ic * 240 + (row + ky) * 16);
                float in[16];
#pragma unroll
                for (int i = 0; i < 4; i++) {
                    float4 v4 = irow4[i];
                    in[4 * i] = v4.x; in[4 * i + 1] = v4.y;
                    in[4 * i + 2] = v4.z; in[4 * i + 3] = v4.w;
                }
#pragma unroll
                for (int kx = 0; kx < 3; kx++) {
                    u64t wv = *(const u64t*)(s_w + (ic * 9 + ky * 3 + kx) * 32 + ocp * 2);
#pragma unroll
                    for (int ox = 0; ox < 13; ox++)
                        ffma2(acc[ox], wv, splat2(in[ox + kx]));
                }
            }
        }
        u64t* ob = (u64t*)(g_buf3 + (((size_t)(img0 + sub) * 13 + row) * 13) * 32 + 2 * ocp);
        float slo = 0.f, qlo = 0.f, shi = 0.f, qhi = 0.f;
#pragma unroll
        for (int ox = 0; ox < 13; ox++) {
            u64t v = acc[ox];
            ob[ox * 16] = v;
            float a = lo32(v), b2 = hi32(v);
            slo += a; qlo += a * a; shi += b2; qhi += b2 * b2;
        }
        s_ss[sub][2 * ocp][row] = slo; s_sq[sub][2 * ocp][row] = qlo;
        s_ss[sub][2 * ocp + 1][row] = shi; s_sq[sub][2 * ocp + 1][row] = qhi;
    }
    __syncthreads();
    if (tid < 64) {
        int ssub = tid >> 5, c = tid & 31;
        float s = 0.f, q = 0.f;
#pragma unroll
        for (int r = 0; r < 13; r++) { s += s_ss[ssub][c][r]; q += s_sq[ssub][c][r]; }
        g_psum[c * NB + img0 + ssub] = s;
        g_psq[c * NB + img0 + ssub] = q;
    }
}

// ------------- conv3: 32->32, 6x6 -> 4x4, fused stats ----------------------
__global__ __launch_bounds__(256) void conv3_kernel(
    const float* __restrict__ w, const float* __restrict__ bias)
{
    __shared__ float s_img[32 * 37];
    __shared__ float s_w[288 * 32];
    __shared__ float s_b[32];
    __shared__ float s_ss[32][16];
    __shared__ float s_sq[32][16];
    int tid = threadIdx.x;
    int img = blockIdx.x;
    const float* ib = g_buf4 + (size_t)img * 1152;
    for (int i = tid; i < 1152; i += 256) {
        int c = i & 31, p = i >> 5;
        s_img[c * 37 + p] = ib[i];
    }
    for (int i = tid; i < 9216; i += 256) {
        int oc = i / 288, r = i % 288;
        s_w[r * 32 + oc] = w[i];
    }
    if (tid < 32) s_b[tid] = bias[tid];
    __syncthreads();

    int ocp = tid & 15;
    int pix = tid >> 4;
    int oy = pix >> 2, ox = pix & 3;
    u64t acc = *(const u64t*)(s_b + ocp * 2);
    for (int ic = 0; ic < 32; ic++) {
#pragma unroll
        for (int ky = 0; ky < 3; ky++) {
            const float* irow = s_img + ic * 37 + (oy + ky) * 6 + ox;
#pragma unroll
            for (int kx = 0; kx < 3; kx++) {
                u64t wv = *(const u64t*)(s_w + (ic * 9 + ky * 3 + kx) * 32 + ocp * 2);
                ffma2(acc, wv, splat2(irow[kx]));
            }
        }
    }
    *(u64t*)(g_buf5 + ((size_t)img * 16 + pix) * 32 + 2 * ocp) = acc;
    float a = lo32(acc), b2 = hi32(acc);
    s_ss[2 * ocp][pix] = a;  s_sq[2 * ocp][pix] = a * a;
    s_ss[2 * ocp + 1][pix] = b2; s_sq[2 * ocp + 1][pix] = b2 * b2;
    __syncthreads();
    if (tid < 32) {
        float s = 0.f, q = 0.f;
#pragma unroll
        for (int r = 0; r < 16; r++) { s += s_ss[tid][r]; q += s_sq[tid][r]; }
        g_psum[tid * NB + img] = s;
        g_psq[tid * NB + img] = q;
    }
}

// --------------------------- beam search -----------------------------------
__global__ __launch_bounds__(128) void beam_kernel(
    const float* __restrict__ W_hh, const float* __restrict__ b_h,
    const float* __restrict__ E_op, const float* __restrict__ W_ho,
    const float* __restrict__ b_ho)
{
    __shared__ float s_h0[128];
    __shared__ float s_h[4][128];
    __shared__ float s_hn[4][128];
    __shared__ float s_Who[512];
    __shared__ float s_logits[4][4];
    __shared__ float s_scores[4];
    __shared__ int   s_op[4];
    __shared__ int   s_src[4];

    int n = blockIdx.x;
    int tid = threadIdx.x;
    int warp = tid >> 5, lane = tid & 31;

    s_h0[tid] = g_h0[(size_t)n * 128 + tid];
#pragma unroll
    for (int i = 0; i < 4; i++) s_Who[i * 128 + tid] = W_ho[i * 128 + tid];
    __syncthreads();

    {
        float a = 0.f;
        for (int d = lane; d < 128; d += 32) a += s_h0[d] * s_Who[d * 4 + warp];
        a = warp_sum(a);
        if (lane == 0) s_logits[0][warp] = a + b_ho[warp];
    }
    __syncthreads();

    if (tid == 0) {
        float l[4], e[4];
        float m = -FLT_MAX;
#pragma unroll
        for (int o = 0; o < 4; o++) { l[o] = s_logits[0][o]; m = fmaxf(m, l[o]); }
        float sum = 0.f;
#pragma unroll
        for (int o = 0; o < 4; o++) { e[o] = expf(l[o] - m); sum += e[o]; }
        float logsum = logf(sum);
        float inv = 1.f / sum;
        bool used[4] = {false, false, false, false};
        for (int b = 0; b < 4; b++) {
            int best = -1; float bv = -FLT_MAX;
            for (int o = 0; o < 4; o++) {
                float lp = l[o] - m - logsum;
                if (!used[o] && lp > bv) { bv = lp; best = o; }
            }
            used[best] = true;
            s_scores[b] = bv;
            s_op[b] = best;
            g_op[0 * (NB * 4) + n * 4 + b] = best;
            g_pv[0 * (NB * 4) + n * 4 + b] = e[best] * inv;
        }
    }
    __syncthreads();

    {
        float common = 0.f;
#pragma unroll 8
        for (int k = 0; k < 128; k++) common += s_h0[k] * W_hh[k * 128 + tid];
        float bh = b_h[tid];
#pragma unroll
        for (int b = 0; b < 4; b++)
            s_h[b][tid] = tanhf(common + E_op[s_op[b] * 128 + tid] + bh);
    }
    __syncthreads();

    for (int step = 1; step < 3; step++) {
        {
            float a0 = 0.f, a1 = 0.f, a2 = 0.f, a3 = 0.f;
            for (int d = lane; d < 128; d += 32) {
                float v = s_h[warp][d];
                a0 += v * s_Who[d * 4 + 0];
                a1 += v * s_Who[d * 4 + 1];
                a2 += v * s_Who[d * 4 + 2];
                a3 += v * s_Who[d * 4 + 3];
            }
            a0 = warp_sum(a0); a1 = warp_sum(a1); a2 = warp_sum(a2); a3 = warp_sum(a3);
            if (lane == 0) {
                s_logits[warp][0] = a0 + b_ho[0];
                s_logits[warp][1] = a1 + b_ho[1];
                s_logits[warp][2] = a2 + b_ho[2];
                s_logits[warp][3] = a3 + b_ho[3];
            }
        }
        __syncthreads();

        if (tid == 0) {
            float cand[16], probs[16];
            for (int b = 0; b < 4; b++) {
                float l[4], e[4];
                float m = -FLT_MAX;
#pragma unroll
                for (int o = 0; o < 4; o++) { l[o] = s_logits[b][o]; m = fmaxf(m, l[o]); }
                float sum = 0.f;
#pragma unroll
                for (int o = 0; o < 4; o++) { e[o] = expf(l[o] - m); sum += e[o]; }
                float logsum = logf(sum);
                float inv = 1.f / sum;
#pragma unroll
                for (int o = 0; o < 4; o++) {
                    cand[b * 4 + o] = s_scores[b] + (l[o] - m - logsum);
                    probs[b * 4 + o] = e[o] * inv;
                }
            }
            bool used[16];
            for (int i = 0; i < 16; i++) used[i] = false;
            float ns[4];
            for (int b = 0; b < 4; b++) {
                int best = -1; float bv = -FLT_MAX;
                for (int f = 0; f < 16; f++)
                    if (!used[f] && cand[f] > bv) { bv = cand[f]; best = f; }
                used[best] = true;
                ns[b] = bv;
                int src = best >> 2, op = best & 3;
                s_src[b] = src; s_op[b] = op;
                g_op[step * (NB * 4) + n * 4 + b] = op;
                g_pv[step * (NB * 4) + n * 4 + b] = probs[best];
            }
#pragma unroll
            for (int b = 0; b < 4; b++) s_scores[b] = ns[b];
        }
        __syncthreads();

        if (step < 2) {
            int r0 = s_src[0], r1 = s_src[1], r2 = s_src[2], r3 = s_src[3];
            float a0 = 0.f, a1 = 0.f, a2 = 0.f, a3 = 0.f;
#pragma unroll 4
            for (int k = 0; k < 128; k++) {
                float wv = W_hh[k * 128 + tid];
                a0 += s_h[r0][k] * wv;
                a1 += s_h[r1][k] * wv;
                a2 += s_h[r2][k] * wv;
                a3 += s_h[r3][k] * wv;
            }
            float bh = b_h[tid];
            s_hn[0][tid] = tanhf(a0 + E_op[s_op[0] * 128 + tid] + bh);
            s_hn[1][tid] = tanhf(a1 + E_op[s_op[1] * 128 + tid] + bh);
            s_hn[2][tid] = tanhf(a2 + E_op[s_op[2] * 128 + tid] + bh);
            s_hn[3][tid] = tanhf(a3 + E_op[s_op[3] * 128 + tid] + bh);
            __syncthreads();
#pragma unroll
            for (int b = 0; b < 4; b++) s_h[b][tid] = s_hn[b][tid];
            __syncthreads();
        }
    }
}

// ------------- fused dispatch chain + output projection --------------------
__global__ __launch_bounds__(256) void dispatch_all_kernel(
    const float* __restrict__ exp_w, const float* __restrict__ exp_b,
    const float* __restrict__ out_w, const float* __restrict__ out_b,
    float* __restrict__ out)
{
    extern __shared__ float sm[];
    float* s_w = sm;              // 16384 floats
    float* buf0 = sm + 16384;     // 32x128
    float* buf1 = sm + 20480;     // 32x128
    __shared__ float s_b[128];
    __shared__ float s_outw[1280];
    __shared__ float s_outb[10];
    __shared__ int   s_opA[32];
    __shared__ float s_pvA[32];

    int tid = threadIdx.x;
    int mb = blockIdx.x * 32;

    for (int i = tid; i < 4096; i += 256) {
        int r = i >> 7, j = i & 127;
        buf0[i] = g_h0[(size_t)((mb + r) >> 2) * 128 + j];
    }
    for (int i = tid; i < 1280; i += 256) s_outw[i] = out_w[i];
    if (tid < 10) s_outb[tid] = out_b[tid];

    float* cur = buf0;
    float* nxt = buf1;

    int cp = tid & 63, rowg = tid >> 6;
    int r0 = rowg * 8, j0 = cp * 2;

    for (int step = 0; step < 3; step++) {
        if (tid < 32) {
            int op = g_op[step * (NB * 4) + mb + tid];
            float p = g_pv[step * (NB * 4) + mb + tid];
            s_opA[tid] = (p > 0.f) ? op : 0;
            s_pvA[tid] = p;
        }
        __syncthreads();

        for (int i = tid; i < 4096; i += 256) {
            int r = i >> 7;
            if (s_opA[r] == 3) nxt[i] = fmaxf(cur[i] * s_pvA[r], 0.f);
        }

        for (int e = 0; e < 3; e++) {
            __syncthreads();
            for (int i = tid; i < 16384; i += 256) s_w[i] = exp_w[e * 16384 + i];
            if (tid < 128) s_b[tid] = exp_b[e * 128 + tid];
            __syncthreads();

            u64t acc[8];
#pragma unroll
            for (int k = 0; k < 8; k++) acc[k] = 0ull;
#pragma unroll 2
            for (int d = 0; d < 128; d++) {
                u64t w2 = *(const u64t*)(s_w + d * 128 + j0);
#pragma unroll
                for (int k = 0; k < 8; k++)
                    ffma2(acc[k], w2, splat2(cur[(r0 + k) * 128 + d]));
            }
            u64t b2 = *(const u64t*)(s_b + j0);
#pragma unroll
            for (int k = 0; k < 8; k++) {
                int r = r0 + k;
                if (s_opA[r] == e) {
                    float v = s_pvA[r];
                    float2 st;
                    st.x = fmaxf((lo32(acc[k]) + lo32(b2)) * v, 0.f);
                    st.y = fmaxf((hi32(acc[k]) + hi32(b2)) * v, 0.f);
                    *(float2*)(nxt + r * 128 + j0) = st;
                }
            }
        }
        __syncthreads();
        float* t = cur; cur = nxt; nxt = t;
    }

    for (int i = tid; i < 320; i += 256) {
        int r = i / 10, o = i % 10;
        float a = s_outb[o];
        const float* hp = cur + r * 128;
#pragma unroll 8
        for (int d = 0; d < 128; d++) a += hp[d] * s_outw[d * 10 + o];
        out[(size_t)(mb + r) * 10 + o] = a;
    }
}

// ---------------------------------------------------------------------------
extern "C" void kernel_launch(void* const* d_in, const int* in_sizes, int n_in,
                              void* d_out, int out_size)
{
    const float* x    = (const float*)d_in[0];
    const float* cw1  = (const float*)d_in[1];
    const float* cb1  = (const float*)d_in[2];
    const float* g1   = (const float*)d_in[3];
    const float* be1  = (const float*)d_in[4];
    const float* cw2  = (const float*)d_in[5];
    const float* cb2  = (const float*)d_in[6];
    const float* g2   = (const float*)d_in[7];
    const float* be2  = (const float*)d_in[8];
    const float* cw3  = (const float*)d_in[9];
    const float* cb3  = (const float*)d_in[10];
    const float* g3   = (const float*)d_in[11];
    const float* be3  = (const float*)d_in[12];
    const float* W_hh = (const float*)d_in[13];
    const float* b_h  = (const float*)d_in[14];
    const float* E_op = (const float*)d_in[15];
    const float* W_ho = (const float*)d_in[16];
    const float* b_ho = (const float*)d_in[17];
    const float* expw = (const float*)d_in[18];
    const float* expb = (const float*)d_in[19];
    const float* outw = (const float*)d_in[20];
    const float* outb = (const float*)d_in[21];
    float* out = (float*)d_out;

    cudaFuncSetAttribute(conv2_kernel, cudaFuncAttributeMaxDynamicSharedMemorySize,
                         (15360 + 9216) * 4);
    cudaFuncSetAttribute(dispatch_all_kernel, cudaFuncAttributeMaxDynamicSharedMemorySize,
                         24576 * 4);

    conv1_kernel<<<NB, 480>>>(x, cw1, cb1);
    reduce_stats_kernel<<<32, 256>>>(0, 1.f / (NB * 900.f), g1, be1);
    pool1_kernel<<<NB, 256>>>();

    conv2_kernel<<<NB / 2, 448, (15360 + 9216) * 4>>>(cw2, cb2);
    reduce_stats_kernel<<<32, 256>>>(1, 1.f / (NB * 169.f), g2, be2);
    pool2_kernel<<<NB, 256>>>();

    conv3_kernel<<<NB, 256>>>(cw3, cb3);
    reduce_stats_kernel<<<32, 256>>>(2, 1.f / (NB * 16.f), g3, be3);
    pool3_kernel<<<NB, 128>>>();

    beam_kernel<<<NB, 128>>>(W_hh, b_h, E_op, W_ho, b_ho);

    dispatch_all_kernel<<<NB * 4 / 32, 256, 24576 * 4>>>(expw, expb, outw, outb, out);
}

// round 7
// speedup vs baseline: 1.7011x; 1.1598x over previous
#include <cuda_runtime.h>
#include <math.h>
#include <float.h>
#include <stdint.h>

// ---------------------------------------------------------------------------
// Supernetwork: backbone (3x conv+BN+relu+pool) -> beam search -> MoE dispatch
// B=2048, BEAMS=4, DEPTH=3, HID=128, NOPS=4
//
// Round-7:
//  * conv1: 960 threads (half-row per thread) -> occ 15->30 warps/SM.
//  * conv3: row-per-thread, 4 images/block, padded [c][6][8] smem rows
//    (6 LDS / 12 FFMA2 instead of 6 LDS / 3 FFMA2).
//  * pool1/pool2: float4 channel vectorization.
//  * conv2 / beam / dispatch unchanged from R6.
//  * Determinism: no float atomics; fixed-order reductions only.
// ---------------------------------------------------------------------------

#define NB 2048

// ------------------------------ scratch ------------------------------------
__device__ float g_buf1[(size_t)NB * 30 * 30 * 32];  // conv1 out, NHWC
__device__ float g_buf2[(size_t)NB * 15 * 15 * 32];  // pool1 out, NHWC
__device__ float g_buf3[(size_t)NB * 13 * 13 * 32];  // conv2 out, NHWC
__device__ float g_buf4[(size_t)NB * 6 * 6 * 32];    // pool2 out, NHWC
__device__ float g_buf5[(size_t)NB * 16 * 32];       // conv3 out, NHWC (4x4)
__device__ float g_h0[(size_t)NB * 128];             // backbone feature
__device__ float g_psum[32 * NB];
__device__ float g_psq[32 * NB];
__device__ float g_scale[3][32];
__device__ float g_shift[3][32];
__device__ int   g_op[3 * NB * 4];
__device__ float g_pv[3 * NB * 4];

// --------------------------- f32x2 helpers ---------------------------------
typedef unsigned long long u64t;

__device__ __forceinline__ void ffma2(u64t& c, u64t a, u64t b) {
    asm("fma.rn.f32x2 %0, %1, %2, %0;" : "+l"(c) : "l"(a), "l"(b));
}
__device__ __forceinline__ u64t splat2(float v) {
    u64t r;
    asm("mov.b64 %0, {%1, %1};" : "=l"(r) : "r"(__float_as_uint(v)));
    return r;
}
__device__ __forceinline__ float lo32(u64t v) { return __uint_as_float((unsigned)v); }
__device__ __forceinline__ float hi32(u64t v) { return __uint_as_float((unsigned)(v >> 32)); }

// ------------------- conv1: 3->32, 32x32 -> 30x30, fused stats -------------
// 960 threads = 2 half-rows x 30 rows x 16 oc-pairs. Warp-uniform halves:
// threads [0,480) do ox 0..14, [480,960) do ox 15..29.
__global__ __launch_bounds__(960, 1) void conv1_kernel(
    const float* __restrict__ x, const float* __restrict__ w,
    const float* __restrict__ bias)
{
    __shared__ float s_img[3 * 1024];
    __shared__ float s_w[27 * 32];
    __shared__ float s_b[32];
    __shared__ float s_ss[32][60];
    __shared__ float s_sq[32][60];
    int tid = threadIdx.x;
    int img = blockIdx.x;
    const float* xb = x + (size_t)img * 3072;
    for (int i = tid; i < 768; i += 960)
        ((float4*)s_img)[i] = ((const float4*)xb)[i];
    if (tid < 864) {
        int oc = tid / 27, k = tid % 27;
        s_w[k * 32 + oc] = w[tid];
    }
    if (tid < 32) s_b[tid] = bias[tid];
    __syncthreads();

    int half = tid / 480;     // warp-uniform
    int rem  = tid % 480;
    int ocp = rem & 15;
    int row = rem >> 4;       // 0..29
    int ox0 = half * 15;

    u64t acc[15];
    u64t bv = *(const u64t*)(s_b + ocp * 2);
#pragma unroll
    for (int i = 0; i < 15; i++) acc[i] = bv;

#pragma unroll
    for (int ic = 0; ic < 3; ic++) {
#pragma unroll
        for (int ky = 0; ky < 3; ky++) {
            const float* irow = s_img + ic * 1024 + (row + ky) * 32;
            float in[17];   // cols ox0 .. ox0+16
            if (half == 0) {
#pragma unroll
                for (int i = 0; i < 4; i++) {
                    float4 v4 = ((const float4*)irow)[i];
                    in[4 * i] = v4.x; in[4 * i + 1] = v4.y;
                    in[4 * i + 2] = v4.z; in[4 * i + 3] = v4.w;
                }
                in[16] = irow[16];
            } else {
                in[0] = irow[15];
#pragma unroll
                for (int i = 0; i < 4; i++) {
                    float4 v4 = ((const float4*)(irow + 16))[i];
                    in[4 * i + 1] = v4.x; in[4 * i + 2] = v4.y;
                    in[4 * i + 3] = v4.z; in[4 * i + 4] = v4.w;
                }
            }
#pragma unroll
            for (int kx = 0; kx < 3; kx++) {
                u64t wv = *(const u64t*)(s_w + ((ic * 3 + ky) * 3 + kx) * 32 + ocp * 2);
#pragma unroll
                for (int i = 0; i < 15; i++)
                    ffma2(acc[i], wv, splat2(in[i + kx]));
            }
        }
    }
    u64t* ob = (u64t*)(g_buf1 + (((size_t)img * 30 + row) * 30 + ox0) * 32 + 2 * ocp);
    float slo = 0.f, qlo = 0.f, shi = 0.f, qhi = 0.f;
#pragma unroll
    for (int i = 0; i < 15; i++) {
        u64t v = acc[i];
        ob[i * 16] = v;
        float a = lo32(v), b2 = hi32(v);
        slo += a; qlo += a * a; shi += b2; qhi += b2 * b2;
    }
    int rh = row + 30 * half;   // 0..59
    s_ss[2 * ocp][rh] = slo; s_sq[2 * ocp][rh] = qlo;
    s_ss[2 * ocp + 1][rh] = shi; s_sq[2 * ocp + 1][rh] = qhi;
    __syncthreads();
    if (tid < 32) {
        float s = 0.f, q = 0.f;
#pragma unroll
        for (int r = 0; r < 60; r++) { s += s_ss[tid][r]; q += s_sq[tid][r]; }
        g_psum[tid * NB + img] = s;
        g_psq[tid * NB + img] = q;
    }
}

// Per-channel reduction over 2048 images (fixed pairwise order) -> scale/shift.
__global__ __launch_bounds__(256) void reduce_stats_kernel(
    int stage, float invN,
    const float* __restrict__ gamma, const float* __restrict__ beta)
{
    __shared__ float ss[256], sq[256];
    int c = blockIdx.x;
    int t = threadIdx.x;
    float s = 0.f, q = 0.f;
#pragma unroll
    for (int k = 0; k < NB / 256; k++) {
        int img = t + k * 256;
        s += g_psum[c * NB + img];
        q += g_psq[c * NB + img];
    }
    ss[t] = s; sq[t] = q;
    __syncthreads();
#pragma unroll
    for (int off = 128; off; off >>= 1) {
        if (t < off) { ss[t] += ss[t + off]; sq[t] += sq[t + off]; }
        __syncthreads();
    }
    if (t == 0) {
        float mu = ss[0] * invN;
        float var = sq[0] * invN - mu * mu;
        float sc = gamma[c] * rsqrtf(var + 1e-5f);
        g_scale[stage][c] = sc;
        g_shift[stage][c] = beta[c] - mu * sc;
    }
}

// ---------------------- bn + relu + avgpool2 (NHWC, float4) ----------------
__device__ __forceinline__ float4 bnrelu4(float4 v, float4 sc, float4 sh) {
    float4 r;
    r.x = fmaxf(v.x * sc.x + sh.x, 0.f);
    r.y = fmaxf(v.y * sc.y + sh.y, 0.f);
    r.z = fmaxf(v.z * sc.z + sh.z, 0.f);
    r.w = fmaxf(v.w * sc.w + sh.w, 0.f);
    return r;
}

__global__ __launch_bounds__(256) void pool1_kernel() {
    int img = blockIdx.x;
    for (int i = threadIdx.x; i < 1800; i += 256) {
        int c4 = i & 7, p = i >> 3;           // p = oy*15+ox
        int oy = p / 15, ox = p % 15;
        const float4* b = (const float4*)(g_buf1
            + (((size_t)img * 30 + 2 * oy) * 30 + 2 * ox) * 32) + c4;
        float4 sc = ((const float4*)g_scale[0])[c4];
        float4 sh = ((const float4*)g_shift[0])[c4];
        float4 a0 = bnrelu4(b[0], sc, sh);
        float4 a1 = bnrelu4(b[8], sc, sh);
        float4 a2 = bnrelu4(b[240], sc, sh);
        float4 a3 = bnrelu4(b[248], sc, sh);
        float4 r;
        r.x = (a0.x + a1.x + a2.x + a3.x) * 0.25f;
        r.y = (a0.y + a1.y + a2.y + a3.y) * 0.25f;
        r.z = (a0.z + a1.z + a2.z + a3.z) * 0.25f;
        r.w = (a0.w + a1.w + a2.w + a3.w) * 0.25f;
        ((float4*)(g_buf2 + ((size_t)img * 225 + p) * 32))[c4] = r;
    }
}

__global__ __launch_bounds__(288) void pool2_kernel() {
    int img = blockIdx.x;
    int i = threadIdx.x;   // 0..287
    int c4 = i & 7, p = i >> 3;               // p = oy*6+ox
    int oy = p / 6, ox = p % 6;
    const float4* b = (const float4*)(g_buf3
        + (((size_t)img * 13 + 2 * oy) * 13 + 2 * ox) * 32) + c4;
    float4 sc = ((const float4*)g_scale[1])[c4];
    float4 sh = ((const float4*)g_shift[1])[c4];
    float4 a0 = bnrelu4(b[0], sc, sh);
    float4 a1 = bnrelu4(b[8], sc, sh);
    float4 a2 = bnrelu4(b[104], sc, sh);
    float4 a3 = bnrelu4(b[112], sc, sh);
    float4 r;
    r.x = (a0.x + a1.x + a2.x + a3.x) * 0.25f;
    r.y = (a0.y + a1.y + a2.y + a3.y) * 0.25f;
    r.z = (a0.z + a1.z + a2.z + a3.z) * 0.25f;
    r.w = (a0.w + a1.w + a2.w + a3.w) * 0.25f;
    ((float4*)(g_buf4 + ((size_t)img * 36 + p) * 32))[c4] = r;
}

__global__ __launch_bounds__(128) void pool3_kernel() {
    int img = blockIdx.x;
    int i = threadIdx.x;
    int c = i & 31, p = i >> 5;
    int oy = p >> 1, ox = p & 1;
    const float* b = g_buf5 + ((size_t)img * 16 + (2 * oy) * 4 + 2 * ox) * 32 + c;
    float sc = g_scale[2][c], sh = g_shift[2][c];
    float v = fmaxf(b[0] * sc + sh, 0.f) + fmaxf(b[32] * sc + sh, 0.f)
            + fmaxf(b[128] * sc + sh, 0.f) + fmaxf(b[160] * sc + sh, 0.f);
    g_h0[(size_t)img * 128 + c * 4 + p] = v * 0.25f;
}

// ------------- conv2: 32->32, 15x15 -> 13x13, 2 images/block ---------------
__global__ __launch_bounds__(448, 2) void conv2_kernel(
    const float* __restrict__ w, const float* __restrict__ bias)
{
    extern __shared__ float sm[];
    float* s_img = sm;            // 2 * 32*15*16 = 15360
    float* s_w = sm + 15360;      // 9216, layout [ic*9+k][oc]
    __shared__ float s_b[32];
    __shared__ float s_ss[2][32][13];
    __shared__ float s_sq[2][32][13];
    int tid = threadIdx.x;
    int img0 = blockIdx.x * 2;

    const float* ib = g_buf2 + (size_t)img0 * 7200;
    for (int i = tid; i < 14400; i += 448) {
        int sub = i / 7200, j = i % 7200;
        int c = j & 31, p = j >> 5;
        s_img[sub * 7680 + c * 240 + (p / 15) * 16 + (p % 15)] = ib[i];
    }
    for (int i = tid; i < 9216; i += 448) {
        int oc = i / 288, r = i % 288;
        s_w[r * 32 + oc] = w[i];
    }
    if (tid < 32) s_b[tid] = bias[tid];
    __syncthreads();

    int sub = tid / 224;
    int local = tid % 224;
    if (local < 208) {
        int ocp = local & 15;
        int row = local >> 4;   // 0..12
        const float* imgbase = s_img + sub * 7680;
        u64t acc[13];
        u64t bv = *(const u64t*)(s_b + ocp * 2);
#pragma unroll
        for (int i = 0; i < 13; i++) acc[i] = bv;

        for (int ic = 0; ic < 32; ic++) {
#pragma unroll
            for (int ky = 0; ky < 3; ky++) {
                const float4* irow4 = (const float4*)(imgbase + ic * 240 + (row + ky) * 16);
                float in[16];
#pragma unroll
                for (int i = 0; i < 4; i++) {
                    float4 v4 = irow4[i];
                    in[4 * i] = v4.x; in[4 * i + 1] = v4.y;
                    in[4 * i + 2] = v4.z; in[4 * i + 3] = v4.w;
                }
#pragma unroll
                for (int kx = 0; kx < 3; kx++) {
                    u64t wv = *(const u64t*)(s_w + (ic * 9 + ky * 3 + kx) * 32 + ocp * 2);
#pragma unroll
                    for (int ox = 0; ox < 13; ox++)
                        ffma2(acc[ox], wv, splat2(in[ox + kx]));
                }
            }
        }
        u64t* ob = (u64t*)(g_buf3 + (((size_t)(img0 + sub) * 13 + row) * 13) * 32 + 2 * ocp);
        float slo = 0.f, qlo = 0.f, shi = 0.f, qhi = 0.f;
#pragma unroll
        for (int ox = 0; ox < 13; ox++) {
            u64t v = acc[ox];
            ob[ox * 16] = v;
            float a = lo32(v), b2 = hi32(v);
            slo += a; qlo += a * a; shi += b2; qhi += b2 * b2;
        }
        s_ss[sub][2 * ocp][row] = slo; s_sq[sub][2 * ocp][row] = qlo;
        s_ss[sub][2 * ocp + 1][row] = shi; s_sq[sub][2 * ocp + 1][row] = qhi;
    }
    __syncthreads();
    if (tid < 64) {
        int ssub = tid >> 5, c = tid & 31;
        float s = 0.f, q = 0.f;
#pragma unroll
        for (int r = 0; r < 13; r++) { s += s_ss[ssub][c][r]; q += s_sq[ssub][c][r]; }
        g_psum[c * NB + img0 + ssub] = s;
        g_psq[c * NB + img0 + ssub] = q;
    }
}

// ------------- conv3: 32->32, 6x6 -> 4x4, 4 images/block, row/thread -------
// 256 threads = 4 img x 4 oy x 16 ocp. smem img rows padded to 8 floats.
__global__ __launch_bounds__(256) void conv3_kernel(
    const float* __restrict__ w, const float* __restrict__ bias)
{
    extern __shared__ float sm[];
    float* s_img = sm;            // 4 * 32*6*8 = 6144
    float* s_w = sm + 6144;       // 9216
    __shared__ float s_b[32];
    __shared__ float s_ss[4][32][4];
    __shared__ float s_sq[4][32][4];
    int tid = threadIdx.x;
    int img0 = blockIdx.x * 4;

    const float* ib = g_buf4 + (size_t)img0 * 1152;
    for (int i = tid; i < 4608; i += 256) {
        int il = i / 1152, j = i % 1152;
        int c = j & 31, p = j >> 5;          // p = r*6+col
        s_img[il * 1536 + c * 48 + (p / 6) * 8 + (p % 6)] = ib[i];
    }
    for (int i = tid; i < 9216; i += 256) {
        int oc = i / 288, r = i % 288;
        s_w[r * 32 + oc] = w[i];
    }
    if (tid < 32) s_b[tid] = bias[tid];
    __syncthreads();

    int ocp = tid & 15;
    int oy = (tid >> 4) & 3;
    int il = tid >> 6;                        // 0..3
    const float* imgbase = s_img + il * 1536;
    u64t acc[4];
    u64t bv = *(const u64t*)(s_b + ocp * 2);
#pragma unroll
    for (int i = 0; i < 4; i++) acc[i] = bv;

    for (int ic = 0; ic < 32; ic++) {
#pragma unroll
        for (int ky = 0; ky < 3; ky++) {
            const float* irow = imgbase + ic * 48 + (oy + ky) * 8;
            float in[6];
            float4 v4 = *(const float4*)irow;
            in[0] = v4.x; in[1] = v4.y; in[2] = v4.z; in[3] = v4.w;
            in[4] = irow[4]; in[5] = irow[5];
#pragma unroll
            for (int kx = 0; kx < 3; kx++) {
                u64t wv = *(const u64t*)(s_w + (ic * 9 + ky * 3 + kx) * 32 + ocp * 2);
#pragma unroll
                for (int ox = 0; ox < 4; ox++)
                    ffma2(acc[ox], wv, splat2(in[ox + kx]));
            }
        }
    }
    u64t* ob = (u64t*)(g_buf5 + ((size_t)(img0 + il) * 16 + oy * 4) * 32 + 2 * ocp);
    float slo = 0.f, qlo = 0.f, shi = 0.f, qhi = 0.f;
#pragma unroll
    for (int ox = 0; ox < 4; ox++) {
        u64t v = acc[ox];
        ob[ox * 16] = v;
        float a = lo32(v), b2 = hi32(v);
        slo += a; qlo += a * a; shi += b2; qhi += b2 * b2;
    }
    s_ss[il][2 * ocp][oy] = slo; s_sq[il][2 * ocp][oy] = qlo;
    s_ss[il][2 * ocp + 1][oy] = shi; s_sq[il][2 * ocp + 1][oy] = qhi;
    __syncthreads();
    if (tid < 128) {
        int iimg = tid >> 5, c = tid & 31;
        float s = 0.f, q = 0.f;
#pragma unroll
        for (int r = 0; r < 4; r++) { s += s_ss[iimg][c][r]; q += s_sq[iimg][c][r]; }
        g_psum[c * NB + img0 + iimg] = s;
        g_psq[c * NB + img0 + iimg] = q;
    }
}

// --------------------------- beam search -----------------------------------
__device__ __forceinline__ float warp_sum(float v) {
#pragma unroll
    for (int off = 16; off; off >>= 1) v += __shfl_down_sync(0xffffffffu, v, off);
    return v;
}

__global__ __launch_bounds__(128) void beam_kernel(
    const float* __restrict__ W_hh, const float* __restrict__ b_h,
    const float* __restrict__ E_op, const float* __restrict__ W_ho,
    const float* __restrict__ b_ho)
{
    __shared__ float s_h0[128];
    __shared__ float s_h[4][128];
    __shared__ float s_hn[4][128];
    __shared__ float s_Who[512];
    __shared__ float s_logits[4][4];
    __shared__ float s_scores[4];
    __shared__ int   s_op[4];
    __shared__ int   s_src[4];

    int n = blockIdx.x;
    int tid = threadIdx.x;
    int warp = tid >> 5, lane = tid & 31;

    s_h0[tid] = g_h0[(size_t)n * 128 + tid];
#pragma unroll
    for (int i = 0; i < 4; i++) s_Who[i * 128 + tid] = W_ho[i * 128 + tid];
    __syncthreads();

    {
        float a = 0.f;
        for (int d = lane; d < 128; d += 32) a += s_h0[d] * s_Who[d * 4 + warp];
        a = warp_sum(a);
        if (lane == 0) s_logits[0][warp] = a + b_ho[warp];
    }
    __syncthreads();

    if (tid == 0) {
        float l[4], e[4];
        float m = -FLT_MAX;
#pragma unroll
        for (int o = 0; o < 4; o++) { l[o] = s_logits[0][o]; m = fmaxf(m, l[o]); }
        float sum = 0.f;
#pragma unroll
        for (int o = 0; o < 4; o++) { e[o] = expf(l[o] - m); sum += e[o]; }
        float logsum = logf(sum);
        float inv = 1.f / sum;
        bool used[4] = {false, false, false, false};
        for (int b = 0; b < 4; b++) {
            int best = -1; float bv = -FLT_MAX;
            for (int o = 0; o < 4; o++) {
                float lp = l[o] - m - logsum;
                if (!used[o] && lp > bv) { bv = lp; best = o; }
            }
            used[best] = true;
            s_scores[b] = bv;
            s_op[b] = best;
            g_op[0 * (NB * 4) + n * 4 + b] = best;
            g_pv[0 * (NB * 4) + n * 4 + b] = e[best] * inv;
        }
    }
    __syncthreads();

    {
        float common = 0.f;
#pragma unroll 8
        for (int k = 0; k < 128; k++) common += s_h0[k] * W_hh[k * 128 + tid];
        float bh = b_h[tid];
#pragma unroll
        for (int b = 0; b < 4; b++)
            s_h[b][tid] = tanhf(common + E_op[s_op[b] * 128 + tid] + bh);
    }
    __syncthreads();

    for (int step = 1; step < 3; step++) {
        {
            float a0 = 0.f, a1 = 0.f, a2 = 0.f, a3 = 0.f;
            for (int d = lane; d < 128; d += 32) {
                float v = s_h[warp][d];
                a0 += v * s_Who[d * 4 + 0];
                a1 += v * s_Who[d * 4 + 1];
                a2 += v * s_Who[d * 4 + 2];
                a3 += v * s_Who[d * 4 + 3];
            }
            a0 = warp_sum(a0); a1 = warp_sum(a1); a2 = warp_sum(a2); a3 = warp_sum(a3);
            if (lane == 0) {
                s_logits[warp][0] = a0 + b_ho[0];
                s_logits[warp][1] = a1 + b_ho[1];
                s_logits[warp][2] = a2 + b_ho[2];
                s_logits[warp][3] = a3 + b_ho[3];
            }
        }
        __syncthreads();

        if (tid == 0) {
            float cand[16], probs[16];
            for (int b = 0; b < 4; b++) {
                float l[4], e[4];
                float m = -FLT_MAX;
#pragma unroll
                for (int o = 0; o < 4; o++) { l[o] = s_logits[b][o]; m = fmaxf(m, l[o]); }
                float sum = 0.f;
#pragma unroll
                for (int o = 0; o < 4; o++) { e[o] = expf(l[o] - m); sum += e[o]; }
                float logsum = logf(sum);
                float inv = 1.f / sum;
#pragma unroll
                for (int o = 0; o < 4; o++) {
                    cand[b * 4 + o] = s_scores[b] + (l[o] - m - logsum);
                    probs[b * 4 + o] = e[o] * inv;
                }
            }
            bool used[16];
            for (int i = 0; i < 16; i++) used[i] = false;
            float ns[4];
            for (int b = 0; b < 4; b++) {
                int best = -1; float bv = -FLT_MAX;
                for (int f = 0; f < 16; f++)
                    if (!used[f] && cand[f] > bv) { bv = cand[f]; best = f; }
                used[best] = true;
                ns[b] = bv;
                int src = best >> 2, op = best & 3;
                s_src[b] = src; s_op[b] = op;
                g_op[step * (NB * 4) + n * 4 + b] = op;
                g_pv[step * (NB * 4) + n * 4 + b] = probs[best];
            }
#pragma unroll
            for (int b = 0; b < 4; b++) s_scores[b] = ns[b];
        }
        __syncthreads();

        if (step < 2) {
            int r0 = s_src[0], r1 = s_src[1], r2 = s_src[2], r3 = s_src[3];
            float a0 = 0.f, a1 = 0.f, a2 = 0.f, a3 = 0.f;
#pragma unroll 4
            for (int k = 0; k < 128; k++) {
                float wv = W_hh[k * 128 + tid];
                a0 += s_h[r0][k] * wv;
                a1 += s_h[r1][k] * wv;
                a2 += s_h[r2][k] * wv;
                a3 += s_h[r3][k] * wv;
            }
            float bh = b_h[tid];
            s_hn[0][tid] = tanhf(a0 + E_op[s_op[0] * 128 + tid] + bh);
            s_hn[1][tid] = tanhf(a1 + E_op[s_op[1] * 128 + tid] + bh);
            s_hn[2][tid] = tanhf(a2 + E_op[s_op[2] * 128 + tid] + bh);
            s_hn[3][tid] = tanhf(a3 + E_op[s_op[3] * 128 + tid] + bh);
            __syncthreads();
#pragma unroll
            for (int b = 0; b < 4; b++) s_h[b][tid] = s_hn[b][tid];
            __syncthreads();
        }
    }
}

// ------------- fused dispatch chain + output projection --------------------
__global__ __launch_bounds__(256) void dispatch_all_kernel(
    const float* __restrict__ exp_w, const float* __restrict__ exp_b,
    const float* __restrict__ out_w, const float* __restrict__ out_b,
    float* __restrict__ out)
{
    extern __shared__ float sm[];
    float* s_w = sm;              // 16384 floats
    float* buf0 = sm + 16384;     // 32x128
    float* buf1 = sm + 20480;     // 32x128
    __shared__ float s_b[128];
    __shared__ float s_outw[1280];
    __shared__ float s_outb[10];
    __shared__ int   s_opA[32];
    __shared__ float s_pvA[32];

    int tid = threadIdx.x;
    int mb = blockIdx.x * 32;

    for (int i = tid; i < 4096; i += 256) {
        int r = i >> 7, j = i & 127;
        buf0[i] = g_h0[(size_t)((mb + r) >> 2) * 128 + j];
    }
    for (int i = tid; i < 1280; i += 256) s_outw[i] = out_w[i];
    if (tid < 10) s_outb[tid] = out_b[tid];

    float* cur = buf0;
    float* nxt = buf1;

    int cp = tid & 63, rowg = tid >> 6;
    int r0 = rowg * 8, j0 = cp * 2;

    for (int step = 0; step < 3; step++) {
        if (tid < 32) {
            int op = g_op[step * (NB * 4) + mb + tid];
            float p = g_pv[step * (NB * 4) + mb + tid];
            s_opA[tid] = (p > 0.f) ? op : 0;
            s_pvA[tid] = p;
        }
        __syncthreads();

        for (int i = tid; i < 4096; i += 256) {
            int r = i >> 7;
            if (s_opA[r] == 3) nxt[i] = fmaxf(cur[i] * s_pvA[r], 0.f);
        }

        for (int e = 0; e < 3; e++) {
            __syncthreads();
            for (int i = tid; i < 16384; i += 256) s_w[i] = exp_w[e * 16384 + i];
            if (tid < 128) s_b[tid] = exp_b[e * 128 + tid];
            __syncthreads();

            u64t acc[8];
#pragma unroll
            for (int k = 0; k < 8; k++) acc[k] = 0ull;
#pragma unroll 2
            for (int d = 0; d < 128; d++) {
                u64t w2 = *(const u64t*)(s_w + d * 128 + j0);
#pragma unroll
                for (int k = 0; k < 8; k++)
                    ffma2(acc[k], w2, splat2(cur[(r0 + k) * 128 + d]));
            }
            u64t b2 = *(const u64t*)(s_b + j0);
#pragma unroll
            for (int k = 0; k < 8; k++) {
                int r = r0 + k;
                if (s_opA[r] == e) {
                    float v = s_pvA[r];
                    float2 st;
                    st.x = fmaxf((lo32(acc[k]) + lo32(b2)) * v, 0.f);
                    st.y = fmaxf((hi32(acc[k]) + hi32(b2)) * v, 0.f);
                    *(float2*)(nxt + r * 128 + j0) = st;
                }
            }
        }
        __syncthreads();
        float* t = cur; cur = nxt; nxt = t;
    }

    for (int i = tid; i < 320; i += 256) {
        int r = i / 10, o = i % 10;
        float a = s_outb[o];
        const float* hp = cur + r * 128;
#pragma unroll 8
        for (int d = 0; d < 128; d++) a += hp[d] * s_outw[d * 10 + o];
        out[(size_t)(mb + r) * 10 + o] = a;
    }
}

// ---------------------------------------------------------------------------
extern "C" void kernel_launch(void* const* d_in, const int* in_sizes, int n_in,
                              void* d_out, int out_size)
{
    const float* x    = (const float*)d_in[0];
    const float* cw1  = (const float*)d_in[1];
    const float* cb1  = (const float*)d_in[2];
    const float* g1   = (const float*)d_in[3];
    const float* be1  = (const float*)d_in[4];
    const float* cw2  = (const float*)d_in[5];
    const float* cb2  = (const float*)d_in[6];
    const float* g2   = (const float*)d_in[7];
    const float* be2  = (const float*)d_in[8];
    const float* cw3  = (const float*)d_in[9];
    const float* cb3  = (const float*)d_in[10];
    const float* g3   = (const float*)d_in[11];
    const float* be3  = (const float*)d_in[12];
    const float* W_hh = (const float*)d_in[13];
    const float* b_h  = (const float*)d_in[14];
    const float* E_op = (const float*)d_in[15];
    const float* W_ho = (const float*)d_in[16];
    const float* b_ho = (const float*)d_in[17];
    const float* expw = (const float*)d_in[18];
    const float* expb = (const float*)d_in[19];
    const float* outw = (const float*)d_in[20];
    const float* outb = (const float*)d_in[21];
    float* out = (float*)d_out;

    cudaFuncSetAttribute(conv2_kernel, cudaFuncAttributeMaxDynamicSharedMemorySize,
                         (15360 + 9216) * 4);
    cudaFuncSetAttribute(conv3_kernel, cudaFuncAttributeMaxDynamicSharedMemorySize,
                         (6144 + 9216) * 4);
    cudaFuncSetAttribute(dispatch_all_kernel, cudaFuncAttributeMaxDynamicSharedMemorySize,
                         24576 * 4);

    conv1_kernel<<<NB, 960>>>(x, cw1, cb1);
    reduce_stats_kernel<<<32, 256>>>(0, 1.f / (NB * 900.f), g1, be1);
    pool1_kernel<<<NB, 256>>>();

    conv2_kernel<<<NB / 2, 448, (15360 + 9216) * 4>>>(cw2, cb2);
    reduce_stats_kernel<<<32, 256>>>(1, 1.f / (NB * 169.f), g2, be2);
    pool2_kernel<<<NB, 288>>>();

    conv3_kernel<<<NB / 4, 256, (6144 + 9216) * 4>>>(cw3, cb3);
    reduce_stats_kernel<<<32, 256>>>(2, 1.f / (NB * 16.f), g3, be3);
    pool3_kernel<<<NB, 128>>>();

    beam_kernel<<<NB, 128>>>(W_hh, b_h, E_op, W_ho, b_ho);

    dispatch_all_kernel<<<NB * 4 / 32, 256, 24576 * 4>>>(expw, expb, outw, outb, out);
}

// round 8
// speedup vs baseline: 1.8099x; 1.0639x over previous
#include <cuda_runtime.h>
#include <math.h>
#include <float.h>
#include <stdint.h>

// ---------------------------------------------------------------------------
// Supernetwork: backbone (3x conv+BN+relu+pool) -> beam search -> MoE dispatch
// B=2048, BEAMS=4, DEPTH=3, HID=128, NOPS=4
//
// Round-8:
//  * Sorted MoE dispatch: rows bucketed by (step, expert) after beam; each
//    GEMM block computes ONE expert for rows that chose it (3x fewer FLOPs
//    than dense-all-experts). Bucket order nondeterministic but per-row
//    output is order-independent -> bit-deterministic results.
//  * pool3 fused into beam kernel.
//  * conv1/conv2/conv3/pools/stats unchanged from R7.
// ---------------------------------------------------------------------------

#define NB 2048

// ------------------------------ scratch ------------------------------------
__device__ float g_buf1[(size_t)NB * 30 * 30 * 32];  // conv1 out, NHWC
__device__ float g_buf2[(size_t)NB * 15 * 15 * 32];  // pool1 out, NHWC
__device__ float g_buf3[(size_t)NB * 13 * 13 * 32];  // conv2 out, NHWC
__device__ float g_buf4[(size_t)NB * 6 * 6 * 32];    // pool2 out, NHWC
__device__ float g_buf5[(size_t)NB * 16 * 32];       // conv3 out, NHWC (4x4)
__device__ float g_h0[(size_t)NB * 128];             // backbone feature
__device__ float g_hid[(size_t)NB * 4 * 128];        // dispatch state
__device__ float g_psum[32 * NB];
__device__ float g_psq[32 * NB];
__device__ float g_scale[3][32];
__device__ float g_shift[3][32];
__device__ int   g_op[3 * NB * 4];
__device__ float g_pv[3 * NB * 4];
__device__ int   g_cnt[3][4];                        // rows per (step, expert)
__device__ int   g_ridx[3 * 4 * NB * 4];             // bucketed row indices

// --------------------------- f32x2 helpers ---------------------------------
typedef unsigned long long u64t;

__device__ __forceinline__ void ffma2(u64t& c, u64t a, u64t b) {
    asm("fma.rn.f32x2 %0, %1, %2, %0;" : "+l"(c) : "l"(a), "l"(b));
}
__device__ __forceinline__ u64t splat2(float v) {
    u64t r;
    asm("mov.b64 %0, {%1, %1};" : "=l"(r) : "r"(__float_as_uint(v)));
    return r;
}
__device__ __forceinline__ float lo32(u64t v) { return __uint_as_float((unsigned)v); }
__device__ __forceinline__ float hi32(u64t v) { return __uint_as_float((unsigned)(v >> 32)); }

// ------------------- conv1: 3->32, 32x32 -> 30x30, fused stats -------------
__global__ __launch_bounds__(960, 1) void conv1_kernel(
    const float* __restrict__ x, const float* __restrict__ w,
    const float* __restrict__ bias)
{
    __shared__ float s_img[3 * 1024];
    __shared__ float s_w[27 * 32];
    __shared__ float s_b[32];
    __shared__ float s_ss[32][60];
    __shared__ float s_sq[32][60];
    int tid = threadIdx.x;
    int img = blockIdx.x;
    const float* xb = x + (size_t)img * 3072;
    for (int i = tid; i < 768; i += 960)
        ((float4*)s_img)[i] = ((const float4*)xb)[i];
    if (tid < 864) {
        int oc = tid / 27, k = tid % 27;
        s_w[k * 32 + oc] = w[tid];
    }
    if (tid < 32) s_b[tid] = bias[tid];
    __syncthreads();

    int half = tid / 480;
    int rem  = tid % 480;
    int ocp = rem & 15;
    int row = rem >> 4;
    int ox0 = half * 15;

    u64t acc[15];
    u64t bv = *(const u64t*)(s_b + ocp * 2);
#pragma unroll
    for (int i = 0; i < 15; i++) acc[i] = bv;

#pragma unroll
    for (int ic = 0; ic < 3; ic++) {
#pragma unroll
        for (int ky = 0; ky < 3; ky++) {
            const float* irow = s_img + ic * 1024 + (row + ky) * 32;
            float in[17];
            if (half == 0) {
#pragma unroll
                for (int i = 0; i < 4; i++) {
                    float4 v4 = ((const float4*)irow)[i];
                    in[4 * i] = v4.x; in[4 * i + 1] = v4.y;
                    in[4 * i + 2] = v4.z; in[4 * i + 3] = v4.w;
                }
                in[16] = irow[16];
            } else {
                in[0] = irow[15];
#pragma unroll
                for (int i = 0; i < 4; i++) {
                    float4 v4 = ((const float4*)(irow + 16))[i];
                    in[4 * i + 1] = v4.x; in[4 * i + 2] = v4.y;
                    in[4 * i + 3] = v4.z; in[4 * i + 4] = v4.w;
                }
            }
#pragma unroll
            for (int kx = 0; kx < 3; kx++) {
                u64t wv = *(const u64t*)(s_w + ((ic * 3 + ky) * 3 + kx) * 32 + ocp * 2);
#pragma unroll
                for (int i = 0; i < 15; i++)
                    ffma2(acc[i], wv, splat2(in[i + kx]));
            }
        }
    }
    u64t* ob = (u64t*)(g_buf1 + (((size_t)img * 30 + row) * 30 + ox0) * 32 + 2 * ocp);
    float slo = 0.f, qlo = 0.f, shi = 0.f, qhi = 0.f;
#pragma unroll
    for (int i = 0; i < 15; i++) {
        u64t v = acc[i];
        ob[i * 16] = v;
        float a = lo32(v), b2 = hi32(v);
        slo += a; qlo += a * a; shi += b2; qhi += b2 * b2;
    }
    int rh = row + 30 * half;
    s_ss[2 * ocp][rh] = slo; s_sq[2 * ocp][rh] = qlo;
    s_ss[2 * ocp + 1][rh] = shi; s_sq[2 * ocp + 1][rh] = qhi;
    __syncthreads();
    if (tid < 32) {
        float s = 0.f, q = 0.f;
#pragma unroll
        for (int r = 0; r < 60; r++) { s += s_ss[tid][r]; q += s_sq[tid][r]; }
        g_psum[tid * NB + img] = s;
        g_psq[tid * NB + img] = q;
    }
}

// Per-channel reduction over 2048 images (fixed pairwise order) -> scale/shift.
__global__ __launch_bounds__(256) void reduce_stats_kernel(
    int stage, float invN,
    const float* __restrict__ gamma, const float* __restrict__ beta)
{
    __shared__ float ss[256], sq[256];
    int c = blockIdx.x;
    int t = threadIdx.x;
    float s = 0.f, q = 0.f;
#pragma unroll
    for (int k = 0; k < NB / 256; k++) {
        int img = t + k * 256;
        s += g_psum[c * NB + img];
        q += g_psq[c * NB + img];
    }
    ss[t] = s; sq[t] = q;
    __syncthreads();
#pragma unroll
    for (int off = 128; off; off >>= 1) {
        if (t < off) { ss[t] += ss[t + off]; sq[t] += sq[t + off]; }
        __syncthreads();
    }
    if (t == 0) {
        float mu = ss[0] * invN;
        float var = sq[0] * invN - mu * mu;
        float sc = gamma[c] * rsqrtf(var + 1e-5f);
        g_scale[stage][c] = sc;
        g_shift[stage][c] = beta[c] - mu * sc;
    }
}

// ---------------------- bn + relu + avgpool2 (NHWC, float4) ----------------
__device__ __forceinline__ float4 bnrelu4(float4 v, float4 sc, float4 sh) {
    float4 r;
    r.x = fmaxf(v.x * sc.x + sh.x, 0.f);
    r.y = fmaxf(v.y * sc.y + sh.y, 0.f);
    r.z = fmaxf(v.z * sc.z + sh.z, 0.f);
    r.w = fmaxf(v.w * sc.w + sh.w, 0.f);
    return r;
}

__global__ __launch_bounds__(256) void pool1_kernel() {
    int img = blockIdx.x;
    for (int i = threadIdx.x; i < 1800; i += 256) {
        int c4 = i & 7, p = i >> 3;
        int oy = p / 15, ox = p % 15;
        const float4* b = (const float4*)(g_buf1
            + (((size_t)img * 30 + 2 * oy) * 30 + 2 * ox) * 32) + c4;
        float4 sc = ((const float4*)g_scale[0])[c4];
        float4 sh = ((const float4*)g_shift[0])[c4];
        float4 a0 = bnrelu4(b[0], sc, sh);
        float4 a1 = bnrelu4(b[8], sc, sh);
        float4 a2 = bnrelu4(b[240], sc, sh);
        float4 a3 = bnrelu4(b[248], sc, sh);
        float4 r;
        r.x = (a0.x + a1.x + a2.x + a3.x) * 0.25f;
        r.y = (a0.y + a1.y + a2.y + a3.y) * 0.25f;
        r.z = (a0.z + a1.z + a2.z + a3.z) * 0.25f;
        r.w = (a0.w + a1.w + a2.w + a3.w) * 0.25f;
        ((float4*)(g_buf2 + ((size_t)img * 225 + p) * 32))[c4] = r;
    }
}

__global__ __launch_bounds__(288) void pool2_kernel() {
    int img = blockIdx.x;
    int i = threadIdx.x;
    int c4 = i & 7, p = i >> 3;
    int oy = p / 6, ox = p % 6;
    const float4* b = (const float4*)(g_buf3
        + (((size_t)img * 13 + 2 * oy) * 13 + 2 * ox) * 32) + c4;
    float4 sc = ((const float4*)g_scale[1])[c4];
    float4 sh = ((const float4*)g_shift[1])[c4];
    float4 a0 = bnrelu4(b[0], sc, sh);
    float4 a1 = bnrelu4(b[8], sc, sh);
    float4 a2 = bnrelu4(b[104], sc, sh);
    float4 a3 = bnrelu4(b[112], sc, sh);
    float4 r;
    r.x = (a0.x + a1.x + a2.x + a3.x) * 0.25f;
    r.y = (a0.y + a1.y + a2.y + a3.y) * 0.25f;
    r.z = (a0.z + a1.z + a2.z + a3.z) * 0.25f;
    r.w = (a0.w + a1.w + a2.w + a3.w) * 0.25f;
    ((float4*)(g_buf4 + ((size_t)img * 36 + p) * 32))[c4] = r;
}

// ------------- conv2: 32->32, 15x15 -> 13x13, 2 images/block ---------------
__global__ __launch_bounds__(448, 2) void conv2_kernel(
    const float* __restrict__ w, const float* __restrict__ bias)
{
    extern __shared__ float sm[];
    float* s_img = sm;            // 2 * 32*15*16 = 15360
    float* s_w = sm + 15360;      // 9216
    __shared__ float s_b[32];
    __shared__ float s_ss[2][32][13];
    __shared__ float s_sq[2][32][13];
    int tid = threadIdx.x;
    int img0 = blockIdx.x * 2;

    const float* ib = g_buf2 + (size_t)img0 * 7200;
    for (int i = tid; i < 14400; i += 448) {
        int sub = i / 7200, j = i % 7200;
        int c = j & 31, p = j >> 5;
        s_img[sub * 7680 + c * 240 + (p / 15) * 16 + (p % 15)] = ib[i];
    }
    for (int i = tid; i < 9216; i += 448) {
        int oc = i / 288, r = i % 288;
        s_w[r * 32 + oc] = w[i];
    }
    if (tid < 32) s_b[tid] = bias[tid];
    __syncthreads();

    int sub = tid / 224;
    int local = tid % 224;
    if (local < 208) {
        int ocp = local & 15;
        int row = local >> 4;
        const float* imgbase = s_img + sub * 7680;
        u64t acc[13];
        u64t bv = *(const u64t*)(s_b + ocp * 2);
#pragma unroll
        for (int i = 0; i < 13; i++) acc[i] = bv;

        for (int ic = 0; ic < 32; ic++) {
#pragma unroll
            for (int ky = 0; ky < 3; ky++) {
                const float4* irow4 = (const float4*)(imgbase + ic * 240 + (row + ky) * 16);
                float in[16];
#pragma unroll
                for (int i = 0; i < 4; i++) {
                    float4 v4 = irow4[i];
                    in[4 * i] = v4.x; in[4 * i + 1] = v4.y;
                    in[4 * i + 2] = v4.z; in[4 * i + 3] = v4.w;
                }
#pragma unroll
                for (int kx = 0; kx < 3; kx++) {
                    u64t wv = *(const u64t*)(s_w + (ic * 9 + ky * 3 + kx) * 32 + ocp * 2);
#pragma unroll
                    for (int ox = 0; ox < 13; ox++)
                        ffma2(acc[ox], wv, splat2(in[ox + kx]));
                }
            }
        }
        u64t* ob = (u64t*)(g_buf3 + (((size_t)(img0 + sub) * 13 + row) * 13) * 32 + 2 * ocp);
        float slo = 0.f, qlo = 0.f, shi = 0.f, qhi = 0.f;
#pragma unroll
        for (int ox = 0; ox < 13; ox++) {
            u64t v = acc[ox];
            ob[ox * 16] = v;
            float a = lo32(v), b2 = hi32(v);
            slo += a; qlo += a * a; shi += b2; qhi += b2 * b2;
        }
        s_ss[sub][2 * ocp][row] = slo; s_sq[sub][2 * ocp][row] = qlo;
        s_ss[sub][2 * ocp + 1][row] = shi; s_sq[sub][2 * ocp + 1][row] = qhi;
    }
    __syncthreads();
    if (tid < 64) {
        int ssub = tid >> 5, c = tid & 31;
        float s = 0.f, q = 0.f;
#pragma unroll
        for (int r = 0; r < 13; r++) { s += s_ss[ssub][c][r]; q += s_sq[ssub][c][r]; }
        g_psum[c * NB + img0 + ssub] = s;
        g_psq[c * NB + img0 + ssub] = q;
    }
}

// ------------- conv3: 32->32, 6x6 -> 4x4, 4 images/block, row/thread -------
__global__ __launch_bounds__(256) void conv3_kernel(
    const float* __restrict__ w, const float* __restrict__ bias)
{
    extern __shared__ float sm[];
    float* s_img = sm;            // 4 * 32*6*8 = 6144
    float* s_w = sm + 6144;       // 9216
    __shared__ float s_b[32];
    __shared__ float s_ss[4][32][4];
    __shared__ float s_sq[4][32][4];
    int tid = threadIdx.x;
    int img0 = blockIdx.x * 4;

    const float* ib = g_buf4 + (size_t)img0 * 1152;
    for (int i = tid; i < 4608; i += 256) {
        int il = i / 1152, j = i % 1152;
        int c = j & 31, p = j >> 5;
        s_img[il * 1536 + c * 48 + (p / 6) * 8 + (p % 6)] = ib[i];
    }
    for (int i = tid; i < 9216; i += 256) {
        int oc = i / 288, r = i % 288;
        s_w[r * 32 + oc] = w[i];
    }
    if (tid < 32) s_b[tid] = bias[tid];
    __syncthreads();

    int ocp = tid & 15;
    int oy = (tid >> 4) & 3;
    int il = tid >> 6;
    const float* imgbase = s_img + il * 1536;
    u64t acc[4];
    u64t bv = *(const u64t*)(s_b + ocp * 2);
#pragma unroll
    for (int i = 0; i < 4; i++) acc[i] = bv;

    for (int ic = 0; ic < 32; ic++) {
#pragma unroll
        for (int ky = 0; ky < 3; ky++) {
            const float* irow = imgbase + ic * 48 + (oy + ky) * 8;
            float in[6];
            float4 v4 = *(const float4*)irow;
            in[0] = v4.x; in[1] = v4.y; in[2] = v4.z; in[3] = v4.w;
            in[4] = irow[4]; in[5] = irow[5];
#pragma unroll
            for (int kx = 0; kx < 3; kx++) {
                u64t wv = *(const u64t*)(s_w + (ic * 9 + ky * 3 + kx) * 32 + ocp * 2);
#pragma unroll
                for (int ox = 0; ox < 4; ox++)
                    ffma2(acc[ox], wv, splat2(in[ox + kx]));
            }
        }
    }
    u64t* ob = (u64t*)(g_buf5 + ((size_t)(img0 + il) * 16 + oy * 4) * 32 + 2 * ocp);
    float slo = 0.f, qlo = 0.f, shi = 0.f, qhi = 0.f;
#pragma unroll
    for (int ox = 0; ox < 4; ox++) {
        u64t v = acc[ox];
        ob[ox * 16] = v;
        float a = lo32(v), b2 = hi32(v);
        slo += a; qlo += a * a; shi += b2; qhi += b2 * b2;
    }
    s_ss[il][2 * ocp][oy] = slo; s_sq[il][2 * ocp][oy] = qlo;
    s_ss[il][2 * ocp + 1][oy] = shi; s_sq[il][2 * ocp + 1][oy] = qhi;
    __syncthreads();
    if (tid < 128) {
        int iimg = tid >> 5, c = tid & 31;
        float s = 0.f, q = 0.f;
#pragma unroll
        for (int r = 0; r < 4; r++) { s += s_ss[iimg][c][r]; q += s_sq[iimg][c][r]; }
        g_psum[c * NB + img0 + iimg] = s;
        g_psq[c * NB + img0 + iimg] = q;
    }
}

// --------------------------- beam search (+ fused pool3) -------------------
__device__ __forceinline__ float warp_sum(float v) {
#pragma unroll
    for (int off = 16; off; off >>= 1) v += __shfl_down_sync(0xffffffffu, v, off);
    return v;
}

__global__ __launch_bounds__(128) void beam_kernel(
    const float* __restrict__ W_hh, const float* __restrict__ b_h,
    const float* __restrict__ E_op, const float* __restrict__ W_ho,
    const float* __restrict__ b_ho)
{
    __shared__ float s_h0[128];
    __shared__ float s_h[4][128];
    __shared__ float s_hn[4][128];
    __shared__ float s_Who[512];
    __shared__ float s_logits[4][4];
    __shared__ float s_scores[4];
    __shared__ int   s_op[4];
    __shared__ int   s_src[4];

    int n = blockIdx.x;
    int tid = threadIdx.x;
    int warp = tid >> 5, lane = tid & 31;

    // fused pool3: h0 element tid = c*4 + p, c = tid>>2, p = tid&3
    {
        int c = tid >> 2, p = tid & 3;
        int oy = p >> 1, ox = p & 1;
        const float* b = g_buf5 + ((size_t)n * 16 + (2 * oy) * 4 + 2 * ox) * 32 + c;
        float sc = g_scale[2][c], sh = g_shift[2][c];
        float v = fmaxf(b[0] * sc + sh, 0.f) + fmaxf(b[32] * sc + sh, 0.f)
                + fmaxf(b[128] * sc + sh, 0.f) + fmaxf(b[160] * sc + sh, 0.f);
        v *= 0.25f;
        s_h0[tid] = v;
        g_h0[(size_t)n * 128 + tid] = v;
    }
#pragma unroll
    for (int i = 0; i < 4; i++) s_Who[i * 128 + tid] = W_ho[i * 128 + tid];
    __syncthreads();

    {
        float a = 0.f;
        for (int d = lane; d < 128; d += 32) a += s_h0[d] * s_Who[d * 4 + warp];
        a = warp_sum(a);
        if (lane == 0) s_logits[0][warp] = a + b_ho[warp];
    }
    __syncthreads();

    if (tid == 0) {
        float l[4], e[4];
        float m = -FLT_MAX;
#pragma unroll
        for (int o = 0; o < 4; o++) { l[o] = s_logits[0][o]; m = fmaxf(m, l[o]); }
        float sum = 0.f;
#pragma unroll
        for (int o = 0; o < 4; o++) { e[o] = expf(l[o] - m); sum += e[o]; }
        float logsum = logf(sum);
        float inv = 1.f / sum;
        bool used[4] = {false, false, false, false};
        for (int b = 0; b < 4; b++) {
            int best = -1; float bv = -FLT_MAX;
            for (int o = 0; o < 4; o++) {
                float lp = l[o] - m - logsum;
                if (!used[o] && lp > bv) { bv = lp; best = o; }
            }
            used[best] = true;
            s_scores[b] = bv;
            s_op[b] = best;
            g_op[0 * (NB * 4) + n * 4 + b] = best;
            g_pv[0 * (NB * 4) + n * 4 + b] = e[best] * inv;
        }
    }
    __syncthreads();

    {
        float common = 0.f;
#pragma unroll 8
        for (int k = 0; k < 128; k++) common += s_h0[k] * W_hh[k * 128 + tid];
        float bh = b_h[tid];
#pragma unroll
        for (int b = 0; b < 4; b++)
            s_h[b][tid] = tanhf(common + E_op[s_op[b] * 128 + tid] + bh);
    }
    __syncthreads();

    for (int step = 1; step < 3; step++) {
        {
            float a0 = 0.f, a1 = 0.f, a2 = 0.f, a3 = 0.f;
            for (int d = lane; d < 128; d += 32) {
                float v = s_h[warp][d];
                a0 += v * s_Who[d * 4 + 0];
                a1 += v * s_Who[d * 4 + 1];
                a2 += v * s_Who[d * 4 + 2];
                a3 += v * s_Who[d * 4 + 3];
            }
            a0 = warp_sum(a0); a1 = warp_sum(a1); a2 = warp_sum(a2); a3 = warp_sum(a3);
            if (lane == 0) {
                s_logits[warp][0] = a0 + b_ho[0];
                s_logits[warp][1] = a1 + b_ho[1];
                s_logits[warp][2] = a2 + b_ho[2];
                s_logits[warp][3] = a3 + b_ho[3];
            }
        }
        __syncthreads();

        if (tid == 0) {
            float cand[16], probs[16];
            for (int b = 0; b < 4; b++) {
                float l[4], e[4];
                float m = -FLT_MAX;
#pragma unroll
                for (int o = 0; o < 4; o++) { l[o] = s_logits[b][o]; m = fmaxf(m, l[o]); }
                float sum = 0.f;
#pragma unroll
                for (int o = 0; o < 4; o++) { e[o] = expf(l[o] - m); sum += e[o]; }
                float logsum = logf(sum);
                float inv = 1.f / sum;
#pragma unroll
                for (int o = 0; o < 4; o++) {
                    cand[b * 4 + o] = s_scores[b] + (l[o] - m - logsum);
                    probs[b * 4 + o] = e[o] * inv;
                }
            }
            bool used[16];
            for (int i = 0; i < 16; i++) used[i] = false;
            float ns[4];
            for (int b = 0; b < 4; b++) {
                int best = -1; float bv = -FLT_MAX;
                for (int f = 0; f < 16; f++)
                    if (!used[f] && cand[f] > bv) { bv = cand[f]; best = f; }
                used[best] = true;
                ns[b] = bv;
                int src = best >> 2, op = best & 3;
                s_src[b] = src; s_op[b] = op;
                g_op[step * (NB * 4) + n * 4 + b] = op;
                g_pv[step * (NB * 4) + n * 4 + b] = probs[best];
            }
#pragma unroll
            for (int b = 0; b < 4; b++) s_scores[b] = ns[b];
        }
        __syncthreads();

        if (step < 2) {
            int r0 = s_src[0], r1 = s_src[1], r2 = s_src[2], r3 = s_src[3];
            float a0 = 0.f, a1 = 0.f, a2 = 0.f, a3 = 0.f;
#pragma unroll 4
            for (int k = 0; k < 128; k++) {
                float wv = W_hh[k * 128 + tid];
                a0 += s_h[r0][k] * wv;
                a1 += s_h[r1][k] * wv;
                a2 += s_h[r2][k] * wv;
                a3 += s_h[r3][k] * wv;
            }
            float bh = b_h[tid];
            s_hn[0][tid] = tanhf(a0 + E_op[s_op[0] * 128 + tid] + bh);
            s_hn[1][tid] = tanhf(a1 + E_op[s_op[1] * 128 + tid] + bh);
            s_hn[2][tid] = tanhf(a2 + E_op[s_op[2] * 128 + tid] + bh);
            s_hn[3][tid] = tanhf(a3 + E_op[s_op[3] * 128 + tid] + bh);
            __syncthreads();
#pragma unroll
            for (int b = 0; b < 4; b++) s_h[b][tid] = s_hn[b][tid];
            __syncthreads();
        }
    }
}

// ---------------------- sorted MoE dispatch --------------------------------
__global__ void zero_cnt_kernel() {
    int i = threadIdx.x;
    if (i < 12) (&g_cnt[0][0])[i] = 0;
}

// Bucket rows by (step, effective expert). Order within bucket is
// nondeterministic (atomics) but per-row outputs are order-independent.
__global__ __launch_bounds__(256) void build_index_kernel() {
    int i = blockIdx.x * 256 + threadIdx.x;   // over 3 * 8192
    if (i >= 3 * NB * 4) return;
    int s = i / (NB * 4), m = i % (NB * 4);
    int op = g_op[s * (NB * 4) + m];
    float p = g_pv[s * (NB * 4) + m];
    int e = (p > 0.f) ? op : 0;
    int pos = atomicAdd(&g_cnt[s][e], 1);
    g_ridx[(s * 4 + e) * (NB * 4) + pos] = m;
}

// One step of dispatch: grid (chunk, expert). Expert e<3: GEMM over that
// expert's rows only. e==3: identity path. step==0 reads from g_h0 (row m
// uses h0[m/4]); otherwise reads g_hid. Writes g_hid (row-disjoint, safe).
__global__ __launch_bounds__(256) void moe_step_kernel(
    const float* __restrict__ exp_w, const float* __restrict__ exp_b, int step)
{
    extern __shared__ float sm[];
    float* s_w = sm;              // 16384 floats
    float* buf = sm + 16384;      // 32 x 128
    __shared__ float s_b[128];
    __shared__ int   s_rows[32];
    __shared__ float s_p[32];
    __shared__ int   s_cnt;

    int e = blockIdx.y;
    int tid = threadIdx.x;
    if (tid == 0) s_cnt = g_cnt[step][e];
    __syncthreads();
    int base = blockIdx.x * 32;
    if (base >= s_cnt) return;
    int nrows = min(32, s_cnt - base);

    if (tid < nrows) {
        int m = g_ridx[(step * 4 + e) * (NB * 4) + base + tid];
        s_rows[tid] = m;
        s_p[tid] = g_pv[step * (NB * 4) + m];
    }
    __syncthreads();

    if (e == 3) {   // identity: out = relu(hid * p)
        for (int i = tid; i < nrows * 128; i += 256) {
            int r = i >> 7, j = i & 127;
            int m = s_rows[r];
            float v = (step == 0) ? g_h0[(size_t)(m >> 2) * 128 + j]
                                  : g_hid[(size_t)m * 128 + j];
            g_hid[(size_t)m * 128 + j] = fmaxf(v * s_p[r], 0.f);
        }
        return;
    }

    for (int i = tid; i < 16384; i += 256) s_w[i] = exp_w[e * 16384 + i];
    if (tid < 128) s_b[tid] = exp_b[e * 128 + tid];
    for (int i = tid; i < 4096; i += 256) {
        int r = i >> 7, j = i & 127;
        float v = 0.f;
        if (r < nrows) {
            int m = s_rows[r];
            v = (step == 0) ? g_h0[(size_t)(m >> 2) * 128 + j]
                            : g_hid[(size_t)m * 128 + j];
        }
        buf[i] = v;
    }
    __syncthreads();

    int cp = tid & 63, rowg = tid >> 6;
    int r0 = rowg * 8, j0 = cp * 2;
    u64t acc[8];
#pragma unroll
    for (int k = 0; k < 8; k++) acc[k] = 0ull;
#pragma unroll 2
    for (int d = 0; d < 128; d++) {
        u64t w2 = *(const u64t*)(s_w + d * 128 + j0);
#pragma unroll
        for (int k = 0; k < 8; k++)
            ffma2(acc[k], w2, splat2(buf[(r0 + k) * 128 + d]));
    }
    u64t b2 = *(const u64t*)(s_b + j0);
#pragma unroll
    for (int k = 0; k < 8; k++) {
        int r = r0 + k;
        if (r < nrows) {
            int m = s_rows[r];
            float v = s_p[r];
            float2 st;
            st.x = fmaxf((lo32(acc[k]) + lo32(b2)) * v, 0.f);
            st.y = fmaxf((hi32(acc[k]) + hi32(b2)) * v, 0.f);
            *(float2*)(g_hid + (size_t)m * 128 + j0) = st;
        }
    }
}

// --------------------------- final projection ------------------------------
__global__ __launch_bounds__(256) void out_kernel(
    const float* __restrict__ out_w, const float* __restrict__ out_b,
    float* __restrict__ out)
{
    int warp = threadIdx.x >> 5, lane = threadIdx.x & 31;
    int row = blockIdx.x * 8 + warp;
    const float* hp = g_hid + (size_t)row * 128;
    float acc[10];
#pragma unroll
    for (int o = 0; o < 10; o++) acc[o] = 0.f;
    for (int d = lane; d < 128; d += 32) {
        float v = hp[d];
#pragma unroll
        for (int o = 0; o < 10; o++) acc[o] += v * out_w[d * 10 + o];
    }
#pragma unroll
    for (int o = 0; o < 10; o++) acc[o] = warp_sum(acc[o]);
    if (lane == 0) {
#pragma unroll
        for (int o = 0; o < 10; o++) out[(size_t)row * 10 + o] = acc[o] + out_b[o];
    }
}

// ---------------------------------------------------------------------------
extern "C" void kernel_launch(void* const* d_in, const int* in_sizes, int n_in,
                              void* d_out, int out_size)
{
    const float* x    = (const float*)d_in[0];
    const float* cw1  = (const float*)d_in[1];
    const float* cb1  = (const float*)d_in[2];
    const float* g1   = (const float*)d_in[3];
    const float* be1  = (const float*)d_in[4];
    const float* cw2  = (const float*)d_in[5];
    const float* cb2  = (const float*)d_in[6];
    const float* g2   = (const float*)d_in[7];
    const float* be2  = (const float*)d_in[8];
    const float* cw3  = (const float*)d_in[9];
    const float* cb3  = (const float*)d_in[10];
    const float* g3   = (const float*)d_in[11];
    const float* be3  = (const float*)d_in[12];
    const float* W_hh = (const float*)d_in[13];
    const float* b_h  = (const float*)d_in[14];
    const float* E_op = (const float*)d_in[15];
    const float* W_ho = (const float*)d_in[16];
    const float* b_ho = (const float*)d_in[17];
    const float* expw = (const float*)d_in[18];
    const float* expb = (const float*)d_in[19];
    const float* outw = (const float*)d_in[20];
    const float* outb = (const float*)d_in[21];
    float* out = (float*)d_out;

    cudaFuncSetAttribute(conv2_kernel, cudaFuncAttributeMaxDynamicSharedMemorySize,
                         (15360 + 9216) * 4);
    cudaFuncSetAttribute(conv3_kernel, cudaFuncAttributeMaxDynamicSharedMemorySize,
                         (6144 + 9216) * 4);
    cudaFuncSetAttribute(moe_step_kernel, cudaFuncAttributeMaxDynamicSharedMemorySize,
                         (16384 + 4096) * 4);

    conv1_kernel<<<NB, 960>>>(x, cw1, cb1);
    reduce_stats_kernel<<<32, 256>>>(0, 1.f / (NB * 900.f), g1, be1);
    pool1_kernel<<<NB, 256>>>();

    conv2_kernel<<<NB / 2, 448, (15360 + 9216) * 4>>>(cw2, cb2);
    reduce_stats_kernel<<<32, 256>>>(1, 1.f / (NB * 169.f), g2, be2);
    pool2_kernel<<<NB, 288>>>();

    conv3_kernel<<<NB / 4, 256, (6144 + 9216) * 4>>>(cw3, cb3);
    reduce_stats_kernel<<<32, 256>>>(2, 1.f / (NB * 16.f), g3, be3);

    beam_kernel<<<NB, 128>>>(W_hh, b_h, E_op, W_ho, b_ho);

    zero_cnt_kernel<<<1, 32>>>();
    build_index_kernel<<<(3 * NB * 4 + 255) / 256, 256>>>();

    dim3 moe_grid(NB * 4 / 32, 4);
    moe_step_kernel<<<moe_grid, 256, (16384 + 4096) * 4>>>(expw, expb, 0);
    moe_step_kernel<<<moe_grid, 256, (16384 + 4096) * 4>>>(expw, expb, 1);
    moe_step_kernel<<<moe_grid, 256, (16384 + 4096) * 4>>>(expw, expb, 2);

    out_kernel<<<NB * 4 / 8, 256>>>(outw, outb, out);
}

// round 10
// speedup vs baseline: 2.0108x; 1.1110x over previous
#include <cuda_runtime.h>
#include <math.h>
#include <float.h>
#include <stdint.h>

// ---------------------------------------------------------------------------
// Supernetwork: backbone (3x conv+BN+relu+pool) -> beam search -> MoE dispatch
// B=2048, BEAMS=4, DEPTH=3, HID=128, NOPS=4
//
// Round-9:
//  * pool1 fused into conv2's smem load (BN+relu+avgpool applied while
//    filling the padded image tile). pool1 kernel deleted.
//  * pool2 fused into conv3's smem load. pool2 kernel deleted.
//  * output projection fused into moe_step(step==2). out kernel deleted.
//  * conv1/conv2 mainloops, beam, sorted-MoE unchanged from R8.
//  * Determinism: no float atomics; fixed-order FP reductions only.
// ---------------------------------------------------------------------------

#define NB 2048

// ------------------------------ scratch ------------------------------------
__device__ float g_buf1[(size_t)NB * 30 * 30 * 32];  // conv1 out, NHWC
__device__ float g_buf3[(size_t)NB * 13 * 13 * 32];  // conv2 out, NHWC
__device__ float g_buf5[(size_t)NB * 16 * 32];       // conv3 out, NHWC (4x4)
__device__ float g_h0[(size_t)NB * 128];             // backbone feature
__device__ float g_hid[(size_t)NB * 4 * 128];        // dispatch state
__device__ float g_psum[32 * NB];
__device__ float g_psq[32 * NB];
__device__ float g_scale[3][32];
__device__ float g_shift[3][32];
__device__ int   g_op[3 * NB * 4];
__device__ float g_pv[3 * NB * 4];
__device__ int   g_cnt[3][4];                        // rows per (step, expert)
__device__ int   g_ridx[3 * 4 * NB * 4];             // bucketed row indices

// --------------------------- f32x2 helpers ---------------------------------
typedef unsigned long long u64t;

__device__ __forceinline__ void ffma2(u64t& c, u64t a, u64t b) {
    asm("fma.rn.f32x2 %0, %1, %2, %0;" : "+l"(c) : "l"(a), "l"(b));
}
__device__ __forceinline__ u64t splat2(float v) {
    u64t r;
    asm("mov.b64 %0, {%1, %1};" : "=l"(r) : "r"(__float_as_uint(v)));
    return r;
}
__device__ __forceinline__ float lo32(u64t v) { return __uint_as_float((unsigned)v); }
__device__ __forceinline__ float hi32(u64t v) { return __uint_as_float((unsigned)(v >> 32)); }

__device__ __forceinline__ float4 bnrelu4(float4 v, float4 sc, float4 sh) {
    float4 r;
    r.x = fmaxf(v.x * sc.x + sh.x, 0.f);
    r.y = fmaxf(v.y * sc.y + sh.y, 0.f);
    r.z = fmaxf(v.z * sc.z + sh.z, 0.f);
    r.w = fmaxf(v.w * sc.w + sh.w, 0.f);
    return r;
}

// ------------------- conv1: 3->32, 32x32 -> 30x30, fused stats -------------
__global__ __launch_bounds__(960, 1) void conv1_kernel(
    const float* __restrict__ x, const float* __restrict__ w,
    const float* __restrict__ bias)
{
    __shared__ float s_img[3 * 1024];
    __shared__ float s_w[27 * 32];
    __shared__ float s_b[32];
    __shared__ float s_ss[32][60];
    __shared__ float s_sq[32][60];
    int tid = threadIdx.x;
    int img = blockIdx.x;
    const float* xb = x + (size_t)img * 3072;
    for (int i = tid; i < 768; i += 960)
        ((float4*)s_img)[i] = ((const float4*)xb)[i];
    if (tid < 864) {
        int oc = tid / 27, k = tid % 27;
        s_w[k * 32 + oc] = w[tid];
    }
    if (tid < 32) s_b[tid] = bias[tid];
    __syncthreads();

    int half = tid / 480;
    int rem  = tid % 480;
    int ocp = rem & 15;
    int row = rem >> 4;
    int ox0 = half * 15;

    u64t acc[15];
    u64t bv = *(const u64t*)(s_b + ocp * 2);
#pragma unroll
    for (int i = 0; i < 15; i++) acc[i] = bv;

#pragma unroll
    for (int ic = 0; ic < 3; ic++) {
#pragma unroll
        for (int ky = 0; ky < 3; ky++) {
            const float* irow = s_img + ic * 1024 + (row + ky) * 32;
            float in[17];
            if (half == 0) {
#pragma unroll
                for (int i = 0; i < 4; i++) {
                    float4 v4 = ((const float4*)irow)[i];
                    in[4 * i] = v4.x; in[4 * i + 1] = v4.y;
                    in[4 * i + 2] = v4.z; in[4 * i + 3] = v4.w;
                }
                in[16] = irow[16];
            } else {
                in[0] = irow[15];
#pragma unroll
                for (int i = 0; i < 4; i++) {
                    float4 v4 = ((const float4*)(irow + 16))[i];
                    in[4 * i + 1] = v4.x; in[4 * i + 2] = v4.y;
                    in[4 * i + 3] = v4.z; in[4 * i + 4] = v4.w;
                }
            }
#pragma unroll
            for (int kx = 0; kx < 3; kx++) {
                u64t wv = *(const u64t*)(s_w + ((ic * 3 + ky) * 3 + kx) * 32 + ocp * 2);
#pragma unroll
                for (int i = 0; i < 15; i++)
                    ffma2(acc[i], wv, splat2(in[i + kx]));
            }
        }
    }
    u64t* ob = (u64t*)(g_buf1 + (((size_t)img * 30 + row) * 30 + ox0) * 32 + 2 * ocp);
    float slo = 0.f, qlo = 0.f, shi = 0.f, qhi = 0.f;
#pragma unroll
    for (int i = 0; i < 15; i++) {
        u64t v = acc[i];
        ob[i * 16] = v;
        float a = lo32(v), b2 = hi32(v);
        slo += a; qlo += a * a; shi += b2; qhi += b2 * b2;
    }
    int rh = row + 30 * half;
    s_ss[2 * ocp][rh] = slo; s_sq[2 * ocp][rh] = qlo;
    s_ss[2 * ocp + 1][rh] = shi; s_sq[2 * ocp + 1][rh] = qhi;
    __syncthreads();
    if (tid < 32) {
        float s = 0.f, q = 0.f;
#pragma unroll
        for (int r = 0; r < 60; r++) { s += s_ss[tid][r]; q += s_sq[tid][r]; }
        g_psum[tid * NB + img] = s;
        g_psq[tid * NB + img] = q;
    }
}

// Per-channel reduction over 2048 images (fixed pairwise order) -> scale/shift.
__global__ __launch_bounds__(256) void reduce_stats_kernel(
    int stage, float invN,
    const float* __restrict__ gamma, const float* __restrict__ beta)
{
    __shared__ float ss[256], sq[256];
    int c = blockIdx.x;
    int t = threadIdx.x;
    float s = 0.f, q = 0.f;
#pragma unroll
    for (int k = 0; k < NB / 256; k++) {
        int img = t + k * 256;
        s += g_psum[c * NB + img];
        q += g_psq[c * NB + img];
    }
    ss[t] = s; sq[t] = q;
    __syncthreads();
#pragma unroll
    for (int off = 128; off; off >>= 1) {
        if (t < off) { ss[t] += ss[t + off]; sq[t] += sq[t + off]; }
        __syncthreads();
    }
    if (t == 0) {
        float mu = ss[0] * invN;
        float var = sq[0] * invN - mu * mu;
        float sc = gamma[c] * rsqrtf(var + 1e-5f);
        g_scale[stage][c] = sc;
        g_shift[stage][c] = beta[c] - mu * sc;
    }
}

// ------- conv2: 32->32, 15x15 -> 13x13, 2 imgs/block, fused pool1 load -----
__global__ __launch_bounds__(448, 2) void conv2_kernel(
    const float* __restrict__ w, const float* __restrict__ bias)
{
    extern __shared__ float sm[];
    float* s_img = sm;            // 2 * 32*15*16 = 15360
    float* s_w = sm + 15360;      // 9216
    __shared__ float s_b[32];
    __shared__ float s_ss[2][32][13];
    __shared__ float s_sq[2][32][13];
    int tid = threadIdx.x;
    int img0 = blockIdx.x * 2;

    // fused pool1: read raw conv1 output, apply BN+relu+avgpool2 into smem
    for (int i = tid; i < 3600; i += 448) {
        int sub = i / 1800, j = i % 1800;
        int c4 = j & 7, p = j >> 3;          // p = oy*15+ox
        int oy = p / 15, ox = p % 15;
        const float4* b = (const float4*)(g_buf1
            + (((size_t)(img0 + sub) * 30 + 2 * oy) * 30 + 2 * ox) * 32) + c4;
        float4 sc = ((const float4*)g_scale[0])[c4];
        float4 sh = ((const float4*)g_shift[0])[c4];
        float4 a0 = bnrelu4(b[0], sc, sh);
        float4 a1 = bnrelu4(b[8], sc, sh);
        float4 a2 = bnrelu4(b[240], sc, sh);
        float4 a3 = bnrelu4(b[248], sc, sh);
        int base = sub * 7680 + oy * 16 + ox;
        s_img[base + (4 * c4 + 0) * 240] = (a0.x + a1.x + a2.x + a3.x) * 0.25f;
        s_img[base + (4 * c4 + 1) * 240] = (a0.y + a1.y + a2.y + a3.y) * 0.25f;
        s_img[base + (4 * c4 + 2) * 240] = (a0.z + a1.z + a2.z + a3.z) * 0.25f;
        s_img[base + (4 * c4 + 3) * 240] = (a0.w + a1.w + a2.w + a3.w) * 0.25f;
    }
    for (int i = tid; i < 9216; i += 448) {
        int oc = i / 288, r = i % 288;
        s_w[r * 32 + oc] = w[i];
    }
    if (tid < 32) s_b[tid] = bias[tid];
    __syncthreads();

    int sub = tid / 224;
    int local = tid % 224;
    if (local < 208) {
        int ocp = local & 15;
        int row = local >> 4;
        const float* imgbase = s_img + sub * 7680;
        u64t acc[13];
        u64t bv = *(const u64t*)(s_b + ocp * 2);
#pragma unroll
        for (int i = 0; i < 13; i++) acc[i] = bv;

        for (int ic = 0; ic < 32; ic++) {
#pragma unroll
            for (int ky = 0; ky < 3; ky++) {
                const float4* irow4 = (const float4*)(imgbase + ic * 240 + (row + ky) * 16);
                float in[16];
#pragma unroll
                for (int i = 0; i < 4; i++) {
                    float4 v4 = irow4[i];
                    in[4 * i] = v4.x; in[4 * i + 1] = v4.y;
                    in[4 * i + 2] = v4.z; in[4 * i + 3] = v4.w;
                }
#pragma unroll
                for (int kx = 0; kx < 3; kx++) {
                    u64t wv = *(const u64t*)(s_w + (ic * 9 + ky * 3 + kx) * 32 + ocp * 2);
#pragma unroll
                    for (int ox = 0; ox < 13; ox++)
                        ffma2(acc[ox], wv, splat2(in[ox + kx]));
                }
            }
        }
        u64t* ob = (u64t*)(g_buf3 + (((size_t)(img0 + sub) * 13 + row) * 13) * 32 + 2 * ocp);
        float slo = 0.f, qlo = 0.f, shi = 0.f, qhi = 0.f;
#pragma unroll
        for (int ox = 0; ox < 13; ox++) {
            u64t v = acc[ox];
            ob[ox * 16] = v;
            float a = lo32(v), b2 = hi32(v);
            slo += a; qlo += a * a; shi += b2; qhi += b2 * b2;
        }
        s_ss[sub][2 * ocp][row] = slo; s_sq[sub][2 * ocp][row] = qlo;
        s_ss[sub][2 * ocp + 1][row] = shi; s_sq[sub][2 * ocp + 1][row] = qhi;
    }
    __syncthreads();
    if (tid < 64) {
        int ssub = tid >> 5, c = tid & 31;
        float s = 0.f, q = 0.f;
#pragma unroll
        for (int r = 0; r < 13; r++) { s += s_ss[ssub][c][r]; q += s_sq[ssub][c][r]; }
        g_psum[c * NB + img0 + ssub] = s;
        g_psq[c * NB + img0 + ssub] = q;
    }
}

// ------- conv3: 32->32, 6x6 -> 4x4, 4 imgs/block, fused pool2 load ---------
__global__ __launch_bounds__(256) void conv3_kernel(
    const float* __restrict__ w, const float* __restrict__ bias)
{
    extern __shared__ float sm[];
    float* s_img = sm;            // 4 * 32*6*8 = 6144
    float* s_w = sm + 6144;       // 9216
    __shared__ float s_b[32];
    __shared__ float s_ss[4][32][4];
    __shared__ float s_sq[4][32][4];
    int tid = threadIdx.x;
    int img0 = blockIdx.x * 4;

    // fused pool2: read raw conv2 output, apply BN+relu+avgpool2 into smem
    for (int i = tid; i < 1152; i += 256) {
        int il = i / 288, j = i % 288;
        int c4 = j & 7, p = j >> 3;          // p = oy*6+ox
        int oy = p / 6, ox = p % 6;
        const float4* b = (const float4*)(g_buf3
            + (((size_t)(img0 + il) * 13 + 2 * oy) * 13 + 2 * ox) * 32) + c4;
        float4 sc = ((const float4*)g_scale[1])[c4];
        float4 sh = ((const float4*)g_shift[1])[c4];
        float4 a0 = bnrelu4(b[0], sc, sh);
        float4 a1 = bnrelu4(b[8], sc, sh);
        float4 a2 = bnrelu4(b[104], sc, sh);
        float4 a3 = bnrelu4(b[112], sc, sh);
        int base = il * 1536 + oy * 8 + ox;
        s_img[base + (4 * c4 + 0) * 48] = (a0.x + a1.x + a2.x + a3.x) * 0.25f;
        s_img[base + (4 * c4 + 1) * 48] = (a0.y + a1.y + a2.y + a3.y) * 0.25f;
        s_img[base + (4 * c4 + 2) * 48] = (a0.z + a1.z + a2.z + a3.z) * 0.25f;
        s_img[base + (4 * c4 + 3) * 48] = (a0.w + a1.w + a2.w + a3.w) * 0.25f;
    }
    for (int i = tid; i < 9216; i += 256) {
        int oc = i / 288, r = i % 288;
        s_w[r * 32 + oc] = w[i];
    }
    if (tid < 32) s_b[tid] = bias[tid];
    __syncthreads();

    int ocp = tid & 15;
    int oy = (tid >> 4) & 3;
    int il = tid >> 6;
    const float* imgbase = s_img + il * 1536;
    u64t acc[4];
    u64t bv = *(const u64t*)(s_b + ocp * 2);
#pragma unroll
    for (int i = 0; i < 4; i++) acc[i] = bv;

    for (int ic = 0; ic < 32; ic++) {
#pragma unroll
        for (int ky = 0; ky < 3; ky++) {
            const float* irow = imgbase + ic * 48 + (oy + ky) * 8;
            float in[6];
            float4 v4 = *(const float4*)irow;
            in[0] = v4.x; in[1] = v4.y; in[2] = v4.z; in[3] = v4.w;
            in[4] = irow[4]; in[5] = irow[5];
#pragma unroll
            for (int kx = 0; kx < 3; kx++) {
                u64t wv = *(const u64t*)(s_w + (ic * 9 + ky * 3 + kx) * 32 + ocp * 2);
#pragma unroll
                for (int ox = 0; ox < 4; ox++)
                    ffma2(acc[ox], wv, splat2(in[ox + kx]));
            }
        }
    }
    u64t* ob = (u64t*)(g_buf5 + ((size_t)(img0 + il) * 16 + oy * 4) * 32 + 2 * ocp);
    float slo = 0.f, qlo = 0.f, shi = 0.f, qhi = 0.f;
#pragma unroll
    for (int ox = 0; ox < 4; ox++) {
        u64t v = acc[ox];
        ob[ox * 16] = v;
        float a = lo32(v), b2 = hi32(v);
        slo += a; qlo += a * a; shi += b2; qhi += b2 * b2;
    }
    s_ss[il][2 * ocp][oy] = slo; s_sq[il][2 * ocp][oy] = qlo;
    s_ss[il][2 * ocp + 1][oy] = shi; s_sq[il][2 * ocp + 1][oy] = qhi;
    __syncthreads();
    if (tid < 128) {
        int iimg = tid >> 5, c = tid & 31;
        float s = 0.f, q = 0.f;
#pragma unroll
        for (int r = 0; r < 4; r++) { s += s_ss[iimg][c][r]; q += s_sq[iimg][c][r]; }
        g_psum[c * NB + img0 + iimg] = s;
        g_psq[c * NB + img0 + iimg] = q;
    }
}

// --------------------------- beam search (+ fused pool3) -------------------
__device__ __forceinline__ float warp_sum(float v) {
#pragma unroll
    for (int off = 16; off; off >>= 1) v += __shfl_down_sync(0xffffffffu, v, off);
    return v;
}

__global__ __launch_bounds__(128) void beam_kernel(
    const float* __restrict__ W_hh, const float* __restrict__ b_h,
    const float* __restrict__ E_op, const float* __restrict__ W_ho,
    const float* __restrict__ b_ho)
{
    __shared__ float s_h0[128];
    __shared__ float s_h[4][128];
    __shared__ float s_hn[4][128];
    __shared__ float s_Who[512];
    __shared__ float s_logits[4][4];
    __shared__ float s_scores[4];
    __shared__ int   s_op[4];
    __shared__ int   s_src[4];

    int n = blockIdx.x;
    int tid = threadIdx.x;
    int warp = tid >> 5, lane = tid & 31;

    // fused pool3
    {
        int c = tid >> 2, p = tid & 3;
        int oy = p >> 1, ox = p & 1;
        const float* b = g_buf5 + ((size_t)n * 16 + (2 * oy) * 4 + 2 * ox) * 32 + c;
        float sc = g_scale[2][c], sh = g_shift[2][c];
        float v = fmaxf(b[0] * sc + sh, 0.f) + fmaxf(b[32] * sc + sh, 0.f)
                + fmaxf(b[128] * sc + sh, 0.f) + fmaxf(b[160] * sc + sh, 0.f);
        v *= 0.25f;
        s_h0[tid] = v;
        g_h0[(size_t)n * 128 + tid] = v;
    }
#pragma unroll
    for (int i = 0; i < 4; i++) s_Who[i * 128 + tid] = W_ho[i * 128 + tid];
    __syncthreads();

    {
        float a = 0.f;
        for (int d = lane; d < 128; d += 32) a += s_h0[d] * s_Who[d * 4 + warp];
        a = warp_sum(a);
        if (lane == 0) s_logits[0][warp] = a + b_ho[warp];
    }
    __syncthreads();

    if (tid == 0) {
        float l[4], e[4];
        float m = -FLT_MAX;
#pragma unroll
        for (int o = 0; o < 4; o++) { l[o] = s_logits[0][o]; m = fmaxf(m, l[o]); }
        float sum = 0.f;
#pragma unroll
        for (int o = 0; o < 4; o++) { e[o] = expf(l[o] - m); sum += e[o]; }
        float logsum = logf(sum);
        float inv = 1.f / sum;
        bool used[4] = {false, false, false, false};
        for (int b = 0; b < 4; b++) {
            int best = -1; float bv = -FLT_MAX;
            for (int o = 0; o < 4; o++) {
                float lp = l[o] - m - logsum;
                if (!used[o] && lp > bv) { bv = lp; best = o; }
            }
            used[best] = true;
            s_scores[b] = bv;
            s_op[b] = best;
            g_op[0 * (NB * 4) + n * 4 + b] = best;
            g_pv[0 * (NB * 4) + n * 4 + b] = e[best] * inv;
        }
    }
    __syncthreads();

    {
        float common = 0.f;
#pragma unroll 8
        for (int k = 0; k < 128; k++) common += s_h0[k] * W_hh[k * 128 + tid];
        float bh = b_h[tid];
#pragma unroll
        for (int b = 0; b < 4; b++)
            s_h[b][tid] = tanhf(common + E_op[s_op[b] * 128 + tid] + bh);
    }
    __syncthreads();

    for (int step = 1; step < 3; step++) {
        {
            float a0 = 0.f, a1 = 0.f, a2 = 0.f, a3 = 0.f;
            for (int d = lane; d < 128; d += 32) {
                float v = s_h[warp][d];
                a0 += v * s_Who[d * 4 + 0];
                a1 += v * s_Who[d * 4 + 1];
                a2 += v * s_Who[d * 4 + 2];
                a3 += v * s_Who[d * 4 + 3];
            }
            a0 = warp_sum(a0); a1 = warp_sum(a1); a2 = warp_sum(a2); a3 = warp_sum(a3);
            if (lane == 0) {
                s_logits[warp][0] = a0 + b_ho[0];
                s_logits[warp][1] = a1 + b_ho[1];
                s_logits[warp][2] = a2 + b_ho[2];
                s_logits[warp][3] = a3 + b_ho[3];
            }
        }
        __syncthreads();

        if (tid == 0) {
            float cand[16], probs[16];
            for (int b = 0; b < 4; b++) {
                float l[4], e[4];
                float m = -FLT_MAX;
#pragma unroll
                for (int o = 0; o < 4; o++) { l[o] = s_logits[b][o]; m = fmaxf(m, l[o]); }
                float sum = 0.f;
#pragma unroll
                for (int o = 0; o < 4; o++) { e[o] = expf(l[o] - m); sum += e[o]; }
                float logsum = logf(sum);
                float inv = 1.f / sum;
#pragma unroll
                for (int o = 0; o < 4; o++) {
                    cand[b * 4 + o] = s_scores[b] + (l[o] - m - logsum);
                    probs[b * 4 + o] = e[o] * inv;
                }
            }
            bool used[16];
            for (int i = 0; i < 16; i++) used[i] = false;
            float ns[4];
            for (int b = 0; b < 4; b++) {
                int best = -1; float bv = -FLT_MAX;
                for (int f = 0; f < 16; f++)
                    if (!used[f] && cand[f] > bv) { bv = cand[f]; best = f; }
                used[best] = true;
                ns[b] = bv;
                int src = best >> 2, op = best & 3;
                s_src[b] = src; s_op[b] = op;
                g_op[step * (NB * 4) + n * 4 + b] = op;
                g_pv[step * (NB * 4) + n * 4 + b] = probs[best];
            }
#pragma unroll
            for (int b = 0; b < 4; b++) s_scores[b] = ns[b];
        }
        __syncthreads();

        if (step < 2) {
            int r0 = s_src[0], r1 = s_src[1], r2 = s_src[2], r3 = s_src[3];
            float a0 = 0.f, a1 = 0.f, a2 = 0.f, a3 = 0.f;
#pragma unroll 4
            for (int k = 0; k < 128; k++) {
                float wv = W_hh[k * 128 + tid];
                a0 += s_h[r0][k] * wv;
                a1 += s_h[r1][k] * wv;
                a2 += s_h[r2][k] * wv;
                a3 += s_h[r3][k] * wv;
            }
            float bh = b_h[tid];
            s_hn[0][tid] = tanhf(a0 + E_op[s_op[0] * 128 + tid] + bh);
            s_hn[1][tid] = tanhf(a1 + E_op[s_op[1] * 128 + tid] + bh);
            s_hn[2][tid] = tanhf(a2 + E_op[s_op[2] * 128 + tid] + bh);
            s_hn[3][tid] = tanhf(a3 + E_op[s_op[3] * 128 + tid] + bh);
            __syncthreads();
#pragma unroll
            for (int b = 0; b < 4; b++) s_h[b][tid] = s_hn[b][tid];
            __syncthreads();
        }
    }
}

// ---------------------- sorted MoE dispatch --------------------------------
__global__ void zero_cnt_kernel() {
    int i = threadIdx.x;
    if (i < 12) (&g_cnt[0][0])[i] = 0;
}

__global__ __launch_bounds__(256) void build_index_kernel() {
    int i = blockIdx.x * 256 + threadIdx.x;   // over 3 * 8192
    if (i >= 3 * NB * 4) return;
    int s = i / (NB * 4), m = i % (NB * 4);
    int op = g_op[s * (NB * 4) + m];
    float p = g_pv[s * (NB * 4) + m];
    int e = (p > 0.f) ? op : 0;
    int pos = atomicAdd(&g_cnt[s][e], 1);
    g_ridx[(s * 4 + e) * (NB * 4) + pos] = m;
}

// One step of dispatch. step==2 additionally computes the final 128->10
// projection from smem (final hid never round-trips through global).
__global__ __launch_bounds__(256) void moe_step_kernel(
    const float* __restrict__ exp_w, const float* __restrict__ exp_b,
    const float* __restrict__ out_w, const float* __restrict__ out_b,
    float* __restrict__ out, int step)
{
    extern __shared__ float sm[];
    float* s_w = sm;              // 16384 floats
    float* buf = sm + 16384;      // 32 x 128
    float* s_outw = sm + 20480;   // 1280 floats (step==2 only)
    __shared__ float s_b[128];
    __shared__ float s_outb[10];
    __shared__ int   s_rows[32];
    __shared__ float s_p[32];
    __shared__ int   s_cnt;

    int e = blockIdx.y;
    int tid = threadIdx.x;
    if (tid == 0) s_cnt = g_cnt[step][e];
    __syncthreads();
    int base = blockIdx.x * 32;
    if (base >= s_cnt) return;
    int nrows = min(32, s_cnt - base);

    if (tid < nrows) {
        int m = g_ridx[(step * 4 + e) * (NB * 4) + base + tid];
        s_rows[tid] = m;
        s_p[tid] = g_pv[step * (NB * 4) + m];
    }
    if (step == 2) {
        for (int i = tid; i < 1280; i += 256) s_outw[i] = out_w[i];
        if (tid < 10) s_outb[tid] = out_b[tid];
    }
    __syncthreads();

    if (e == 3) {   // identity: out = relu(hid * p)
        if (step < 2) {
            for (int i = tid; i < nrows * 128; i += 256) {
                int r = i >> 7, j = i & 127;
                int m = s_rows[r];
                float v = (step == 0) ? g_h0[(size_t)(m >> 2) * 128 + j]
                                      : g_hid[(size_t)m * 128 + j];
                g_hid[(size_t)m * 128 + j] = fmaxf(v * s_p[r], 0.f);
            }
            return;
        }
        // step==2: into smem, then project
        for (int i = tid; i < nrows * 128; i += 256) {
            int r = i >> 7, j = i & 127;
            float v = g_hid[(size_t)s_rows[r] * 128 + j];
            buf[i] = fmaxf(v * s_p[r], 0.f);
        }
        __syncthreads();
        for (int i = tid; i < nrows * 10; i += 256) {
            int r = i / 10, o = i % 10;
            float a = s_outb[o];
            const float* hp = buf + r * 128;
#pragma unroll 8
            for (int d = 0; d < 128; d++) a += hp[d] * s_outw[d * 10 + o];
            out[(size_t)s_rows[r] * 10 + o] = a;
        }
        return;
    }

    for (int i = tid; i < 16384; i += 256) s_w[i] = exp_w[e * 16384 + i];
    if (tid < 128) s_b[tid] = exp_b[e * 128 + tid];
    for (int i = tid; i < 4096; i += 256) {
        int r = i >> 7, j = i & 127;
        float v = 0.f;
        if (r < nrows) {
            int m = s_rows[r];
            v = (step == 0) ? g_h0[(size_t)(m >> 2) * 128 + j]
                            : g_hid[(size_t)m * 128 + j];
        }
        buf[i] = v;
    }
    __syncthreads();

    int cp = tid & 63, rowg = tid >> 6;
    int r0 = rowg * 8, j0 = cp * 2;
    u64t acc[8];
#pragma unroll
    for (int k = 0; k < 8; k++) acc[k] = 0ull;
#pragma unroll 2
    for (int d = 0; d < 128; d++) {
        u64t w2 = *(const u64t*)(s_w + d * 128 + j0);
#pragma unroll
        for (int k = 0; k < 8; k++)
            ffma2(acc[k], w2, splat2(buf[(r0 + k) * 128 + d]));
    }
    u64t b2 = *(const u64t*)(s_b + j0);

    if (step < 2) {
#pragma unroll
        for (int k = 0; k < 8; k++) {
            int r = r0 + k;
            if (r < nrows) {
                int m = s_rows[r];
                float v = s_p[r];
                float2 st;
                st.x = fmaxf((lo32(acc[k]) + lo32(b2)) * v, 0.f);
                st.y = fmaxf((hi32(acc[k]) + hi32(b2)) * v, 0.f);
                *(float2*)(g_hid + (size_t)m * 128 + j0) = st;
            }
        }
        return;
    }

    // step==2: write results back into buf, then project
    __syncthreads();   // all reads of buf done
#pragma unroll
    for (int k = 0; k < 8; k++) {
        int r = r0 + k;
        float v = s_p[r < nrows ? r : 0];
        float2 st;
        st.x = fmaxf((lo32(acc[k]) + lo32(b2)) * v, 0.f);
        st.y = fmaxf((hi32(acc[k]) + hi32(b2)) * v, 0.f);
        *(float2*)(buf + r * 128 + j0) = st;
    }
    __syncthreads();
    for (int i = tid; i < nrows * 10; i += 256) {
        int r = i / 10, o = i % 10;
        float a = s_outb[o];
        const float* hp = buf + r * 128;
#pragma unroll 8
        for (int d = 0; d < 128; d++) a += hp[d] * s_outw[d * 10 + o];
        out[(size_t)s_rows[r] * 10 + o] = a;
    }
}

// ---------------------------------------------------------------------------
extern "C" void kernel_launch(void* const* d_in, const int* in_sizes, int n_in,
                              void* d_out, int out_size)
{
    const float* x    = (const float*)d_in[0];
    const float* cw1  = (const float*)d_in[1];
    const float* cb1  = (const float*)d_in[2];
    const float* g1   = (const float*)d_in[3];
    const float* be1  = (const float*)d_in[4];
    const float* cw2  = (const float*)d_in[5];
    const float* cb2  = (const float*)d_in[6];
    const float* g2   = (const float*)d_in[7];
    const float* be2  = (const float*)d_in[8];
    const float* cw3  = (const float*)d_in[9];
    const float* cb3  = (const float*)d_in[10];
    const float* g3   = (const float*)d_in[11];
    const float* be3  = (const float*)d_in[12];
    const float* W_hh = (const float*)d_in[13];
    const float* b_h  = (const float*)d_in[14];
    const float* E_op = (const float*)d_in[15];
    const float* W_ho = (const float*)d_in[16];
    const float* b_ho = (const float*)d_in[17];
    const float* expw = (const float*)d_in[18];
    const float* expb = (const float*)d_in[19];
    const float* outw = (const float*)d_in[20];
    const float* outb = (const float*)d_in[21];
    float* out = (float*)d_out;

    cudaFuncSetAttribute(conv2_kernel, cudaFuncAttributeMaxDynamicSharedMemorySize,
                         (15360 + 9216) * 4);
    cudaFuncSetAttribute(conv3_kernel, cudaFuncAttributeMaxDynamicSharedMemorySize,
                         (6144 + 9216) * 4);
    cudaFuncSetAttribute(moe_step_kernel, cudaFuncAttributeMaxDynamicSharedMemorySize,
                         (16384 + 4096 + 1280) * 4);

    conv1_kernel<<<NB, 960>>>(x, cw1, cb1);
    reduce_stats_kernel<<<32, 256>>>(0, 1.f / (NB * 900.f), g1, be1);

    conv2_kernel<<<NB / 2, 448, (15360 + 9216) * 4>>>(cw2, cb2);
    reduce_stats_kernel<<<32, 256>>>(1, 1.f / (NB * 169.f), g2, be2);

    conv3_kernel<<<NB / 4, 256, (6144 + 9216) * 4>>>(cw3, cb3);
    reduce_stats_kernel<<<32, 256>>>(2, 1.f / (NB * 16.f), g3, be3);

    beam_kernel<<<NB, 128>>>(W_hh, b_h, E_op, W_ho, b_ho);

    zero_cnt_kernel<<<1, 32>>>();
    build_index_kernel<<<(3 * NB * 4 + 255) / 256, 256>>>();

    dim3 moe_grid(NB * 4 / 32, 4);
    size_t moe_smem = (16384 + 4096 + 1280) * 4;
    moe_step_kernel<<<moe_grid, 256, moe_smem>>>(expw, expb, outw, outb, out, 0);
    moe_step_kernel<<<moe_grid, 256, moe_smem>>>(expw, expb, outw, outb, out, 1);
    moe_step_kernel<<<moe_grid, 256, moe_smem>>>(expw, expb, outw, outb, out, 2);
}

// round 11
// speedup vs baseline: 2.1713x; 1.0798x over previous
#include <cuda_runtime.h>
#include <math.h>
#include <float.h>
#include <stdint.h>

// ---------------------------------------------------------------------------
// Supernetwork: backbone (3x conv+BN+relu+pool) -> beam search -> MoE dispatch
// B=2048, BEAMS=4, DEPTH=3, HID=128, NOPS=4
//
// Round-11:
//  * conv2/conv3 persistent with atomic work-stealing (weights loaded once
//    per block; no wave-quantization tail). Counters reset in reduce_stats.
//  * MoE bucketing fused into beam kernel tail (zero_cnt/build_index gone).
//  * moe GEMM inner loop float4-vectorized activation loads.
//  * Determinism: work-stealing order varies but per-image outputs are pure
//    functions of inputs; no float atomics; fixed-order FP reductions.
// ---------------------------------------------------------------------------

#define NB 2048

// ------------------------------ scratch ------------------------------------
__device__ float g_buf1[(size_t)NB * 30 * 30 * 32];  // conv1 out, NHWC
__device__ float g_buf3[(size_t)NB * 13 * 13 * 32];  // conv2 out, NHWC
__device__ float g_buf5[(size_t)NB * 16 * 32];       // conv3 out, NHWC (4x4)
__device__ float g_h0[(size_t)NB * 128];             // backbone feature
__device__ float g_hid[(size_t)NB * 4 * 128];        // dispatch state
__device__ float g_psum[32 * NB];
__device__ float g_psq[32 * NB];
__device__ float g_scale[3][32];
__device__ float g_shift[3][32];
__device__ int   g_op[3 * NB * 4];
__device__ float g_pv[3 * NB * 4];
__device__ int   g_cnt[3][4];                        // rows per (step, expert)
__device__ int   g_ridx[3 * 4 * NB * 4];             // bucketed row indices
__device__ unsigned int g_ctr2;                      // conv2 work counter
__device__ unsigned int g_ctr3;                      // conv3 work counter

// --------------------------- f32x2 helpers ---------------------------------
typedef unsigned long long u64t;

__device__ __forceinline__ void ffma2(u64t& c, u64t a, u64t b) {
    asm("fma.rn.f32x2 %0, %1, %2, %0;" : "+l"(c) : "l"(a), "l"(b));
}
__device__ __forceinline__ u64t splat2(float v) {
    u64t r;
    asm("mov.b64 %0, {%1, %1};" : "=l"(r) : "r"(__float_as_uint(v)));
    return r;
}
__device__ __forceinline__ float lo32(u64t v) { return __uint_as_float((unsigned)v); }
__device__ __forceinline__ float hi32(u64t v) { return __uint_as_float((unsigned)(v >> 32)); }

__device__ __forceinline__ float4 bnrelu4(float4 v, float4 sc, float4 sh) {
    float4 r;
    r.x = fmaxf(v.x * sc.x + sh.x, 0.f);
    r.y = fmaxf(v.y * sc.y + sh.y, 0.f);
    r.z = fmaxf(v.z * sc.z + sh.z, 0.f);
    r.w = fmaxf(v.w * sc.w + sh.w, 0.f);
    return r;
}

// ------------------- conv1: 3->32, 32x32 -> 30x30, fused stats -------------
__global__ __launch_bounds__(960, 1) void conv1_kernel(
    const float* __restrict__ x, const float* __restrict__ w,
    const float* __restrict__ bias)
{
    __shared__ float s_img[3 * 1024];
    __shared__ float s_w[27 * 32];
    __shared__ float s_b[32];
    __shared__ float s_ss[32][60];
    __shared__ float s_sq[32][60];
    int tid = threadIdx.x;
    int img = blockIdx.x;
    const float* xb = x + (size_t)img * 3072;
    for (int i = tid; i < 768; i += 960)
        ((float4*)s_img)[i] = ((const float4*)xb)[i];
    if (tid < 864) {
        int oc = tid / 27, k = tid % 27;
        s_w[k * 32 + oc] = w[tid];
    }
    if (tid < 32) s_b[tid] = bias[tid];
    __syncthreads();

    int half = tid / 480;
    int rem  = tid % 480;
    int ocp = rem & 15;
    int row = rem >> 4;
    int ox0 = half * 15;

    u64t acc[15];
    u64t bv = *(const u64t*)(s_b + ocp * 2);
#pragma unroll
    for (int i = 0; i < 15; i++) acc[i] = bv;

#pragma unroll
    for (int ic = 0; ic < 3; ic++) {
#pragma unroll
        for (int ky = 0; ky < 3; ky++) {
            const float* irow = s_img + ic * 1024 + (row + ky) * 32;
            float in[17];
            if (half == 0) {
#pragma unroll
                for (int i = 0; i < 4; i++) {
                    float4 v4 = ((const float4*)irow)[i];
                    in[4 * i] = v4.x; in[4 * i + 1] = v4.y;
                    in[4 * i + 2] = v4.z; in[4 * i + 3] = v4.w;
                }
                in[16] = irow[16];
            } else {
                in[0] = irow[15];
#pragma unroll
                for (int i = 0; i < 4; i++) {
                    float4 v4 = ((const float4*)(irow + 16))[i];
                    in[4 * i + 1] = v4.x; in[4 * i + 2] = v4.y;
                    in[4 * i + 3] = v4.z; in[4 * i + 4] = v4.w;
                }
            }
#pragma unroll
            for (int kx = 0; kx < 3; kx++) {
                u64t wv = *(const u64t*)(s_w + ((ic * 3 + ky) * 3 + kx) * 32 + ocp * 2);
#pragma unroll
                for (int i = 0; i < 15; i++)
                    ffma2(acc[i], wv, splat2(in[i + kx]));
            }
        }
    }
    u64t* ob = (u64t*)(g_buf1 + (((size_t)img * 30 + row) * 30 + ox0) * 32 + 2 * ocp);
    float slo = 0.f, qlo = 0.f, shi = 0.f, qhi = 0.f;
#pragma unroll
    for (int i = 0; i < 15; i++) {
        u64t v = acc[i];
        ob[i * 16] = v;
        float a = lo32(v), b2 = hi32(v);
        slo += a; qlo += a * a; shi += b2; qhi += b2 * b2;
    }
    int rh = row + 30 * half;
    s_ss[2 * ocp][rh] = slo; s_sq[2 * ocp][rh] = qlo;
    s_ss[2 * ocp + 1][rh] = shi; s_sq[2 * ocp + 1][rh] = qhi;
    __syncthreads();
    if (tid < 32) {
        float s = 0.f, q = 0.f;
#pragma unroll
        for (int r = 0; r < 60; r++) { s += s_ss[tid][r]; q += s_sq[tid][r]; }
        g_psum[tid * NB + img] = s;
        g_psq[tid * NB + img] = q;
    }
}

// Per-channel reduction over 2048 images (fixed pairwise order) -> scale/shift.
// Also resets the next stage's work counters (runs between conv stages).
__global__ __launch_bounds__(256) void reduce_stats_kernel(
    int stage, float invN,
    const float* __restrict__ gamma, const float* __restrict__ beta)
{
    __shared__ float ss[256], sq[256];
    int c = blockIdx.x;
    int t = threadIdx.x;
    if (blockIdx.x == 0) {
        if (stage == 0 && t == 0) g_ctr2 = 0u;
        if (stage == 1 && t == 0) g_ctr3 = 0u;
        if (stage == 2 && t < 12) (&g_cnt[0][0])[t] = 0;
    }
    float s = 0.f, q = 0.f;
#pragma unroll
    for (int k = 0; k < NB / 256; k++) {
        int img = t + k * 256;
        s += g_psum[c * NB + img];
        q += g_psq[c * NB + img];
    }
    ss[t] = s; sq[t] = q;
    __syncthreads();
#pragma unroll
    for (int off = 128; off; off >>= 1) {
        if (t < off) { ss[t] += ss[t + off]; sq[t] += sq[t + off]; }
        __syncthreads();
    }
    if (t == 0) {
        float mu = ss[0] * invN;
        float var = sq[0] * invN - mu * mu;
        float sc = gamma[c] * rsqrtf(var + 1e-5f);
        g_scale[stage][c] = sc;
        g_shift[stage][c] = beta[c] - mu * sc;
    }
}

// ------- conv2: persistent, 2 imgs/iteration, fused pool1 load -------------
__global__ __launch_bounds__(448, 2) void conv2_kernel(
    const float* __restrict__ w, const float* __restrict__ bias)
{
    extern __shared__ float sm[];
    float* s_img = sm;            // 2 * 32*15*16 = 15360
    float* s_w = sm + 15360;      // 9216
    __shared__ float s_b[32];
    __shared__ float s_ss[2][32][13];
    __shared__ float s_sq[2][32][13];
    __shared__ int s_pair;
    int tid = threadIdx.x;

    for (int i = tid; i < 9216; i += 448) {
        int oc = i / 288, r = i % 288;
        s_w[r * 32 + oc] = w[i];
    }
    if (tid < 32) s_b[tid] = bias[tid];

    while (true) {
        __syncthreads();   // weights ready / previous iteration fully done
        if (tid == 0) s_pair = (int)atomicAdd(&g_ctr2, 1u);
        __syncthreads();
        int img0 = s_pair * 2;
        if (img0 >= NB) break;

        // fused pool1: read raw conv1 output, BN+relu+avgpool2 into smem
        for (int i = tid; i < 3600; i += 448) {
            int sub = i / 1800, j = i % 1800;
            int c4 = j & 7, p = j >> 3;          // p = oy*15+ox
            int oy = p / 15, ox = p % 15;
            const float4* b = (const float4*)(g_buf1
                + (((size_t)(img0 + sub) * 30 + 2 * oy) * 30 + 2 * ox) * 32) + c4;
            float4 sc = ((const float4*)g_scale[0])[c4];
            float4 sh = ((const float4*)g_shift[0])[c4];
            float4 a0 = bnrelu4(b[0], sc, sh);
            float4 a1 = bnrelu4(b[8], sc, sh);
            float4 a2 = bnrelu4(b[240], sc, sh);
            float4 a3 = bnrelu4(b[248], sc, sh);
            int base = sub * 7680 + oy * 16 + ox;
            s_img[base + (4 * c4 + 0) * 240] = (a0.x + a1.x + a2.x + a3.x) * 0.25f;
            s_img[base + (4 * c4 + 1) * 240] = (a0.y + a1.y + a2.y + a3.y) * 0.25f;
            s_img[base + (4 * c4 + 2) * 240] = (a0.z + a1.z + a2.z + a3.z) * 0.25f;
            s_img[base + (4 * c4 + 3) * 240] = (a0.w + a1.w + a2.w + a3.w) * 0.25f;
        }
        __syncthreads();

        int sub = tid / 224;
        int local = tid % 224;
        if (local < 208) {
            int ocp = local & 15;
            int row = local >> 4;
            const float* imgbase = s_img + sub * 7680;
            u64t acc[13];
            u64t bv = *(const u64t*)(s_b + ocp * 2);
#pragma unroll
            for (int i = 0; i < 13; i++) acc[i] = bv;

            for (int ic = 0; ic < 32; ic++) {
#pragma unroll
                for (int ky = 0; ky < 3; ky++) {
                    const float4* irow4 = (const float4*)(imgbase + ic * 240 + (row + ky) * 16);
                    float in[16];
#pragma unroll
                    for (int i = 0; i < 4; i++) {
                        float4 v4 = irow4[i];
                        in[4 * i] = v4.x; in[4 * i + 1] = v4.y;
                        in[4 * i + 2] = v4.z; in[4 * i + 3] = v4.w;
                    }
#pragma unroll
                    for (int kx = 0; kx < 3; kx++) {
                        u64t wv = *(const u64t*)(s_w + (ic * 9 + ky * 3 + kx) * 32 + ocp * 2);
#pragma unroll
                        for (int ox = 0; ox < 13; ox++)
                            ffma2(acc[ox], wv, splat2(in[ox + kx]));
                    }
                }
            }
            u64t* ob = (u64t*)(g_buf3 + (((size_t)(img0 + sub) * 13 + row) * 13) * 32 + 2 * ocp);
            float slo = 0.f, qlo = 0.f, shi = 0.f, qhi = 0.f;
#pragma unroll
            for (int ox = 0; ox < 13; ox++) {
                u64t v = acc[ox];
                ob[ox * 16] = v;
                float a = lo32(v), b2 = hi32(v);
                slo += a; qlo += a * a; shi += b2; qhi += b2 * b2;
            }
            s_ss[sub][2 * ocp][row] = slo; s_sq[sub][2 * ocp][row] = qlo;
            s_ss[sub][2 * ocp + 1][row] = shi; s_sq[sub][2 * ocp + 1][row] = qhi;
        }
        __syncthreads();
        if (tid < 64) {
            int ssub = tid >> 5, c = tid & 31;
            float s = 0.f, q = 0.f;
#pragma unroll
            for (int r = 0; r < 13; r++) { s += s_ss[ssub][c][r]; q += s_sq[ssub][c][r]; }
            g_psum[c * NB + img0 + ssub] = s;
            g_psq[c * NB + img0 + ssub] = q;
        }
    }
}

// ------- conv3: persistent, 4 imgs/iteration, fused pool2 load -------------
__global__ __launch_bounds__(256, 3) void conv3_kernel(
    const float* __restrict__ w, const float* __restrict__ bias)
{
    extern __shared__ float sm[];
    float* s_img = sm;            // 4 * 32*6*8 = 6144
    float* s_w = sm + 6144;       // 9216
    __shared__ float s_b[32];
    __shared__ float s_ss[4][32][4];
    __shared__ float s_sq[4][32][4];
    __shared__ int s_chunk;
    int tid = threadIdx.x;

    for (int i = tid; i < 9216; i += 256) {
        int oc = i / 288, r = i % 288;
        s_w[r * 32 + oc] = w[i];
    }
    if (tid < 32) s_b[tid] = bias[tid];

    while (true) {
        __syncthreads();
        if (tid == 0) s_chunk = (int)atomicAdd(&g_ctr3, 1u);
        __syncthreads();
        int img0 = s_chunk * 4;
        if (img0 >= NB) break;

        // fused pool2
        for (int i = tid; i < 1152; i += 256) {
            int il = i / 288, j = i % 288;
            int c4 = j & 7, p = j >> 3;          // p = oy*6+ox
            int oy = p / 6, ox = p % 6;
            const float4* b = (const float4*)(g_buf3
                + (((size_t)(img0 + il) * 13 + 2 * oy) * 13 + 2 * ox) * 32) + c4;
            float4 sc = ((const float4*)g_scale[1])[c4];
            float4 sh = ((const float4*)g_shift[1])[c4];
            float4 a0 = bnrelu4(b[0], sc, sh);
            float4 a1 = bnrelu4(b[8], sc, sh);
            float4 a2 = bnrelu4(b[104], sc, sh);
            float4 a3 = bnrelu4(b[112], sc, sh);
            int base = il * 1536 + oy * 8 + ox;
            s_img[base + (4 * c4 + 0) * 48] = (a0.x + a1.x + a2.x + a3.x) * 0.25f;
            s_img[base + (4 * c4 + 1) * 48] = (a0.y + a1.y + a2.y + a3.y) * 0.25f;
            s_img[base + (4 * c4 + 2) * 48] = (a0.z + a1.z + a2.z + a3.z) * 0.25f;
            s_img[base + (4 * c4 + 3) * 48] = (a0.w + a1.w + a2.w + a3.w) * 0.25f;
        }
        __syncthreads();

        int ocp = tid & 15;
        int oy = (tid >> 4) & 3;
        int il = tid >> 6;
        const float* imgbase = s_img + il * 1536;
        u64t acc[4];
        u64t bv = *(const u64t*)(s_b + ocp * 2);
#pragma unroll
        for (int i = 0; i < 4; i++) acc[i] = bv;

        for (int ic = 0; ic < 32; ic++) {
#pragma unroll
            for (int ky = 0; ky < 3; ky++) {
                const float* irow = imgbase + ic * 48 + (oy + ky) * 8;
                float in[6];
                float4 v4 = *(const float4*)irow;
                in[0] = v4.x; in[1] = v4.y; in[2] = v4.z; in[3] = v4.w;
                in[4] = irow[4]; in[5] = irow[5];
#pragma unroll
                for (int kx = 0; kx < 3; kx++) {
                    u64t wv = *(const u64t*)(s_w + (ic * 9 + ky * 3 + kx) * 32 + ocp * 2);
#pragma unroll
                    for (int ox = 0; ox < 4; ox++)
                        ffma2(acc[ox], wv, splat2(in[ox + kx]));
                }
            }
        }
        u64t* ob = (u64t*)(g_buf5 + ((size_t)(img0 + il) * 16 + oy * 4) * 32 + 2 * ocp);
        float slo = 0.f, qlo = 0.f, shi = 0.f, qhi = 0.f;
#pragma unroll
        for (int ox = 0; ox < 4; ox++) {
            u64t v = acc[ox];
            ob[ox * 16] = v;
            float a = lo32(v), b2 = hi32(v);
            slo += a; qlo += a * a; shi += b2; qhi += b2 * b2;
        }
        s_ss[il][2 * ocp][oy] = slo; s_sq[il][2 * ocp][oy] = qlo;
        s_ss[il][2 * ocp + 1][oy] = shi; s_sq[il][2 * ocp + 1][oy] = qhi;
        __syncthreads();
        if (tid < 128) {
            int iimg = tid >> 5, c = tid & 31;
            float s = 0.f, q = 0.f;
#pragma unroll
            for (int r = 0; r < 4; r++) { s += s_ss[iimg][c][r]; q += s_sq[iimg][c][r]; }
            g_psum[c * NB + img0 + iimg] = s;
            g_psq[c * NB + img0 + iimg] = q;
        }
    }
}

// ------------- beam search (+ fused pool3, + fused MoE bucketing) ----------
__device__ __forceinline__ float warp_sum(float v) {
#pragma unroll
    for (int off = 16; off; off >>= 1) v += __shfl_down_sync(0xffffffffu, v, off);
    return v;
}

__global__ __launch_bounds__(128) void beam_kernel(
    const float* __restrict__ W_hh, const float* __restrict__ b_h,
    const float* __restrict__ E_op, const float* __restrict__ W_ho,
    const float* __restrict__ b_ho)
{
    __shared__ float s_h0[128];
    __shared__ float s_h[4][128];
    __shared__ float s_hn[4][128];
    __shared__ float s_Who[512];
    __shared__ float s_logits[4][4];
    __shared__ float s_scores[4];
    __shared__ int   s_op[4];
    __shared__ int   s_src[4];

    int n = blockIdx.x;
    int tid = threadIdx.x;
    int warp = tid >> 5, lane = tid & 31;

    // fused pool3
    {
        int c = tid >> 2, p = tid & 3;
        int oy = p >> 1, ox = p & 1;
        const float* b = g_buf5 + ((size_t)n * 16 + (2 * oy) * 4 + 2 * ox) * 32 + c;
        float sc = g_scale[2][c], sh = g_shift[2][c];
        float v = fmaxf(b[0] * sc + sh, 0.f) + fmaxf(b[32] * sc + sh, 0.f)
                + fmaxf(b[128] * sc + sh, 0.f) + fmaxf(b[160] * sc + sh, 0.f);
        v *= 0.25f;
        s_h0[tid] = v;
        g_h0[(size_t)n * 128 + tid] = v;
    }
#pragma unroll
    for (int i = 0; i < 4; i++) s_Who[i * 128 + tid] = W_ho[i * 128 + tid];
    __syncthreads();

    {
        float a = 0.f;
        for (int d = lane; d < 128; d += 32) a += s_h0[d] * s_Who[d * 4 + warp];
        a = warp_sum(a);
        if (lane == 0) s_logits[0][warp] = a + b_ho[warp];
    }
    __syncthreads();

    if (tid == 0) {
        float l[4], e[4];
        float m = -FLT_MAX;
#pragma unroll
        for (int o = 0; o < 4; o++) { l[o] = s_logits[0][o]; m = fmaxf(m, l[o]); }
        float sum = 0.f;
#pragma unroll
        for (int o = 0; o < 4; o++) { e[o] = expf(l[o] - m); sum += e[o]; }
        float logsum = logf(sum);
        float inv = 1.f / sum;
        bool used[4] = {false, false, false, false};
        for (int b = 0; b < 4; b++) {
            int best = -1; float bv = -FLT_MAX;
            for (int o = 0; o < 4; o++) {
                float lp = l[o] - m - logsum;
                if (!used[o] && lp > bv) { bv = lp; best = o; }
            }
            used[best] = true;
            s_scores[b] = bv;
            s_op[b] = best;
            g_op[0 * (NB * 4) + n * 4 + b] = best;
            g_pv[0 * (NB * 4) + n * 4 + b] = e[best] * inv;
        }
    }
    __syncthreads();

    {
        float common = 0.f;
#pragma unroll 8
        for (int k = 0; k < 128; k++) common += s_h0[k] * W_hh[k * 128 + tid];
        float bh = b_h[tid];
#pragma unroll
        for (int b = 0; b < 4; b++)
            s_h[b][tid] = tanhf(common + E_op[s_op[b] * 128 + tid] + bh);
    }
    __syncthreads();

    for (int step = 1; step < 3; step++) {
        {
            float a0 = 0.f, a1 = 0.f, a2 = 0.f, a3 = 0.f;
            for (int d = lane; d < 128; d += 32) {
                float v = s_h[warp][d];
                a0 += v * s_Who[d * 4 + 0];
                a1 += v * s_Who[d * 4 + 1];
                a2 += v * s_Who[d * 4 + 2];
                a3 += v * s_Who[d * 4 + 3];
            }
            a0 = warp_sum(a0); a1 = warp_sum(a1); a2 = warp_sum(a2); a3 = warp_sum(a3);
            if (lane == 0) {
                s_logits[warp][0] = a0 + b_ho[0];
                s_logits[warp][1] = a1 + b_ho[1];
                s_logits[warp][2] = a2 + b_ho[2];
                s_logits[warp][3] = a3 + b_ho[3];
            }
        }
        __syncthreads();

        if (tid == 0) {
            float cand[16], probs[16];
            for (int b = 0; b < 4; b++) {
                float l[4], e[4];
                float m = -FLT_MAX;
#pragma unroll
                for (int o = 0; o < 4; o++) { l[o] = s_logits[b][o]; m = fmaxf(m, l[o]); }
                float sum = 0.f;
#pragma unroll
                for (int o = 0; o < 4; o++) { e[o] = expf(l[o] - m); sum += e[o]; }
                float logsum = logf(sum);
                float inv = 1.f / sum;
#pragma unroll
                for (int o = 0; o < 4; o++) {
                    cand[b * 4 + o] = s_scores[b] + (l[o] - m - logsum);
                    probs[b * 4 + o] = e[o] * inv;
                }
            }
            bool used[16];
            for (int i = 0; i < 16; i++) used[i] = false;
            float ns[4];
            for (int b = 0; b < 4; b++) {
                int best = -1; float bv = -FLT_MAX;
                for (int f = 0; f < 16; f++)
                    if (!used[f] && cand[f] > bv) { bv = cand[f]; best = f; }
                used[best] = true;
                ns[b] = bv;
                int src = best >> 2, op = best & 3;
                s_src[b] = src; s_op[b] = op;
                g_op[step * (NB * 4) + n * 4 + b] = op;
                g_pv[step * (NB * 4) + n * 4 + b] = probs[best];
            }
#pragma unroll
            for (int b = 0; b < 4; b++) s_scores[b] = ns[b];
        }
        __syncthreads();

        if (step < 2) {
            int r0 = s_src[0], r1 = s_src[1], r2 = s_src[2], r3 = s_src[3];
            float a0 = 0.f, a1 = 0.f, a2 = 0.f, a3 = 0.f;
#pragma unroll 4
            for (int k = 0; k < 128; k++) {
                float wv = W_hh[k * 128 + tid];
                a0 += s_h[r0][k] * wv;
                a1 += s_h[r1][k] * wv;
                a2 += s_h[r2][k] * wv;
                a3 += s_h[r3][k] * wv;
            }
            float bh = b_h[tid];
            s_hn[0][tid] = tanhf(a0 + E_op[s_op[0] * 128 + tid] + bh);
            s_hn[1][tid] = tanhf(a1 + E_op[s_op[1] * 128 + tid] + bh);
            s_hn[2][tid] = tanhf(a2 + E_op[s_op[2] * 128 + tid] + bh);
            s_hn[3][tid] = tanhf(a3 + E_op[s_op[3] * 128 + tid] + bh);
            __syncthreads();
#pragma unroll
            for (int b = 0; b < 4; b++) s_h[b][tid] = s_hn[b][tid];
            __syncthreads();
        }
    }

    // fused MoE bucketing: all g_op/g_pv for this sample are now final
    // (global writes by tid 0 are visible after the loop's last __syncthreads)
    if (tid < 12) {
        int step = tid >> 2, b = tid & 3;
        int m = n * 4 + b;
        int op = g_op[step * (NB * 4) + m];
        float p = g_pv[step * (NB * 4) + m];
        int e = (p > 0.f) ? op : 0;
        int pos = atomicAdd(&g_cnt[step][e], 1);
        g_ridx[(step * 4 + e) * (NB * 4) + pos] = m;
    }
}

// ---------------------- sorted MoE dispatch --------------------------------
// One step of dispatch. step==2 additionally computes the final 128->10
// projection from smem (final hid never round-trips through global).
__global__ __launch_bounds__(256) void moe_step_kernel(
    const float* __restrict__ exp_w, const float* __restrict__ exp_b,
    const float* __restrict__ out_w, const float* __restrict__ out_b,
    float* __restrict__ out, int step)
{
    extern __shared__ float sm[];
    float* s_w = sm;              // 16384 floats
    float* buf = sm + 16384;      // 32 x 128
    float* s_outw = sm + 20480;   // 1280 floats (step==2 only)
    __shared__ float s_b[128];
    __shared__ float s_outb[10];
    __shared__ int   s_rows[32];
    __shared__ float s_p[32];
    __shared__ int   s_cnt;

    int e = blockIdx.y;
    int tid = threadIdx.x;
    if (tid == 0) s_cnt = g_cnt[step][e];
    __syncthreads();
    int base = blockIdx.x * 32;
    if (base >= s_cnt) return;
    int nrows = min(32, s_cnt - base);

    if (tid < nrows) {
        int m = g_ridx[(step * 4 + e) * (NB * 4) + base + tid];
        s_rows[tid] = m;
        s_p[tid] = g_pv[step * (NB * 4) + m];
    }
    if (step == 2) {
        for (int i = tid; i < 1280; i += 256) s_outw[i] = out_w[i];
        if (tid < 10) s_outb[tid] = out_b[tid];
    }
    __syncthreads();

    if (e == 3) {   // identity: out = relu(hid * p)
        if (step < 2) {
            for (int i = tid; i < nrows * 128; i += 256) {
                int r = i >> 7, j = i & 127;
                int m = s_rows[r];
                float v = (step == 0) ? g_h0[(size_t)(m >> 2) * 128 + j]
                                      : g_hid[(size_t)m * 128 + j];
                g_hid[(size_t)m * 128 + j] = fmaxf(v * s_p[r], 0.f);
            }
            return;
        }
        for (int i = tid; i < nrows * 128; i += 256) {
            int r = i >> 7, j = i & 127;
            float v = g_hid[(size_t)s_rows[r] * 128 + j];
            buf[i] = fmaxf(v * s_p[r], 0.f);
        }
        __syncthreads();
        for (int i = tid; i < nrows * 10; i += 256) {
            int r = i / 10, o = i % 10;
            float a = s_outb[o];
            const float* hp = buf + r * 128;
#pragma unroll 8
            for (int d = 0; d < 128; d++) a += hp[d] * s_outw[d * 10 + o];
            out[(size_t)s_rows[r] * 10 + o] = a;
        }
        return;
    }

    for (int i = tid; i < 16384; i += 256) s_w[i] = exp_w[e * 16384 + i];
    if (tid < 128) s_b[tid] = exp_b[e * 128 + tid];
    for (int i = tid; i < 4096; i += 256) {
        int r = i >> 7, j = i & 127;
        float v = 0.f;
        if (r < nrows) {
            int m = s_rows[r];
            v = (step == 0) ? g_h0[(size_t)(m >> 2) * 128 + j]
                            : g_hid[(size_t)m * 128 + j];
        }
        buf[i] = v;
    }
    __syncthreads();

    int cp = tid & 63, rowg = tid >> 6;
    int r0 = rowg * 8, j0 = cp * 2;
    u64t acc[8];
#pragma unroll
    for (int k = 0; k < 8; k++) acc[k] = 0ull;
    for (int d = 0; d < 128; d += 4) {
        u64t w0 = *(const u64t*)(s_w + (d + 0) * 128 + j0);
        u64t w1 = *(const u64t*)(s_w + (d + 1) * 128 + j0);
        u64t w2 = *(const u64t*)(s_w + (d + 2) * 128 + j0);
        u64t w3 = *(const u64t*)(s_w + (d + 3) * 128 + j0);
#pragma unroll
        for (int k = 0; k < 8; k++) {
            float4 h = *(const float4*)(buf + (r0 + k) * 128 + d);
            ffma2(acc[k], w0, splat2(h.x));
            ffma2(acc[k], w1, splat2(h.y));
            ffma2(acc[k], w2, splat2(h.z));
            ffma2(acc[k], w3, splat2(h.w));
        }
    }
    u64t b2 = *(const u64t*)(s_b + j0);

    if (step < 2) {
#pragma unroll
        for (int k = 0; k < 8; k++) {
            int r = r0 + k;
            if (r < nrows) {
                int m = s_rows[r];
                float v = s_p[r];
                float2 st;
                st.x = fmaxf((lo32(acc[k]) + lo32(b2)) * v, 0.f);
                st.y = fmaxf((hi32(acc[k]) + hi32(b2)) * v, 0.f);
                *(float2*)(g_hid + (size_t)m * 128 + j0) = st;
            }
        }
        return;
    }

    // step==2: write results back into buf, then project
    __syncthreads();   // all reads of buf done
#pragma unroll
    for (int k = 0; k < 8; k++) {
        int r = r0 + k;
        float v = s_p[r < nrows ? r : 0];
        float2 st;
        st.x = fmaxf((lo32(acc[k]) + lo32(b2)) * v, 0.f);
        st.y = fmaxf((hi32(acc[k]) + hi32(b2)) * v, 0.f);
        *(float2*)(buf + r * 128 + j0) = st;
    }
    __syncthreads();
    for (int i = tid; i < nrows * 10; i += 256) {
        int r = i / 10, o = i % 10;
        float a = s_outb[o];
        const float* hp = buf + r * 128;
#pragma unroll 8
        for (int d = 0; d < 128; d++) a += hp[d] * s_outw[d * 10 + o];
        out[(size_t)s_rows[r] * 10 + o] = a;
    }
}

// ---------------------------------------------------------------------------
extern "C" void kernel_launch(void* const* d_in, const int* in_sizes, int n_in,
                              void* d_out, int out_size)
{
    const float* x    = (const float*)d_in[0];
    const float* cw1  = (const float*)d_in[1];
    const float* cb1  = (const float*)d_in[2];
    const float* g1   = (const float*)d_in[3];
    const float* be1  = (const float*)d_in[4];
    const float* cw2  = (const float*)d_in[5];
    const float* cb2  = (const float*)d_in[6];
    const float* g2   = (const float*)d_in[7];
    const float* be2  = (const float*)d_in[8];
    const float* cw3  = (const float*)d_in[9];
    const float* cb3  = (const float*)d_in[10];
    const float* g3   = (const float*)d_in[11];
    const float* be3  = (const float*)d_in[12];
    const float* W_hh = (const float*)d_in[13];
    const float* b_h  = (const float*)d_in[14];
    const float* E_op = (const float*)d_in[15];
    const float* W_ho = (const float*)d_in[16];
    const float* b_ho = (const float*)d_in[17];
    const float* expw = (const float*)d_in[18];
    const float* expb = (const float*)d_in[19];
    const float* outw = (const float*)d_in[20];
    const float* outb = (const float*)d_in[21];
    float* out = (float*)d_out;

    cudaFuncSetAttribute(conv2_kernel, cudaFuncAttributeMaxDynamicSharedMemorySize,
                         (15360 + 9216) * 4);
    cudaFuncSetAttribute(conv3_kernel, cudaFuncAttributeMaxDynamicSharedMemorySize,
                         (6144 + 9216) * 4);
    cudaFuncSetAttribute(moe_step_kernel, cudaFuncAttributeMaxDynamicSharedMemorySize,
                         (16384 + 4096 + 1280) * 4);

    conv1_kernel<<<NB, 960>>>(x, cw1, cb1);
    reduce_stats_kernel<<<32, 256>>>(0, 1.f / (NB * 900.f), g1, be1);

    conv2_kernel<<<304, 448, (15360 + 9216) * 4>>>(cw2, cb2);
    reduce_stats_kernel<<<32, 256>>>(1, 1.f / (NB * 169.f), g2, be2);

    conv3_kernel<<<456, 256, (6144 + 9216) * 4>>>(cw3, cb3);
    reduce_stats_kernel<<<32, 256>>>(2, 1.f / (NB * 16.f), g3, be3);

    beam_kernel<<<NB, 128>>>(W_hh, b_h, E_op, W_ho, b_ho);

    dim3 moe_grid(NB * 4 / 32, 4);
    size_t moe_smem = (16384 + 4096 + 1280) * 4;
    moe_step_kernel<<<moe_grid, 256, moe_smem>>>(expw, expb, outw, outb, out, 0);
    moe_step_kernel<<<moe_grid, 256, moe_smem>>>(expw, expb, outw, outb, out, 1);
    moe_step_kernel<<<moe_grid, 256, moe_smem>>>(expw, expb, outw, outb, out, 2);
}